// round 1
// baseline (speedup 1.0000x reference)
#include <cuda_runtime.h>
#include <cuda_bf16.h>
#include <cstdint>
#include <cstddef>
#include <math.h>

// ---------------- problem constants ----------------
#define Bimg 64
#define Hdim 56
#define Wdim 56
#define WS 7
#define SHIFT 3
#define Cdim 128
#define NHn 4
#define HDd 32
#define Nn 49          // tokens per window
#define NWn 64         // windows per image
#define HID 512
#define SCALE 0.17677669529663688f

#define NWIN_TOTAL (Bimg * NWn)          // 4096
#define NWIN_HALF  (NWIN_TOTAL / 2)      // 2048
#define TOK_TOTAL  (NWIN_TOTAL * Nn)     // 200704
#define TOK_HALF   (NWIN_HALF * Nn)      // 100352

// ---------------- scratch (device globals; no allocation APIs) ----------------
__device__ float g_XW [(size_t)TOK_TOTAL * Cdim];   // LN1 + windowed input
__device__ float g_QKV[(size_t)TOK_HALF  * 384];    // qkv for one half (reused)
__device__ float g_O  [(size_t)TOK_HALF  * Cdim];   // attention output (reused)
__device__ float g_Y  [(size_t)TOK_TOTAL * Cdim];   // attention branch output (window layout)
__device__ float g_XN [(size_t)TOK_TOTAL * Cdim];   // LN2 output (image layout)
__device__ float g_H  [(size_t)TOK_HALF  * HID];    // MLP hidden (reused)

// ---------------- LN1 + roll(-3,-3) + window partition ----------------
__global__ void ln1_part_kernel(const float* __restrict__ x,
                                const float* __restrict__ w,
                                const float* __restrict__ b,
                                float* __restrict__ XW) {
    int t = blockIdx.x;                  // window-token index
    int win = t / Nn, n = t - win * Nn;
    int bi = win >> 6, wi = win & 63;
    int hs = ((wi >> 3) * WS + n / WS + SHIFT) % Hdim;
    int ws = ((wi & 7) * WS + n % WS + SHIFT) % Wdim;
    const float* xp = x + ((size_t)bi * (Hdim * Wdim) + hs * Wdim + ws) * Cdim;
    int c = threadIdx.x;
    float val = xp[c];
    __shared__ float red[8];
    float s = val, s2 = val * val;
    #pragma unroll
    for (int o = 16; o > 0; o >>= 1) {
        s  += __shfl_down_sync(0xffffffffu, s, o);
        s2 += __shfl_down_sync(0xffffffffu, s2, o);
    }
    int lane = c & 31, wd = c >> 5;
    if (lane == 0) { red[wd] = s; red[4 + wd] = s2; }
    __syncthreads();
    s  = red[0] + red[1] + red[2] + red[3];
    s2 = red[4] + red[5] + red[6] + red[7];
    float mu  = s * (1.0f / Cdim);
    float var = s2 * (1.0f / Cdim) - mu * mu;
    float inv = rsqrtf(var + 1e-5f);
    XW[(size_t)t * Cdim + c] = (val - mu) * inv * w[c] + b[c];
}

// ---------------- window reverse + roll(+3,+3) + residual + LN2 ----------------
__global__ void resid_ln2_kernel(const float* __restrict__ x,
                                 const float* __restrict__ Y,
                                 const float* __restrict__ w,
                                 const float* __restrict__ b,
                                 float* __restrict__ out,
                                 float* __restrict__ XN) {
    int t = blockIdx.x;
    int win = t / Nn, n = t - win * Nn;
    int bi = win >> 6, wi = win & 63;
    int hs = ((wi >> 3) * WS + n / WS + SHIFT) % Hdim;
    int ws = ((wi & 7) * WS + n % WS + SHIFT) % Wdim;
    size_t pos = ((size_t)bi * (Hdim * Wdim) + hs * Wdim + ws) * Cdim;
    int c = threadIdx.x;
    float val = x[pos + c] + Y[(size_t)t * Cdim + c];
    out[pos + c] = val;                  // X2 residual base lives in d_out
    __shared__ float red[8];
    float s = val, s2 = val * val;
    #pragma unroll
    for (int o = 16; o > 0; o >>= 1) {
        s  += __shfl_down_sync(0xffffffffu, s, o);
        s2 += __shfl_down_sync(0xffffffffu, s2, o);
    }
    int lane = c & 31, wd = c >> 5;
    if (lane == 0) { red[wd] = s; red[4 + wd] = s2; }
    __syncthreads();
    s  = red[0] + red[1] + red[2] + red[3];
    s2 = red[4] + red[5] + red[6] + red[7];
    float mu  = s * (1.0f / Cdim);
    float var = s2 * (1.0f / Cdim) - mu * mu;
    float inv = rsqrtf(var + 1e-5f);
    XN[pos + c] = (val - mu) * inv * w[c] + b[c];
}

// ---------------- generic SGEMM: C = beta*C + alpha*act(A @ B^T + bias) ----------------
// A: M x K row-major (ld lda), B: N x K row-major (ld ldb), C: M x N (ld ldc)
#define BM 64
#define BN 64
#define BK 16
__global__ __launch_bounds__(256) void sgemm_nt(
    const float* __restrict__ A, int lda,
    const float* __restrict__ B, int ldb,
    const float* __restrict__ bias,
    float* __restrict__ C, int ldc,
    int M, int N, int K,
    const float* __restrict__ alphaPtr, int alphaIdx,
    int betaOne, int doGelu) {
    __shared__ float As[BK][BM];
    __shared__ float Bs[BK][BN];
    const int bm = blockIdx.y * BM;
    const int bn = blockIdx.x * BN;
    const int tid = threadIdx.x;
    const int tx = tid & 15;        // n direction
    const int ty = tid >> 4;        // m direction
    const int lrow = tid >> 2;      // 0..63
    const int lcol = (tid & 3) * 4; // 0,4,8,12

    float acc[4][4];
    #pragma unroll
    for (int i = 0; i < 4; i++)
        #pragma unroll
        for (int j = 0; j < 4; j++) acc[i][j] = 0.0f;

    const float* Aptr = A + (size_t)(bm + lrow) * lda + lcol;
    const float* Bptr = B + (size_t)(bn + lrow) * ldb + lcol;
    const bool bvalid = (bn + lrow) < N;

    for (int k0 = 0; k0 < K; k0 += BK) {
        float4 av = *(const float4*)(Aptr + k0);
        float4 bv = bvalid ? *(const float4*)(Bptr + k0) : make_float4(0.f, 0.f, 0.f, 0.f);
        As[lcol + 0][lrow] = av.x; As[lcol + 1][lrow] = av.y;
        As[lcol + 2][lrow] = av.z; As[lcol + 3][lrow] = av.w;
        Bs[lcol + 0][lrow] = bv.x; Bs[lcol + 1][lrow] = bv.y;
        Bs[lcol + 2][lrow] = bv.z; Bs[lcol + 3][lrow] = bv.w;
        __syncthreads();
        #pragma unroll
        for (int kk = 0; kk < BK; kk++) {
            float ar[4], br[4];
            *(float4*)ar = *(const float4*)&As[kk][ty << 2];
            *(float4*)br = *(const float4*)&Bs[kk][tx << 2];
            #pragma unroll
            for (int i = 0; i < 4; i++)
                #pragma unroll
                for (int j = 0; j < 4; j++) acc[i][j] += ar[i] * br[j];
        }
        __syncthreads();
    }

    float alpha = alphaPtr ? __ldg(&alphaPtr[alphaIdx]) : 1.0f;
    #pragma unroll
    for (int i = 0; i < 4; i++) {
        int m = bm + (ty << 2) + i;
        #pragma unroll
        for (int j = 0; j < 4; j++) {
            int n = bn + (tx << 2) + j;
            if (n < N) {
                float t = acc[i][j] + (bias ? bias[n] : 0.0f);
                if (doGelu) t = 0.5f * t * (1.0f + erff(t * 0.70710678118654752f));
                float o = alpha * t;
                size_t off = (size_t)m * ldc + n;
                if (betaOne) o += C[off];
                C[off] = o;
            }
        }
    }
}

// ---------------- fused window attention (one block per window x head) ----------------
__global__ __launch_bounds__(128) void attn_kernel(
    const float* __restrict__ QKV,      // (TOK_HALF, 384)
    const float* __restrict__ rbt,      // (169, 4)
    const int*   __restrict__ relIdx,   // (49, 49)
    const float* __restrict__ mask,     // (64, 49, 49)
    float* __restrict__ O,              // (TOK_HALF, 128)
    int winBase) {
    int lw = blockIdx.x;   // local window (0..2047)
    int h  = blockIdx.y;   // head
    int mi = (winBase + lw) & 63;
    __shared__ float sq[Nn][HDd], sk[Nn][HDd], sv[Nn][HDd];
    __shared__ float sS[Nn][Nn + 1];
    int tid = threadIdx.x;

    const float* base = QKV + (size_t)lw * Nn * 384;
    for (int idx = tid; idx < Nn * HDd; idx += 128) {
        int n = idx >> 5, d = idx & 31;
        const float* row = base + n * 384;
        int col = h * HDd + d;
        sq[n][d] = row[col] * SCALE;
        sk[n][d] = row[128 + col];
        sv[n][d] = row[256 + col];
    }
    __syncthreads();

    const float* mrow = mask + (size_t)mi * (Nn * Nn);
    for (int idx = tid; idx < Nn * Nn; idx += 128) {
        int n = idx / Nn, m = idx - n * Nn;
        float acc = 0.0f;
        #pragma unroll
        for (int d = 0; d < HDd; d++) acc += sq[n][d] * sk[m][d];
        acc += __ldg(&rbt[relIdx[idx] * NHn + h]);
        acc += mrow[idx];
        sS[n][m] = acc;
    }
    __syncthreads();

    if (tid < Nn) {
        float mx = -1e30f;
        for (int m = 0; m < Nn; m++) mx = fmaxf(mx, sS[tid][m]);
        float sum = 0.0f;
        for (int m = 0; m < Nn; m++) { float e = expf(sS[tid][m] - mx); sS[tid][m] = e; sum += e; }
        float r = 1.0f / sum;
        for (int m = 0; m < Nn; m++) sS[tid][m] *= r;
    }
    __syncthreads();

    for (int idx = tid; idx < Nn * HDd; idx += 128) {
        int n = idx >> 5, d = idx & 31;
        float acc = 0.0f;
        #pragma unroll
        for (int m = 0; m < Nn; m++) acc += sS[n][m] * sv[m][d];
        O[(size_t)(lw * Nn + n) * Cdim + h * HDd + d] = acc;
    }
}

// ---------------- host-side helpers ----------------
static inline void launch_gemm(const float* A, int lda, const float* B, int ldb,
                               const float* bias, float* C, int ldc,
                               int M, int N, int K,
                               const float* aP, int ai, int betaOne, int gelu) {
    dim3 grid((N + BN - 1) / BN, M / BM);
    sgemm_nt<<<grid, 256>>>(A, lda, B, ldb, bias, C, ldc, M, N, K, aP, ai, betaOne, gelu);
}

extern "C" void kernel_launch(void* const* d_in, const int* in_sizes, int n_in,
                              void* d_out, int out_size) {
    const float* x     = (const float*)d_in[0];
    const float* gw    = (const float*)d_in[1];
    const float* n1w   = (const float*)d_in[2];
    const float* n1b   = (const float*)d_in[3];
    const float* qkvw  = (const float*)d_in[4];
    const float* qkvb  = (const float*)d_in[5];
    const float* rbt   = (const float*)d_in[6];
    const float* projw = (const float*)d_in[7];
    const float* projb = (const float*)d_in[8];
    const float* amask = (const float*)d_in[9];
    const float* n2w   = (const float*)d_in[10];
    const float* n2b   = (const float*)d_in[11];
    const float* f1w   = (const float*)d_in[12];
    const float* f1b   = (const float*)d_in[13];
    const float* f2w   = (const float*)d_in[14];
    const float* f2b   = (const float*)d_in[15];
    const int*   relIdx= (const int*)d_in[16];
    float* out = (float*)d_out;

    float *XW, *QKV, *O, *Y, *XN, *Hb;
    cudaGetSymbolAddress((void**)&XW,  g_XW);
    cudaGetSymbolAddress((void**)&QKV, g_QKV);
    cudaGetSymbolAddress((void**)&O,   g_O);
    cudaGetSymbolAddress((void**)&Y,   g_Y);
    cudaGetSymbolAddress((void**)&XN,  g_XN);
    cudaGetSymbolAddress((void**)&Hb,  g_H);

    const int Mh = TOK_HALF;         // 100352 rows per half
    const int Ks[3] = {128, 64, 32}; // C/alpha for alpha = 1,2,4

    // LN1 + shift + window partition
    ln1_part_kernel<<<TOK_TOTAL, 128>>>(x, n1w, n1b, XW);

    // ---- attention, large branch (first half of windows) ----
    launch_gemm(XW, Cdim, qkvw, Cdim, qkvb, QKV, 384, Mh, 384, 128, nullptr, 0, 0, 0);
    attn_kernel<<<dim3(NWIN_HALF, NHn), 128>>>(QKV, rbt, relIdx, amask, O, 0);
    launch_gemm(O, Cdim, projw, Cdim, projb, Y, Cdim, Mh, 128, 128, nullptr, 0, 0, 0);

    // ---- attention, gumbel-mixed sub-network branch (second half) ----
    for (int v = 0; v < 3; v++) {
        launch_gemm(XW + (size_t)Mh * Cdim, Cdim, qkvw, Cdim, qkvb, QKV, 384,
                    Mh, 384, Ks[v], nullptr, 0, 0, 0);
        attn_kernel<<<dim3(NWIN_HALF, NHn), 128>>>(QKV, rbt, relIdx, amask, O, NWIN_HALF);
        launch_gemm(O, Cdim, projw, Cdim, projb, Y + (size_t)Mh * Cdim, Cdim,
                    Mh, Ks[v], 128, gw, v, (v > 0) ? 1 : 0, 0);
    }

    // window reverse + shift back + residual; d_out := X2; XN := LN2(X2)
    resid_ln2_kernel<<<TOK_TOTAL, 128>>>(x, Y, n2w, n2b, out, XN);

    // ---- MLP, large branch (first 32 images) ----
    launch_gemm(XN, Cdim, f1w, Cdim, f1b, Hb, HID, Mh, HID, 128, nullptr, 0, 0, 1);
    launch_gemm(Hb, HID, f2w, HID, f2b, out, Cdim, Mh, 128, HID, nullptr, 0, 1, 0);

    // ---- MLP, sub-network branch (last 32 images) ----
    for (int v = 0; v < 3; v++) {
        launch_gemm(XN + (size_t)Mh * Cdim, Cdim, f1w, Cdim, f1b, Hb, HID,
                    Mh, HID, Ks[v], nullptr, 0, 0, 1);
        launch_gemm(Hb, HID, f2w, HID, f2b, out + (size_t)Mh * Cdim, Cdim,
                    Mh, Ks[v], HID, gw, v, 1, 0);
    }
}

// round 2
// speedup vs baseline: 1.3540x; 1.3540x over previous
#include <cuda_runtime.h>
#include <cuda_bf16.h>
#include <cstdint>
#include <cstddef>
#include <math.h>

// ---------------- problem constants ----------------
#define Bimg 64
#define Hdim 56
#define Wdim 56
#define WS 7
#define SHIFT 3
#define Cdim 128
#define NHn 4
#define HDd 32
#define Nn 49          // tokens per window
#define NWn 64         // windows per image
#define HID 512
#define SCALE 0.17677669529663688f

#define NWIN_TOTAL (Bimg * NWn)          // 4096
#define NWIN_HALF  (NWIN_TOTAL / 2)      // 2048
#define TOK_TOTAL  (NWIN_TOTAL * Nn)     // 200704
#define TOK_HALF   (NWIN_HALF * Nn)      // 100352

// ---------------- scratch (device globals; no allocation APIs) ----------------
__device__ float g_XW [(size_t)TOK_TOTAL * Cdim];   // LN1 + windowed input
__device__ float g_QKV[(size_t)TOK_HALF  * 384];    // qkv for one half (reused)
__device__ float g_O  [(size_t)TOK_HALF  * Cdim];   // attention output (reused)
__device__ float g_Y  [(size_t)TOK_TOTAL * Cdim];   // attention branch output (window layout)
__device__ float g_XN [(size_t)TOK_TOTAL * Cdim];   // LN2 output (image layout)
__device__ float g_H  [(size_t)TOK_HALF  * HID];    // MLP hidden (reused)

// ---------------- LN1 + roll(-3,-3) + window partition ----------------
__global__ void ln1_part_kernel(const float* __restrict__ x,
                                const float* __restrict__ w,
                                const float* __restrict__ b,
                                float* __restrict__ XW) {
    int t = blockIdx.x;                  // window-token index
    int win = t / Nn, n = t - win * Nn;
    int bi = win >> 6, wi = win & 63;
    int hs = ((wi >> 3) * WS + n / WS + SHIFT) % Hdim;
    int ws = ((wi & 7) * WS + n % WS + SHIFT) % Wdim;
    const float* xp = x + ((size_t)bi * (Hdim * Wdim) + hs * Wdim + ws) * Cdim;
    int c = threadIdx.x;
    float val = xp[c];
    __shared__ float red[8];
    float s = val, s2 = val * val;
    #pragma unroll
    for (int o = 16; o > 0; o >>= 1) {
        s  += __shfl_down_sync(0xffffffffu, s, o);
        s2 += __shfl_down_sync(0xffffffffu, s2, o);
    }
    int lane = c & 31, wd = c >> 5;
    if (lane == 0) { red[wd] = s; red[4 + wd] = s2; }
    __syncthreads();
    s  = red[0] + red[1] + red[2] + red[3];
    s2 = red[4] + red[5] + red[6] + red[7];
    float mu  = s * (1.0f / Cdim);
    float var = s2 * (1.0f / Cdim) - mu * mu;
    float inv = rsqrtf(var + 1e-5f);
    XW[(size_t)t * Cdim + c] = (val - mu) * inv * w[c] + b[c];
}

// ---------------- window reverse + roll(+3,+3) + residual + LN2 ----------------
__global__ void resid_ln2_kernel(const float* __restrict__ x,
                                 const float* __restrict__ Y,
                                 const float* __restrict__ w,
                                 const float* __restrict__ b,
                                 float* __restrict__ out,
                                 float* __restrict__ XN) {
    int t = blockIdx.x;
    int win = t / Nn, n = t - win * Nn;
    int bi = win >> 6, wi = win & 63;
    int hs = ((wi >> 3) * WS + n / WS + SHIFT) % Hdim;
    int ws = ((wi & 7) * WS + n % WS + SHIFT) % Wdim;
    size_t pos = ((size_t)bi * (Hdim * Wdim) + hs * Wdim + ws) * Cdim;
    int c = threadIdx.x;
    float val = x[pos + c] + Y[(size_t)t * Cdim + c];
    out[pos + c] = val;                  // X2 residual base lives in d_out
    __shared__ float red[8];
    float s = val, s2 = val * val;
    #pragma unroll
    for (int o = 16; o > 0; o >>= 1) {
        s  += __shfl_down_sync(0xffffffffu, s, o);
        s2 += __shfl_down_sync(0xffffffffu, s2, o);
    }
    int lane = c & 31, wd = c >> 5;
    if (lane == 0) { red[wd] = s; red[4 + wd] = s2; }
    __syncthreads();
    s  = red[0] + red[1] + red[2] + red[3];
    s2 = red[4] + red[5] + red[6] + red[7];
    float mu  = s * (1.0f / Cdim);
    float var = s2 * (1.0f / Cdim) - mu * mu;
    float inv = rsqrtf(var + 1e-5f);
    XN[pos + c] = (val - mu) * inv * w[c] + b[c];
}

// ---------------- TF32 tensor-core GEMM: C = beta*C + alpha*act(A @ B^T + bias) ----------------
// A: M x K row-major (M % 128 == 0, K % 32 == 0), B: N x K row-major, C: M x N
#define BM 128
#define BN 128
#define BK 32
#define PAD 36

__device__ __forceinline__ uint32_t f2tf32(float f) {
    uint32_t u; asm("cvt.rna.tf32.f32 %0, %1;" : "=r"(u) : "f"(f)); return u;
}
__device__ __forceinline__ void mma_tf32(float* c, const uint32_t* a, uint32_t b0, uint32_t b1) {
    asm volatile("mma.sync.aligned.m16n8k8.row.col.f32.tf32.tf32.f32 "
        "{%0,%1,%2,%3}, {%4,%5,%6,%7}, {%8,%9}, {%0,%1,%2,%3};\n"
        : "+f"(c[0]), "+f"(c[1]), "+f"(c[2]), "+f"(c[3])
        : "r"(a[0]), "r"(a[1]), "r"(a[2]), "r"(a[3]), "r"(b0), "r"(b1));
}

__global__ __launch_bounds__(256) void tgemm(
    const float* __restrict__ A, int lda,
    const float* __restrict__ B, int ldb,
    const float* __restrict__ bias,
    float* __restrict__ C, int ldc,
    int M, int N, int K,
    const float* __restrict__ alphaPtr, int alphaIdx,
    int betaOne, int doGelu) {
    __shared__ uint32_t As[BM * PAD];
    __shared__ uint32_t Bs[BN * PAD];

    const int tid = threadIdx.x;
    const int bm = blockIdx.y * BM;
    const int bn = blockIdx.x * BN;
    const int wid = tid >> 5, lane = tid & 31;
    const int wm = (wid & 3) * 32;     // warp m offset in tile
    const int wn = (wid >> 2) * 64;    // warp n offset in tile
    const int g = lane >> 2, t4 = lane & 3;

    float acc[2][8][4];
    #pragma unroll
    for (int i = 0; i < 2; i++)
        #pragma unroll
        for (int j = 0; j < 8; j++)
            #pragma unroll
            for (int q = 0; q < 4; q++) acc[i][j][q] = 0.0f;

    const int lrow = tid >> 3;         // 0..31
    const int lcol = (tid & 7) * 4;    // 0..28
    const float* Ag = A + (size_t)(bm + lrow) * lda + lcol;
    const float* Bg = B + (size_t)(bn + lrow) * ldb + lcol;

    for (int k0 = 0; k0 < K; k0 += BK) {
        #pragma unroll
        for (int r = 0; r < 4; r++) {
            int row = lrow + r * 32;
            float4 av = *(const float4*)(Ag + (size_t)r * 32 * lda + k0);
            uint4 au;
            au.x = f2tf32(av.x); au.y = f2tf32(av.y);
            au.z = f2tf32(av.z); au.w = f2tf32(av.w);
            *(uint4*)&As[row * PAD + lcol] = au;
            float4 bv = make_float4(0.f, 0.f, 0.f, 0.f);
            if (bn + row < N) bv = *(const float4*)(Bg + (size_t)r * 32 * ldb + k0);
            uint4 bu;
            bu.x = f2tf32(bv.x); bu.y = f2tf32(bv.y);
            bu.z = f2tf32(bv.z); bu.w = f2tf32(bv.w);
            *(uint4*)&Bs[row * PAD + lcol] = bu;
        }
        __syncthreads();
        #pragma unroll
        for (int ks = 0; ks < 4; ks++) {
            const int kb = ks * 8;
            uint32_t af[2][4];
            #pragma unroll
            for (int mt = 0; mt < 2; mt++) {
                int r = wm + mt * 16 + g;
                af[mt][0] = As[r * PAD + kb + t4];
                af[mt][1] = As[(r + 8) * PAD + kb + t4];
                af[mt][2] = As[r * PAD + kb + t4 + 4];
                af[mt][3] = As[(r + 8) * PAD + kb + t4 + 4];
            }
            #pragma unroll
            for (int nt = 0; nt < 8; nt++) {
                int c = wn + nt * 8 + g;
                uint32_t b0 = Bs[c * PAD + kb + t4];
                uint32_t b1 = Bs[c * PAD + kb + t4 + 4];
                mma_tf32(acc[0][nt], af[0], b0, b1);
                mma_tf32(acc[1][nt], af[1], b0, b1);
            }
        }
        __syncthreads();
    }

    const float alpha = alphaPtr ? __ldg(&alphaPtr[alphaIdx]) : 1.0f;
    #pragma unroll
    for (int nt = 0; nt < 8; nt++) {
        int c0 = bn + wn + nt * 8 + t4 * 2;
        if (c0 >= N) continue;
        float bv0 = bias ? bias[c0] : 0.0f;
        float bv1 = bias ? bias[c0 + 1] : 0.0f;
        #pragma unroll
        for (int mt = 0; mt < 2; mt++) {
            #pragma unroll
            for (int half = 0; half < 2; half++) {
                int r = bm + wm + mt * 16 + g + half * 8;
                float v0 = acc[mt][nt][half * 2 + 0] + bv0;
                float v1 = acc[mt][nt][half * 2 + 1] + bv1;
                if (doGelu) {
                    v0 = 0.5f * v0 * (1.0f + erff(v0 * 0.70710678118654752f));
                    v1 = 0.5f * v1 * (1.0f + erff(v1 * 0.70710678118654752f));
                }
                v0 *= alpha; v1 *= alpha;
                size_t off = (size_t)r * ldc + c0;
                if (betaOne) {
                    float2 old = *(const float2*)(C + off);
                    v0 += old.x; v1 += old.y;
                }
                *(float2*)(C + off) = make_float2(v0, v1);
            }
        }
    }
}

// ---------------- fused window attention (one block per window x head) ----------------
__global__ __launch_bounds__(128) void attn_kernel(
    const float* __restrict__ QKV,      // (TOK_HALF, 384)
    const float* __restrict__ rbt,      // (169, 4)
    const int*   __restrict__ relIdx,   // (49, 49)
    const float* __restrict__ mask,     // (64, 49, 49)
    float* __restrict__ O,              // (TOK_HALF, 128)
    int winBase) {
    int lw = blockIdx.x;   // local window (0..2047)
    int h  = blockIdx.y;   // head
    int mi = (winBase + lw) & 63;
    __shared__ float sq[Nn][HDd], sk[Nn][HDd], sv[Nn][HDd];
    __shared__ float sS[Nn][Nn + 1];
    int tid = threadIdx.x;

    const float* base = QKV + (size_t)lw * Nn * 384;
    for (int idx = tid; idx < Nn * HDd; idx += 128) {
        int n = idx >> 5, d = idx & 31;
        const float* row = base + n * 384;
        int col = h * HDd + d;
        sq[n][d] = row[col] * SCALE;
        sk[n][d] = row[128 + col];
        sv[n][d] = row[256 + col];
    }
    __syncthreads();

    const float* mrow = mask + (size_t)mi * (Nn * Nn);
    for (int idx = tid; idx < Nn * Nn; idx += 128) {
        int n = idx / Nn, m = idx - n * Nn;
        float acc = 0.0f;
        #pragma unroll
        for (int d = 0; d < HDd; d++) acc += sq[n][d] * sk[m][d];
        acc += __ldg(&rbt[relIdx[idx] * NHn + h]);
        acc += mrow[idx];
        sS[n][m] = acc;
    }
    __syncthreads();

    if (tid < Nn) {
        float mx = -1e30f;
        for (int m = 0; m < Nn; m++) mx = fmaxf(mx, sS[tid][m]);
        float sum = 0.0f;
        for (int m = 0; m < Nn; m++) { float e = expf(sS[tid][m] - mx); sS[tid][m] = e; sum += e; }
        float r = 1.0f / sum;
        for (int m = 0; m < Nn; m++) sS[tid][m] *= r;
    }
    __syncthreads();

    for (int idx = tid; idx < Nn * HDd; idx += 128) {
        int n = idx >> 5, d = idx & 31;
        float acc = 0.0f;
        #pragma unroll
        for (int m = 0; m < Nn; m++) acc += sS[n][m] * sv[m][d];
        O[(size_t)(lw * Nn + n) * Cdim + h * HDd + d] = acc;
    }
}

// ---------------- host-side helpers ----------------
static inline void launch_gemm(const float* A, int lda, const float* B, int ldb,
                               const float* bias, float* C, int ldc,
                               int M, int N, int K,
                               const float* aP, int ai, int betaOne, int gelu) {
    dim3 grid((N + BN - 1) / BN, M / BM);
    tgemm<<<grid, 256>>>(A, lda, B, ldb, bias, C, ldc, M, N, K, aP, ai, betaOne, gelu);
}

extern "C" void kernel_launch(void* const* d_in, const int* in_sizes, int n_in,
                              void* d_out, int out_size) {
    const float* x     = (const float*)d_in[0];
    const float* gw    = (const float*)d_in[1];
    const float* n1w   = (const float*)d_in[2];
    const float* n1b   = (const float*)d_in[3];
    const float* qkvw  = (const float*)d_in[4];
    const float* qkvb  = (const float*)d_in[5];
    const float* rbt   = (const float*)d_in[6];
    const float* projw = (const float*)d_in[7];
    const float* projb = (const float*)d_in[8];
    const float* amask = (const float*)d_in[9];
    const float* n2w   = (const float*)d_in[10];
    const float* n2b   = (const float*)d_in[11];
    const float* f1w   = (const float*)d_in[12];
    const float* f1b   = (const float*)d_in[13];
    const float* f2w   = (const float*)d_in[14];
    const float* f2b   = (const float*)d_in[15];
    const int*   relIdx= (const int*)d_in[16];
    float* out = (float*)d_out;

    float *XW, *QKV, *O, *Y, *XN, *Hb;
    cudaGetSymbolAddress((void**)&XW,  g_XW);
    cudaGetSymbolAddress((void**)&QKV, g_QKV);
    cudaGetSymbolAddress((void**)&O,   g_O);
    cudaGetSymbolAddress((void**)&Y,   g_Y);
    cudaGetSymbolAddress((void**)&XN,  g_XN);
    cudaGetSymbolAddress((void**)&Hb,  g_H);

    const int Mh = TOK_HALF;         // 100352 rows per half
    const int Ks[3] = {128, 64, 32}; // C/alpha for alpha = 1,2,4

    // LN1 + shift + window partition
    ln1_part_kernel<<<TOK_TOTAL, 128>>>(x, n1w, n1b, XW);

    // ---- attention, large branch (first half of windows) ----
    launch_gemm(XW, Cdim, qkvw, Cdim, qkvb, QKV, 384, Mh, 384, 128, nullptr, 0, 0, 0);
    attn_kernel<<<dim3(NWIN_HALF, NHn), 128>>>(QKV, rbt, relIdx, amask, O, 0);
    launch_gemm(O, Cdim, projw, Cdim, projb, Y, Cdim, Mh, 128, 128, nullptr, 0, 0, 0);

    // ---- attention, gumbel-mixed sub-network branch (second half) ----
    for (int v = 0; v < 3; v++) {
        launch_gemm(XW + (size_t)Mh * Cdim, Cdim, qkvw, Cdim, qkvb, QKV, 384,
                    Mh, 384, Ks[v], nullptr, 0, 0, 0);
        attn_kernel<<<dim3(NWIN_HALF, NHn), 128>>>(QKV, rbt, relIdx, amask, O, NWIN_HALF);
        launch_gemm(O, Cdim, projw, Cdim, projb, Y + (size_t)Mh * Cdim, Cdim,
                    Mh, Ks[v], 128, gw, v, (v > 0) ? 1 : 0, 0);
    }

    // window reverse + shift back + residual; d_out := X2; XN := LN2(X2)
    resid_ln2_kernel<<<TOK_TOTAL, 128>>>(x, Y, n2w, n2b, out, XN);

    // ---- MLP, large branch (first 32 images) ----
    launch_gemm(XN, Cdim, f1w, Cdim, f1b, Hb, HID, Mh, HID, 128, nullptr, 0, 0, 1);
    launch_gemm(Hb, HID, f2w, HID, f2b, out, Cdim, Mh, 128, HID, nullptr, 0, 1, 0);

    // ---- MLP, sub-network branch (last 32 images) ----
    for (int v = 0; v < 3; v++) {
        launch_gemm(XN + (size_t)Mh * Cdim, Cdim, f1w, Cdim, f1b, Hb, HID,
                    Mh, HID, Ks[v], nullptr, 0, 0, 1);
        launch_gemm(Hb, HID, f2w, HID, f2b, out + (size_t)Mh * Cdim, Cdim,
                    Mh, Ks[v], HID, gw, v, 1, 0);
    }
}

// round 3
// speedup vs baseline: 2.3155x; 1.7101x over previous
#include <cuda_runtime.h>
#include <cuda_bf16.h>
#include <cstdint>
#include <cstddef>
#include <math.h>

// ---------------- problem constants ----------------
#define Bimg 64
#define Hdim 56
#define Wdim 56
#define WS 7
#define SHIFT 3
#define Cdim 128
#define NHn 4
#define HDd 32
#define Nn 49
#define NWn 64
#define HID 512
#define SCALE 0.17677669529663688f

#define NWIN_TOTAL (Bimg * NWn)          // 4096
#define NWIN_HALF  (NWIN_TOTAL / 2)      // 2048
#define TOK_TOTAL  (NWIN_TOTAL * Nn)     // 200704
#define TOK_HALF   (NWIN_HALF * Nn)      // 100352

// ---------------- scratch (device globals) ----------------
__device__ float g_XW  [(size_t)TOK_TOTAL * Cdim];
__device__ float g_QKVf[(size_t)TOK_TOTAL * 384];
__device__ float g_QKV1[(size_t)TOK_HALF  * 384];
__device__ float g_QKV2[(size_t)TOK_HALF  * 384];
__device__ float g_O   [(size_t)TOK_TOTAL * Cdim];
__device__ float g_Oh  [(size_t)TOK_HALF  * Cdim];
__device__ float g_Y   [(size_t)TOK_TOTAL * Cdim];
__device__ float g_XN  [(size_t)TOK_TOTAL * Cdim];
__device__ float g_H   [(size_t)TOK_TOTAL * HID];
__device__ float g_CB  [(size_t)NWn * NHn * Nn * Nn];   // fused rel-bias + shift mask

// ---------------- fused bias+mask precompute ----------------
__global__ void bias_combine_kernel(const float* __restrict__ rbt,
                                    const int*   __restrict__ relIdx,
                                    const float* __restrict__ mask,
                                    float* __restrict__ CB) {
    int mi = blockIdx.x, h = blockIdx.y;
    float* dst = CB + ((size_t)mi * NHn + h) * (Nn * Nn);
    const float* msk = mask + (size_t)mi * (Nn * Nn);
    for (int idx = threadIdx.x; idx < Nn * Nn; idx += blockDim.x)
        dst[idx] = __ldg(&rbt[relIdx[idx] * NHn + h]) + msk[idx];
}

// ---------------- LN1 + roll(-3,-3) + window partition (warp per token) ----------------
__global__ __launch_bounds__(256) void ln1_part_kernel(const float* __restrict__ x,
                                const float* __restrict__ w,
                                const float* __restrict__ b,
                                float* __restrict__ XW) {
    int t = blockIdx.x * 8 + (threadIdx.x >> 5);
    int lane = threadIdx.x & 31;
    int win = t / Nn, n = t - win * Nn;
    int bi = win >> 6, wi = win & 63;
    int hs = ((wi >> 3) * WS + n / WS + SHIFT) % Hdim;
    int ws = ((wi & 7) * WS + n % WS + SHIFT) % Wdim;
    const float* xp = x + ((size_t)bi * (Hdim * Wdim) + hs * Wdim + ws) * Cdim;
    float4 v = *(const float4*)(xp + lane * 4);
    float s  = v.x + v.y + v.z + v.w;
    float s2 = v.x * v.x + v.y * v.y + v.z * v.z + v.w * v.w;
    #pragma unroll
    for (int o = 16; o > 0; o >>= 1) {
        s  += __shfl_xor_sync(0xffffffffu, s, o);
        s2 += __shfl_xor_sync(0xffffffffu, s2, o);
    }
    float mu  = s * (1.0f / Cdim);
    float var = s2 * (1.0f / Cdim) - mu * mu;
    float inv = rsqrtf(var + 1e-5f);
    float4 wv = *(const float4*)(w + lane * 4);
    float4 bv = *(const float4*)(b + lane * 4);
    float4 o;
    o.x = (v.x - mu) * inv * wv.x + bv.x;
    o.y = (v.y - mu) * inv * wv.y + bv.y;
    o.z = (v.z - mu) * inv * wv.z + bv.z;
    o.w = (v.w - mu) * inv * wv.w + bv.w;
    *(float4*)(XW + (size_t)t * Cdim + lane * 4) = o;
}

// ---------------- window reverse + roll + residual + LN2 (warp per token) ----------------
__global__ __launch_bounds__(256) void resid_ln2_kernel(const float* __restrict__ x,
                                 const float* __restrict__ Y,
                                 const float* __restrict__ w,
                                 const float* __restrict__ b,
                                 float* __restrict__ out,
                                 float* __restrict__ XN) {
    int t = blockIdx.x * 8 + (threadIdx.x >> 5);
    int lane = threadIdx.x & 31;
    int win = t / Nn, n = t - win * Nn;
    int bi = win >> 6, wi = win & 63;
    int hs = ((wi >> 3) * WS + n / WS + SHIFT) % Hdim;
    int ws = ((wi & 7) * WS + n % WS + SHIFT) % Wdim;
    size_t pos = ((size_t)bi * (Hdim * Wdim) + hs * Wdim + ws) * Cdim;
    float4 xv = *(const float4*)(x + pos + lane * 4);
    float4 yv = *(const float4*)(Y + (size_t)t * Cdim + lane * 4);
    float4 v;
    v.x = xv.x + yv.x; v.y = xv.y + yv.y; v.z = xv.z + yv.z; v.w = xv.w + yv.w;
    *(float4*)(out + pos + lane * 4) = v;
    float s  = v.x + v.y + v.z + v.w;
    float s2 = v.x * v.x + v.y * v.y + v.z * v.z + v.w * v.w;
    #pragma unroll
    for (int o = 16; o > 0; o >>= 1) {
        s  += __shfl_xor_sync(0xffffffffu, s, o);
        s2 += __shfl_xor_sync(0xffffffffu, s2, o);
    }
    float mu  = s * (1.0f / Cdim);
    float var = s2 * (1.0f / Cdim) - mu * mu;
    float inv = rsqrtf(var + 1e-5f);
    float4 wv = *(const float4*)(w + lane * 4);
    float4 bv = *(const float4*)(b + lane * 4);
    float4 o;
    o.x = (v.x - mu) * inv * wv.x + bv.x;
    o.y = (v.y - mu) * inv * wv.y + bv.y;
    o.z = (v.z - mu) * inv * wv.z + bv.z;
    o.w = (v.w - mu) * inv * wv.w + bv.w;
    *(float4*)(XN + pos + lane * 4) = o;
}

// ---------------- TF32 tensor-core GEMM, double-buffered ----------------
// C = beta*C + alpha*act(A @ B^T + bias); alphaMode: 0=1.0, 1=gw[ai], 2=row-split gw[0]
#define BM 128
#define BN 128
#define BK 32
#define PAD 36

__device__ __forceinline__ uint32_t f2tf32(float f) {
    uint32_t u; asm("cvt.rna.tf32.f32 %0, %1;" : "=r"(u) : "f"(f)); return u;
}
__device__ __forceinline__ void mma_tf32(float* c, const uint32_t* a, uint32_t b0, uint32_t b1) {
    asm volatile("mma.sync.aligned.m16n8k8.row.col.f32.tf32.tf32.f32 "
        "{%0,%1,%2,%3}, {%4,%5,%6,%7}, {%8,%9}, {%0,%1,%2,%3};\n"
        : "+f"(c[0]), "+f"(c[1]), "+f"(c[2]), "+f"(c[3])
        : "r"(a[0]), "r"(a[1]), "r"(a[2]), "r"(a[3]), "r"(b0), "r"(b1));
}

__global__ __launch_bounds__(256, 2) void tgemm(
    const float* __restrict__ A, int lda,
    const float* __restrict__ B, int ldb,
    const float* __restrict__ bias,
    float* __restrict__ C, int ldc,
    int M, int N, int K,
    const float* __restrict__ gwPtr, int alphaIdx, int alphaMode, int splitM,
    int betaOne, int doGelu) {
    __shared__ uint32_t As[2][BM * PAD];
    __shared__ uint32_t Bs[2][BN * PAD];

    const int tid = threadIdx.x;
    const int bm = blockIdx.y * BM;
    const int bn = blockIdx.x * BN;
    const int wid = tid >> 5, lane = tid & 31;
    const int wm = (wid & 3) * 32;
    const int wn = (wid >> 2) * 64;
    const int g = lane >> 2, t4 = lane & 3;

    float acc[2][8][4];
    #pragma unroll
    for (int i = 0; i < 2; i++)
        #pragma unroll
        for (int j = 0; j < 8; j++)
            #pragma unroll
            for (int q = 0; q < 4; q++) acc[i][j][q] = 0.0f;

    const int lrow = tid >> 3;
    const int lcol = (tid & 7) * 4;
    const float* Ag = A + (size_t)(bm + lrow) * lda + lcol;
    const float* Bg = B + (size_t)(bn + lrow) * ldb + lcol;

    float4 ar[4], br[4];
    #pragma unroll
    for (int r = 0; r < 4; r++) {
        ar[r] = *(const float4*)(Ag + (size_t)r * 32 * lda);
        br[r] = (bn + lrow + r * 32 < N) ? *(const float4*)(Bg + (size_t)r * 32 * ldb)
                                         : make_float4(0.f, 0.f, 0.f, 0.f);
    }

    int buf = 0;
    for (int k0 = 0; k0 < K; k0 += BK) {
        #pragma unroll
        for (int r = 0; r < 4; r++) {
            int row = lrow + r * 32;
            uint4 au, bu;
            au.x = f2tf32(ar[r].x); au.y = f2tf32(ar[r].y);
            au.z = f2tf32(ar[r].z); au.w = f2tf32(ar[r].w);
            bu.x = f2tf32(br[r].x); bu.y = f2tf32(br[r].y);
            bu.z = f2tf32(br[r].z); bu.w = f2tf32(br[r].w);
            *(uint4*)&As[buf][row * PAD + lcol] = au;
            *(uint4*)&Bs[buf][row * PAD + lcol] = bu;
        }
        __syncthreads();
        if (k0 + BK < K) {
            #pragma unroll
            for (int r = 0; r < 4; r++) {
                ar[r] = *(const float4*)(Ag + (size_t)r * 32 * lda + k0 + BK);
                br[r] = (bn + lrow + r * 32 < N) ? *(const float4*)(Bg + (size_t)r * 32 * ldb + k0 + BK)
                                                 : make_float4(0.f, 0.f, 0.f, 0.f);
            }
        }
        #pragma unroll
        for (int ks = 0; ks < 4; ks++) {
            const int kb = ks * 8;
            uint32_t af[2][4];
            #pragma unroll
            for (int mt = 0; mt < 2; mt++) {
                int r = wm + mt * 16 + g;
                af[mt][0] = As[buf][r * PAD + kb + t4];
                af[mt][1] = As[buf][(r + 8) * PAD + kb + t4];
                af[mt][2] = As[buf][r * PAD + kb + t4 + 4];
                af[mt][3] = As[buf][(r + 8) * PAD + kb + t4 + 4];
            }
            #pragma unroll
            for (int nt = 0; nt < 8; nt++) {
                int c = wn + nt * 8 + g;
                uint32_t b0 = Bs[buf][c * PAD + kb + t4];
                uint32_t b1 = Bs[buf][c * PAD + kb + t4 + 4];
                mma_tf32(acc[0][nt], af[0], b0, b1);
                mma_tf32(acc[1][nt], af[1], b0, b1);
            }
        }
        buf ^= 1;
    }

    float alpha = 1.0f;
    if (alphaMode == 1) alpha = __ldg(&gwPtr[alphaIdx]);
    else if (alphaMode == 2 && bm >= splitM) alpha = __ldg(&gwPtr[0]);

    #pragma unroll
    for (int nt = 0; nt < 8; nt++) {
        int c0 = bn + wn + nt * 8 + t4 * 2;
        if (c0 >= N) continue;
        float bv0 = bias ? bias[c0] : 0.0f;
        float bv1 = bias ? bias[c0 + 1] : 0.0f;
        #pragma unroll
        for (int mt = 0; mt < 2; mt++) {
            #pragma unroll
            for (int half = 0; half < 2; half++) {
                int r = bm + wm + mt * 16 + g + half * 8;
                float v0 = acc[mt][nt][half * 2 + 0] + bv0;
                float v1 = acc[mt][nt][half * 2 + 1] + bv1;
                if (doGelu) {
                    v0 = 0.5f * v0 * (1.0f + erff(v0 * 0.70710678118654752f));
                    v1 = 0.5f * v1 * (1.0f + erff(v1 * 0.70710678118654752f));
                }
                v0 *= alpha; v1 *= alpha;
                size_t off = (size_t)r * ldc + c0;
                if (betaOne) {
                    float2 old = *(const float2*)(C + off);
                    v0 += old.x; v1 += old.y;
                }
                *(float2*)(C + off) = make_float2(v0, v1);
            }
        }
    }
}

// ---------------- fused window attention ----------------
#define QPAD 36
#define SPAD 52
__global__ __launch_bounds__(128) void attn_kernel(
    const float* __restrict__ QKV,   // (nwin*49, 384)
    const float* __restrict__ CB,    // (64, 4, 49*49) fused bias+mask
    float* __restrict__ O) {         // (nwin*49, 128)
    const int lw = blockIdx.x;
    const int h  = blockIdx.y;
    const int mi = lw & 63;
    __shared__ float sq[Nn * QPAD], sk[Nn * QPAD], sv[Nn * QPAD];
    __shared__ float sS[Nn * SPAD];
    const int tid = threadIdx.x;

    const float* base = QKV + (size_t)lw * Nn * 384 + h * HDd;
    for (int idx = tid; idx < Nn * HDd; idx += 128) {
        int n = idx >> 5, d = idx & 31;
        const float* row = base + n * 384;
        sq[n * QPAD + d] = row[d] * SCALE;
        sk[n * QPAD + d] = row[128 + d];
        sv[n * QPAD + d] = row[256 + d];
    }
    __syncthreads();

    const float* cb = CB + ((size_t)mi * NHn + h) * (Nn * Nn);
    for (int idx = tid; idx < Nn * Nn; idx += 128) {
        int n = idx / Nn, m = idx - n * Nn;
        const float4* aq = (const float4*)&sq[n * QPAD];
        const float4* ak = (const float4*)&sk[m * QPAD];
        float acc = 0.0f;
        #pragma unroll
        for (int j = 0; j < 8; j++) {
            float4 a = aq[j], b = ak[j];
            acc += a.x * b.x + a.y * b.y + a.z * b.z + a.w * b.w;
        }
        sS[n * SPAD + m] = acc + __ldg(&cb[idx]);
    }
    __syncthreads();

    if (tid < Nn) {
        float* row = &sS[tid * SPAD];
        float mx = -1e30f;
        #pragma unroll
        for (int m = 0; m < Nn; m++) mx = fmaxf(mx, row[m]);
        float sum = 0.0f;
        #pragma unroll
        for (int m = 0; m < Nn; m++) { float e = __expf(row[m] - mx); row[m] = e; sum += e; }
        float r = 1.0f / sum;
        #pragma unroll
        for (int m = 0; m < Nn; m++) row[m] *= r;
    }
    __syncthreads();

    for (int t = tid; t < Nn * 8; t += 128) {
        int n = t >> 3, d4 = (t & 7) << 2;
        float4 acc = make_float4(0.f, 0.f, 0.f, 0.f);
        const float* srow = &sS[n * SPAD];
        #pragma unroll
        for (int m4 = 0; m4 < 12; m4++) {
            float4 s4 = *(const float4*)&srow[m4 * 4];
            float4 v0 = *(const float4*)&sv[(m4 * 4 + 0) * QPAD + d4];
            float4 v1 = *(const float4*)&sv[(m4 * 4 + 1) * QPAD + d4];
            float4 v2 = *(const float4*)&sv[(m4 * 4 + 2) * QPAD + d4];
            float4 v3 = *(const float4*)&sv[(m4 * 4 + 3) * QPAD + d4];
            acc.x += s4.x * v0.x + s4.y * v1.x + s4.z * v2.x + s4.w * v3.x;
            acc.y += s4.x * v0.y + s4.y * v1.y + s4.z * v2.y + s4.w * v3.y;
            acc.z += s4.x * v0.z + s4.y * v1.z + s4.z * v2.z + s4.w * v3.z;
            acc.w += s4.x * v0.w + s4.y * v1.w + s4.z * v2.w + s4.w * v3.w;
        }
        {
            float s = srow[48];
            float4 v = *(const float4*)&sv[48 * QPAD + d4];
            acc.x += s * v.x; acc.y += s * v.y; acc.z += s * v.z; acc.w += s * v.w;
        }
        *(float4*)(O + (size_t)(lw * Nn + n) * Cdim + h * HDd + d4) = acc;
    }
}

// ---------------- host helpers ----------------
static inline void launch_gemm(const float* A, int lda, const float* B, int ldb,
                               const float* bias, float* C, int ldc,
                               int M, int N, int K,
                               const float* gwP, int ai, int aMode, int splitM,
                               int betaOne, int gelu) {
    dim3 grid((N + BN - 1) / BN, M / BM);
    tgemm<<<grid, 256>>>(A, lda, B, ldb, bias, C, ldc, M, N, K,
                         gwP, ai, aMode, splitM, betaOne, gelu);
}

extern "C" void kernel_launch(void* const* d_in, const int* in_sizes, int n_in,
                              void* d_out, int out_size) {
    const float* x     = (const float*)d_in[0];
    const float* gw    = (const float*)d_in[1];
    const float* n1w   = (const float*)d_in[2];
    const float* n1b   = (const float*)d_in[3];
    const float* qkvw  = (const float*)d_in[4];
    const float* qkvb  = (const float*)d_in[5];
    const float* rbt   = (const float*)d_in[6];
    const float* projw = (const float*)d_in[7];
    const float* projb = (const float*)d_in[8];
    const float* amask = (const float*)d_in[9];
    const float* n2w   = (const float*)d_in[10];
    const float* n2b   = (const float*)d_in[11];
    const float* f1w   = (const float*)d_in[12];
    const float* f1b   = (const float*)d_in[13];
    const float* f2w   = (const float*)d_in[14];
    const float* f2b   = (const float*)d_in[15];
    const int*   relIdx= (const int*)d_in[16];
    float* out = (float*)d_out;

    float *XW, *QKVf, *QKV1, *QKV2, *O, *Oh, *Y, *XN, *Hb, *CB;
    cudaGetSymbolAddress((void**)&XW,   g_XW);
    cudaGetSymbolAddress((void**)&QKVf, g_QKVf);
    cudaGetSymbolAddress((void**)&QKV1, g_QKV1);
    cudaGetSymbolAddress((void**)&QKV2, g_QKV2);
    cudaGetSymbolAddress((void**)&O,    g_O);
    cudaGetSymbolAddress((void**)&Oh,   g_Oh);
    cudaGetSymbolAddress((void**)&Y,    g_Y);
    cudaGetSymbolAddress((void**)&XN,   g_XN);
    cudaGetSymbolAddress((void**)&Hb,   g_H);
    cudaGetSymbolAddress((void**)&CB,   g_CB);

    const int Mh = TOK_HALF;
    const int Mf = TOK_TOTAL;

    bias_combine_kernel<<<dim3(NWn, NHn), 256>>>(rbt, relIdx, amask, CB);
    ln1_part_kernel<<<TOK_TOTAL / 8, 256>>>(x, n1w, n1b, XW);

    // QKV: merged full (large + v0), then K-truncated variants on second half
    launch_gemm(XW, Cdim, qkvw, Cdim, qkvb, QKVf, 384, Mf, 384, 128, nullptr, 0, 0, 0, 0, 0);
    launch_gemm(XW + (size_t)Mh * Cdim, Cdim, qkvw, Cdim, qkvb, QKV1, 384, Mh, 384, 64,  nullptr, 0, 0, 0, 0, 0);
    launch_gemm(XW + (size_t)Mh * Cdim, Cdim, qkvw, Cdim, qkvb, QKV2, 384, Mh, 384, 32,  nullptr, 0, 0, 0, 0, 0);

    // attention: one merged launch for large+v0, then variants
    attn_kernel<<<dim3(NWIN_TOTAL, NHn), 128>>>(QKVf, CB, O);
    // proj merged: rows < Mh alpha=1 (large), rows >= Mh alpha=gw[0] (v0)
    launch_gemm(O, Cdim, projw, Cdim, projb, Y, Cdim, Mf, 128, 128, gw, 0, 2, Mh, 0, 0);

    attn_kernel<<<dim3(NWIN_HALF, NHn), 128>>>(QKV1, CB, Oh);
    launch_gemm(Oh, Cdim, projw, Cdim, projb, Y + (size_t)Mh * Cdim, Cdim, Mh, 64, 128, gw, 1, 1, 0, 1, 0);

    attn_kernel<<<dim3(NWIN_HALF, NHn), 128>>>(QKV2, CB, Oh);
    launch_gemm(Oh, Cdim, projw, Cdim, projb, Y + (size_t)Mh * Cdim, Cdim, Mh, 32, 128, gw, 2, 1, 0, 1, 0);

    // residual + LN2
    resid_ln2_kernel<<<TOK_TOTAL / 8, 256>>>(x, Y, n2w, n2b, out, XN);

    // MLP: merged full (large + v0), then variants
    launch_gemm(XN, Cdim, f1w, Cdim, f1b, Hb, HID, Mf, HID, 128, nullptr, 0, 0, 0, 0, 1);
    launch_gemm(Hb, HID, f2w, HID, f2b, out, Cdim, Mf, 128, 512, gw, 0, 2, Mh, 1, 0);

    launch_gemm(XN + (size_t)Mh * Cdim, Cdim, f1w, Cdim, f1b, Hb + (size_t)Mh * HID, HID, Mh, HID, 64, nullptr, 0, 0, 0, 0, 1);
    launch_gemm(Hb + (size_t)Mh * HID, HID, f2w, HID, f2b, out + (size_t)Mh * Cdim, Cdim, Mh, 64, 512, gw, 1, 1, 0, 1, 0);

    launch_gemm(XN + (size_t)Mh * Cdim, Cdim, f1w, Cdim, f1b, Hb + (size_t)Mh * HID, HID, Mh, HID, 32, nullptr, 0, 0, 0, 0, 1);
    launch_gemm(Hb + (size_t)Mh * HID, HID, f2w, HID, f2b, out + (size_t)Mh * Cdim, Cdim, Mh, 32, 512, gw, 2, 1, 0, 1, 0);
}

// round 4
// speedup vs baseline: 3.5080x; 1.5150x over previous
#include <cuda_runtime.h>
#include <cuda_bf16.h>
#include <cstdint>
#include <cstddef>
#include <math.h>

// ---------------- problem constants ----------------
#define Bimg 64
#define Hdim 56
#define Wdim 56
#define WS 7
#define SHIFT 3
#define Cdim 128
#define NHn 4
#define HDd 32
#define Nn 49
#define NWn 64
#define HID 512
#define SCALE 0.17677669529663688f

#define NWIN_TOTAL (Bimg * NWn)          // 4096
#define NWIN_HALF  (NWIN_TOTAL / 2)      // 2048
#define TOK_TOTAL  (NWIN_TOTAL * Nn)     // 200704
#define TOK_HALF   (NWIN_HALF * Nn)      // 100352

// ---------------- scratch (device globals) ----------------
__device__ float g_XW  [(size_t)TOK_TOTAL * Cdim];
__device__ float g_QKVf[(size_t)TOK_TOTAL * 384];
__device__ float g_QKV1[(size_t)TOK_HALF  * 384];
__device__ float g_QKV2[(size_t)TOK_HALF  * 384];
__device__ float g_O   [(size_t)TOK_TOTAL * Cdim];
__device__ float g_Oh  [(size_t)TOK_HALF  * Cdim];
__device__ float g_Y   [(size_t)TOK_TOTAL * Cdim];
__device__ float g_XN  [(size_t)TOK_TOTAL * Cdim];
__device__ float g_H   [(size_t)TOK_TOTAL * HID];
__device__ float g_CB  [(size_t)NWn * NHn * Nn * Nn];
__device__ float g_Wr  [196608];   // tf32-rounded weights: qkvw|projw|f1w|f2w

__device__ __forceinline__ float rnd_tf32(float f) {
    uint32_t u; asm("cvt.rna.tf32.f32 %0, %1;" : "=r"(u) : "f"(f));
    return __uint_as_float(u);
}

// ---------------- weight rounding (tf32-exact operands) ----------------
__global__ void roundcopy_kernel(const float* __restrict__ src, float* __restrict__ dst) {
    int i = (blockIdx.x * 256 + threadIdx.x) * 4;
    float4 v = *(const float4*)(src + i);
    v.x = rnd_tf32(v.x); v.y = rnd_tf32(v.y); v.z = rnd_tf32(v.z); v.w = rnd_tf32(v.w);
    *(float4*)(dst + i) = v;
}

// ---------------- fused bias+mask precompute ----------------
__global__ void bias_combine_kernel(const float* __restrict__ rbt,
                                    const int*   __restrict__ relIdx,
                                    const float* __restrict__ mask,
                                    float* __restrict__ CB) {
    int mi = blockIdx.x, h = blockIdx.y;
    float* dst = CB + ((size_t)mi * NHn + h) * (Nn * Nn);
    const float* msk = mask + (size_t)mi * (Nn * Nn);
    for (int idx = threadIdx.x; idx < Nn * Nn; idx += blockDim.x)
        dst[idx] = __ldg(&rbt[relIdx[idx] * NHn + h]) + msk[idx];
}

// ---------------- LN1 + roll(-3,-3) + window partition ----------------
__global__ __launch_bounds__(256) void ln1_part_kernel(const float* __restrict__ x,
                                const float* __restrict__ w,
                                const float* __restrict__ b,
                                float* __restrict__ XW) {
    int t = blockIdx.x * 8 + (threadIdx.x >> 5);
    int lane = threadIdx.x & 31;
    int win = t / Nn, n = t - win * Nn;
    int bi = win >> 6, wi = win & 63;
    int hs = ((wi >> 3) * WS + n / WS + SHIFT) % Hdim;
    int ws = ((wi & 7) * WS + n % WS + SHIFT) % Wdim;
    const float* xp = x + ((size_t)bi * (Hdim * Wdim) + hs * Wdim + ws) * Cdim;
    float4 v = *(const float4*)(xp + lane * 4);
    float s  = v.x + v.y + v.z + v.w;
    float s2 = v.x * v.x + v.y * v.y + v.z * v.z + v.w * v.w;
    #pragma unroll
    for (int o = 16; o > 0; o >>= 1) {
        s  += __shfl_xor_sync(0xffffffffu, s, o);
        s2 += __shfl_xor_sync(0xffffffffu, s2, o);
    }
    float mu  = s * (1.0f / Cdim);
    float var = s2 * (1.0f / Cdim) - mu * mu;
    float inv = rsqrtf(var + 1e-5f);
    float4 wv = *(const float4*)(w + lane * 4);
    float4 bv = *(const float4*)(b + lane * 4);
    float4 o;
    o.x = rnd_tf32((v.x - mu) * inv * wv.x + bv.x);
    o.y = rnd_tf32((v.y - mu) * inv * wv.y + bv.y);
    o.z = rnd_tf32((v.z - mu) * inv * wv.z + bv.z);
    o.w = rnd_tf32((v.w - mu) * inv * wv.w + bv.w);
    *(float4*)(XW + (size_t)t * Cdim + lane * 4) = o;
}

// ---------------- window reverse + roll + residual + LN2 ----------------
__global__ __launch_bounds__(256) void resid_ln2_kernel(const float* __restrict__ x,
                                 const float* __restrict__ Y,
                                 const float* __restrict__ w,
                                 const float* __restrict__ b,
                                 float* __restrict__ out,
                                 float* __restrict__ XN) {
    int t = blockIdx.x * 8 + (threadIdx.x >> 5);
    int lane = threadIdx.x & 31;
    int win = t / Nn, n = t - win * Nn;
    int bi = win >> 6, wi = win & 63;
    int hs = ((wi >> 3) * WS + n / WS + SHIFT) % Hdim;
    int ws = ((wi & 7) * WS + n % WS + SHIFT) % Wdim;
    size_t pos = ((size_t)bi * (Hdim * Wdim) + hs * Wdim + ws) * Cdim;
    float4 xv = *(const float4*)(x + pos + lane * 4);
    float4 yv = *(const float4*)(Y + (size_t)t * Cdim + lane * 4);
    float4 v;
    v.x = xv.x + yv.x; v.y = xv.y + yv.y; v.z = xv.z + yv.z; v.w = xv.w + yv.w;
    *(float4*)(out + pos + lane * 4) = v;
    float s  = v.x + v.y + v.z + v.w;
    float s2 = v.x * v.x + v.y * v.y + v.z * v.z + v.w * v.w;
    #pragma unroll
    for (int o = 16; o > 0; o >>= 1) {
        s  += __shfl_xor_sync(0xffffffffu, s, o);
        s2 += __shfl_xor_sync(0xffffffffu, s2, o);
    }
    float mu  = s * (1.0f / Cdim);
    float var = s2 * (1.0f / Cdim) - mu * mu;
    float inv = rsqrtf(var + 1e-5f);
    float4 wv = *(const float4*)(w + lane * 4);
    float4 bv = *(const float4*)(b + lane * 4);
    float4 o;
    o.x = rnd_tf32((v.x - mu) * inv * wv.x + bv.x);
    o.y = rnd_tf32((v.y - mu) * inv * wv.y + bv.y);
    o.z = rnd_tf32((v.z - mu) * inv * wv.z + bv.z);
    o.w = rnd_tf32((v.w - mu) * inv * wv.w + bv.w);
    *(float4*)(XN + pos + lane * 4) = o;
}

// ---------------- mma helpers ----------------
__device__ __forceinline__ void mma_tf32(float* c, const uint32_t* a, uint32_t b0, uint32_t b1) {
    asm volatile("mma.sync.aligned.m16n8k8.row.col.f32.tf32.tf32.f32 "
        "{%0,%1,%2,%3}, {%4,%5,%6,%7}, {%8,%9}, {%0,%1,%2,%3};\n"
        : "+f"(c[0]), "+f"(c[1]), "+f"(c[2]), "+f"(c[3])
        : "r"(a[0]), "r"(a[1]), "r"(a[2]), "r"(a[3]), "r"(b0), "r"(b1));
}
__device__ __forceinline__ void cpa16(uint32_t dst, const void* src, bool pred) {
    int sz = pred ? 16 : 0;
    asm volatile("cp.async.cg.shared.global [%0], [%1], 16, %2;\n"
                 :: "r"(dst), "l"(src), "r"(sz));
}

// ---------------- TF32 GEMM, cp.async double-buffered ----------------
#define BM 128
#define BN 128
#define BK 32
#define PAD 36

__global__ __launch_bounds__(256, 2) void tgemm(
    const float* __restrict__ A, int lda,
    const float* __restrict__ B, int ldb,
    const float* __restrict__ bias,
    float* __restrict__ C, int ldc,
    int M, int N, int K,
    const float* __restrict__ gwPtr, int alphaIdx, int alphaMode, int splitM,
    int betaOne, int doGelu, int doRound) {
    __shared__ float As[2][BM * PAD];
    __shared__ float Bs[2][BN * PAD];

    const int tid = threadIdx.x;
    const int bm = blockIdx.y * BM;
    const int bn = blockIdx.x * BN;
    const int wid = tid >> 5, lane = tid & 31;
    const int wm = (wid & 3) * 32;
    const int wn = (wid >> 2) * 64;
    const int g = lane >> 2, t4 = lane & 3;

    float acc[2][8][4];
    #pragma unroll
    for (int i = 0; i < 2; i++)
        #pragma unroll
        for (int j = 0; j < 8; j++)
            #pragma unroll
            for (int q = 0; q < 4; q++) acc[i][j][q] = 0.0f;

    const int lrow = tid >> 3;
    const int lcol = (tid & 7) * 4;
    const float* Ag = A + (size_t)(bm + lrow) * lda + lcol;
    const float* Bg = B + (size_t)(bn + lrow) * ldb + lcol;
    uint32_t asA[2][4], asB[2][4];
    #pragma unroll
    for (int bf = 0; bf < 2; bf++)
        #pragma unroll
        for (int r = 0; r < 4; r++) {
            asA[bf][r] = (uint32_t)__cvta_generic_to_shared(&As[bf][(lrow + r * 32) * PAD + lcol]);
            asB[bf][r] = (uint32_t)__cvta_generic_to_shared(&Bs[bf][(lrow + r * 32) * PAD + lcol]);
        }

    // prologue
    #pragma unroll
    for (int r = 0; r < 4; r++) {
        cpa16(asA[0][r], Ag + (size_t)r * 32 * lda, true);
        cpa16(asB[0][r], Bg + (size_t)r * 32 * ldb, (bn + lrow + r * 32) < N);
    }
    asm volatile("cp.async.commit_group;\n");

    int buf = 0;
    for (int k0 = 0; k0 < K; k0 += BK) {
        if (k0 + BK < K) {
            #pragma unroll
            for (int r = 0; r < 4; r++) {
                cpa16(asA[buf ^ 1][r], Ag + (size_t)r * 32 * lda + k0 + BK, true);
                cpa16(asB[buf ^ 1][r], Bg + (size_t)r * 32 * ldb + k0 + BK, (bn + lrow + r * 32) < N);
            }
            asm volatile("cp.async.commit_group;\n");
            asm volatile("cp.async.wait_group 1;\n");
        } else {
            asm volatile("cp.async.wait_group 0;\n");
        }
        __syncthreads();
        #pragma unroll
        for (int ks = 0; ks < 4; ks++) {
            const int kb = ks * 8;
            uint32_t af[2][4];
            #pragma unroll
            for (int mt = 0; mt < 2; mt++) {
                int r = wm + mt * 16 + g;
                af[mt][0] = __float_as_uint(As[buf][r * PAD + kb + t4]);
                af[mt][1] = __float_as_uint(As[buf][(r + 8) * PAD + kb + t4]);
                af[mt][2] = __float_as_uint(As[buf][r * PAD + kb + t4 + 4]);
                af[mt][3] = __float_as_uint(As[buf][(r + 8) * PAD + kb + t4 + 4]);
            }
            #pragma unroll
            for (int nt = 0; nt < 8; nt++) {
                int c = wn + nt * 8 + g;
                uint32_t b0 = __float_as_uint(Bs[buf][c * PAD + kb + t4]);
                uint32_t b1 = __float_as_uint(Bs[buf][c * PAD + kb + t4 + 4]);
                mma_tf32(acc[0][nt], af[0], b0, b1);
                mma_tf32(acc[1][nt], af[1], b0, b1);
            }
        }
        __syncthreads();
        buf ^= 1;
    }

    float alpha = 1.0f;
    if (alphaMode == 1) alpha = __ldg(&gwPtr[alphaIdx]);
    else if (alphaMode == 2 && bm >= splitM) alpha = __ldg(&gwPtr[0]);

    #pragma unroll
    for (int nt = 0; nt < 8; nt++) {
        int c0 = bn + wn + nt * 8 + t4 * 2;
        if (c0 >= N) continue;
        float bv0 = bias ? bias[c0] : 0.0f;
        float bv1 = bias ? bias[c0 + 1] : 0.0f;
        #pragma unroll
        for (int mt = 0; mt < 2; mt++) {
            #pragma unroll
            for (int half = 0; half < 2; half++) {
                int r = bm + wm + mt * 16 + g + half * 8;
                float v0 = acc[mt][nt][half * 2 + 0] + bv0;
                float v1 = acc[mt][nt][half * 2 + 1] + bv1;
                if (doGelu) {
                    v0 = 0.5f * v0 * (1.0f + erff(v0 * 0.70710678118654752f));
                    v1 = 0.5f * v1 * (1.0f + erff(v1 * 0.70710678118654752f));
                }
                v0 *= alpha; v1 *= alpha;
                size_t off = (size_t)r * ldc + c0;
                if (betaOne) {
                    float2 old = *(const float2*)(C + off);
                    v0 += old.x; v1 += old.y;
                }
                if (doRound) { v0 = rnd_tf32(v0); v1 = rnd_tf32(v1); }
                *(float2*)(C + off) = make_float2(v0, v1);
            }
        }
    }
}

// ---------------- tensor-core window attention ----------------
// one block per (window, head); 4 warps; rows padded 49->64, cols 49->56
#define AQP 36
#define ASP 60
__global__ __launch_bounds__(128) void attn_kernel(
    const float* __restrict__ QKV,   // (nwin*49, 384), tf32-rounded
    const float* __restrict__ CB,    // (64, 4, 49*49)
    float* __restrict__ O) {         // (nwin*49, 128)
    const int lw = blockIdx.x;
    const int h  = blockIdx.y;
    const int mi = lw & 63;
    __shared__ float sq[64 * AQP];   // Q rows (pad rows zero)
    __shared__ float sk[56 * AQP];   // K rows (pad rows zero)
    __shared__ float sVt[32 * ASP];  // V transposed [d][m] (pad cols zero)
    __shared__ float sS[64 * ASP];   // scores / P
    const int tid = threadIdx.x;
    const int wid = tid >> 5, lane = tid & 31;
    const int g = lane >> 2, t4 = lane & 3;
    const int wr = wid * 16;

    const float* base = QKV + (size_t)lw * Nn * 384 + h * HDd;
    for (int idx = tid; idx < Nn * HDd; idx += 128) {
        int n = idx >> 5, d = idx & 31;
        const float* row = base + n * 384;
        sq[n * AQP + d]  = row[d];
        sk[n * AQP + d]  = row[128 + d];
        sVt[d * ASP + n] = row[256 + d];
    }
    for (int idx = tid; idx < 15 * 32; idx += 128) {       // q pad rows 49..63
        int n = 49 + (idx >> 5), d = idx & 31;
        sq[n * AQP + d] = 0.0f;
    }
    for (int idx = tid; idx < 7 * 32; idx += 128) {        // k pad rows 49..55
        int n = 49 + (idx >> 5), d = idx & 31;
        sk[n * AQP + d] = 0.0f;
    }
    for (int idx = tid; idx < 32 * 7; idx += 128) {        // v pad cols 49..55
        int d = idx >> 3, m = 49 + (idx & 7);
        sVt[d * ASP + m] = 0.0f;
    }
    __syncthreads();

    // ---- S = (Q @ K^T) * SCALE + CB ----
    const float* cb = CB + ((size_t)mi * NHn + h) * (Nn * Nn);
    {
        uint32_t aq[4][4];
        #pragma unroll
        for (int ks = 0; ks < 4; ks++) {
            int kb = ks * 8;
            int r = wr + g;
            aq[ks][0] = __float_as_uint(sq[r * AQP + kb + t4]);
            aq[ks][1] = __float_as_uint(sq[(r + 8) * AQP + kb + t4]);
            aq[ks][2] = __float_as_uint(sq[r * AQP + kb + t4 + 4]);
            aq[ks][3] = __float_as_uint(sq[(r + 8) * AQP + kb + t4 + 4]);
        }
        #pragma unroll
        for (int nt = 0; nt < 7; nt++) {
            float acc[4] = {0.f, 0.f, 0.f, 0.f};
            #pragma unroll
            for (int ks = 0; ks < 4; ks++) {
                int kb = ks * 8;
                uint32_t b0 = __float_as_uint(sk[(nt * 8 + g) * AQP + kb + t4]);
                uint32_t b1 = __float_as_uint(sk[(nt * 8 + g) * AQP + kb + t4 + 4]);
                mma_tf32(acc, aq[ks], b0, b1);
            }
            int col = nt * 8 + t4 * 2;
            #pragma unroll
            for (int half = 0; half < 2; half++) {
                int r = wr + g + half * 8;
                float v0 = acc[half * 2 + 0] * SCALE;
                float v1 = acc[half * 2 + 1] * SCALE;
                if (r < Nn) {
                    if (col < Nn)     v0 += __ldg(&cb[r * Nn + col]);
                    if (col + 1 < Nn) v1 += __ldg(&cb[r * Nn + col + 1]);
                }
                sS[r * ASP + col]     = v0;
                sS[r * ASP + col + 1] = v1;
            }
        }
    }
    __syncthreads();

    // ---- softmax over valid 49 cols, zero pad cols, round P to tf32 ----
    if (tid < Nn) {
        float* row = &sS[tid * ASP];
        float mx = -1e30f;
        #pragma unroll
        for (int m = 0; m < Nn; m++) mx = fmaxf(mx, row[m]);
        float sum = 0.0f;
        #pragma unroll
        for (int m = 0; m < Nn; m++) { float e = __expf(row[m] - mx); row[m] = e; sum += e; }
        float rs = 1.0f / sum;
        #pragma unroll
        for (int m = 0; m < Nn; m++) row[m] = rnd_tf32(row[m] * rs);
        #pragma unroll
        for (int m = Nn; m < 56; m++) row[m] = 0.0f;
    }
    __syncthreads();

    // ---- O = P @ V ----
    {
        uint32_t ap[7][4];
        #pragma unroll
        for (int ks = 0; ks < 7; ks++) {
            int kb = ks * 8;
            int r = wr + g;
            ap[ks][0] = __float_as_uint(sS[r * ASP + kb + t4]);
            ap[ks][1] = __float_as_uint(sS[(r + 8) * ASP + kb + t4]);
            ap[ks][2] = __float_as_uint(sS[r * ASP + kb + t4 + 4]);
            ap[ks][3] = __float_as_uint(sS[(r + 8) * ASP + kb + t4 + 4]);
        }
        #pragma unroll
        for (int nt = 0; nt < 4; nt++) {
            float acc[4] = {0.f, 0.f, 0.f, 0.f};
            #pragma unroll
            for (int ks = 0; ks < 7; ks++) {
                int kb = ks * 8;
                uint32_t b0 = __float_as_uint(sVt[(nt * 8 + g) * ASP + kb + t4]);
                uint32_t b1 = __float_as_uint(sVt[(nt * 8 + g) * ASP + kb + t4 + 4]);
                mma_tf32(acc, ap[ks], b0, b1);
            }
            int col = nt * 8 + t4 * 2;
            #pragma unroll
            for (int half = 0; half < 2; half++) {
                int r = wr + g + half * 8;
                if (r < Nn) {
                    float2 v;
                    v.x = rnd_tf32(acc[half * 2 + 0]);
                    v.y = rnd_tf32(acc[half * 2 + 1]);
                    *(float2*)(O + (size_t)(lw * Nn + r) * Cdim + h * HDd + col) = v;
                }
            }
        }
    }
}

// ---------------- host helpers ----------------
static inline void launch_gemm(const float* A, int lda, const float* B, int ldb,
                               const float* bias, float* C, int ldc,
                               int M, int N, int K,
                               const float* gwP, int ai, int aMode, int splitM,
                               int betaOne, int gelu, int doRound) {
    dim3 grid((N + BN - 1) / BN, M / BM);
    tgemm<<<grid, 256>>>(A, lda, B, ldb, bias, C, ldc, M, N, K,
                         gwP, ai, aMode, splitM, betaOne, gelu, doRound);
}

extern "C" void kernel_launch(void* const* d_in, const int* in_sizes, int n_in,
                              void* d_out, int out_size) {
    const float* x     = (const float*)d_in[0];
    const float* gw    = (const float*)d_in[1];
    const float* n1w   = (const float*)d_in[2];
    const float* n1b   = (const float*)d_in[3];
    const float* qkvw  = (const float*)d_in[4];
    const float* qkvb  = (const float*)d_in[5];
    const float* rbt   = (const float*)d_in[6];
    const float* projw = (const float*)d_in[7];
    const float* projb = (const float*)d_in[8];
    const float* amask = (const float*)d_in[9];
    const float* n2w   = (const float*)d_in[10];
    const float* n2b   = (const float*)d_in[11];
    const float* f1w   = (const float*)d_in[12];
    const float* f1b   = (const float*)d_in[13];
    const float* f2w   = (const float*)d_in[14];
    const float* f2b   = (const float*)d_in[15];
    const int*   relIdx= (const int*)d_in[16];
    float* out = (float*)d_out;

    float *XW, *QKVf, *QKV1, *QKV2, *O, *Oh, *Y, *XN, *Hb, *CB, *Wr;
    cudaGetSymbolAddress((void**)&XW,   g_XW);
    cudaGetSymbolAddress((void**)&QKVf, g_QKVf);
    cudaGetSymbolAddress((void**)&QKV1, g_QKV1);
    cudaGetSymbolAddress((void**)&QKV2, g_QKV2);
    cudaGetSymbolAddress((void**)&O,    g_O);
    cudaGetSymbolAddress((void**)&Oh,   g_Oh);
    cudaGetSymbolAddress((void**)&Y,    g_Y);
    cudaGetSymbolAddress((void**)&XN,   g_XN);
    cudaGetSymbolAddress((void**)&Hb,   g_H);
    cudaGetSymbolAddress((void**)&CB,   g_CB);
    cudaGetSymbolAddress((void**)&Wr,   g_Wr);

    const float* qkvwR = Wr;
    const float* projwR = Wr + 49152;
    const float* f1wR = Wr + 65536;
    const float* f2wR = Wr + 131072;

    const int Mh = TOK_HALF;
    const int Mf = TOK_TOTAL;

    // prep: rounded weights + fused bias table
    roundcopy_kernel<<<49152 / 1024, 256>>>(qkvw, Wr);
    roundcopy_kernel<<<16384 / 1024, 256>>>(projw, Wr + 49152);
    roundcopy_kernel<<<65536 / 1024, 256>>>(f1w, Wr + 65536);
    roundcopy_kernel<<<65536 / 1024, 256>>>(f2w, Wr + 131072);
    bias_combine_kernel<<<dim3(NWn, NHn), 256>>>(rbt, relIdx, amask, CB);
    ln1_part_kernel<<<TOK_TOTAL / 8, 256>>>(x, n1w, n1b, XW);

    // QKV (rounded outputs feed attention mma)
    launch_gemm(XW, Cdim, qkvwR, Cdim, qkvb, QKVf, 384, Mf, 384, 128, nullptr, 0, 0, 0, 0, 0, 1);
    launch_gemm(XW + (size_t)Mh * Cdim, Cdim, qkvwR, Cdim, qkvb, QKV1, 384, Mh, 384, 64,  nullptr, 0, 0, 0, 0, 0, 1);
    launch_gemm(XW + (size_t)Mh * Cdim, Cdim, qkvwR, Cdim, qkvb, QKV2, 384, Mh, 384, 32,  nullptr, 0, 0, 0, 0, 0, 1);

    // attention + proj
    attn_kernel<<<dim3(NWIN_TOTAL, NHn), 128>>>(QKVf, CB, O);
    launch_gemm(O, Cdim, projwR, Cdim, projb, Y, Cdim, Mf, 128, 128, gw, 0, 2, Mh, 0, 0, 0);

    attn_kernel<<<dim3(NWIN_HALF, NHn), 128>>>(QKV1, CB, Oh);
    launch_gemm(Oh, Cdim, projwR, Cdim, projb, Y + (size_t)Mh * Cdim, Cdim, Mh, 64, 128, gw, 1, 1, 0, 1, 0, 0);

    attn_kernel<<<dim3(NWIN_HALF, NHn), 128>>>(QKV2, CB, Oh);
    launch_gemm(Oh, Cdim, projwR, Cdim, projb, Y + (size_t)Mh * Cdim, Cdim, Mh, 32, 128, gw, 2, 1, 0, 1, 0, 0);

    // residual + LN2
    resid_ln2_kernel<<<TOK_TOTAL / 8, 256>>>(x, Y, n2w, n2b, out, XN);

    // MLP
    launch_gemm(XN, Cdim, f1wR, Cdim, f1b, Hb, HID, Mf, HID, 128, nullptr, 0, 0, 0, 0, 1, 1);
    launch_gemm(Hb, HID, f2wR, HID, f2b, out, Cdim, Mf, 128, 512, gw, 0, 2, Mh, 1, 0, 0);

    launch_gemm(XN + (size_t)Mh * Cdim, Cdim, f1wR, Cdim, f1b, Hb + (size_t)Mh * HID, HID, Mh, HID, 64, nullptr, 0, 0, 0, 0, 1, 1);
    launch_gemm(Hb + (size_t)Mh * HID, HID, f2wR, HID, f2b, out + (size_t)Mh * Cdim, Cdim, Mh, 64, 512, gw, 1, 1, 0, 1, 0, 0);

    launch_gemm(XN + (size_t)Mh * Cdim, Cdim, f1wR, Cdim, f1b, Hb + (size_t)Mh * HID, HID, Mh, HID, 32, nullptr, 0, 0, 0, 0, 1, 1);
    launch_gemm(Hb + (size_t)Mh * HID, HID, f2wR, HID, f2b, out + (size_t)Mh * Cdim, Cdim, Mh, 32, 512, gw, 2, 1, 0, 1, 0, 0);
}

// round 5
// speedup vs baseline: 4.5249x; 1.2899x over previous
#include <cuda_runtime.h>
#include <cuda_bf16.h>
#include <cstdint>
#include <cstddef>
#include <math.h>

// ---------------- problem constants ----------------
#define Bimg 64
#define Hdim 56
#define Wdim 56
#define WS 7
#define SHIFT 3
#define Cdim 128
#define NHn 4
#define HDd 32
#define Nn 49
#define NWn 64
#define HID 512
#define SCALE 0.17677669529663688f

#define NWIN_TOTAL (Bimg * NWn)          // 4096
#define NWIN_HALF  (NWIN_TOTAL / 2)      // 2048
#define TOK_TOTAL  (NWIN_TOTAL * Nn)     // 200704
#define TOK_HALF   (NWIN_HALF * Nn)      // 100352

typedef __nv_bfloat16 bf16;
typedef __nv_bfloat162 bf162;

// ---------------- scratch (device globals) ----------------
__device__ bf16  g_XW  [(size_t)TOK_TOTAL * Cdim];
__device__ bf16  g_QKVf[(size_t)TOK_TOTAL * 384];
__device__ bf16  g_QKV1[(size_t)TOK_HALF  * 384];
__device__ bf16  g_QKV2[(size_t)TOK_HALF  * 384];
__device__ bf16  g_O   [(size_t)TOK_TOTAL * Cdim];
__device__ bf16  g_Oh  [(size_t)TOK_HALF  * Cdim];
__device__ float g_Y   [(size_t)TOK_TOTAL * Cdim];
__device__ bf16  g_XN  [(size_t)TOK_TOTAL * Cdim];
__device__ bf16  g_H   [(size_t)TOK_TOTAL * HID];
__device__ float g_CB  [(size_t)NWn * NHn * Nn * Nn];
__device__ bf16  g_Wb  [196608];   // bf16 weights: qkvw|projw|f1w|f2w

// ---------------- weight fp32 -> bf16 ----------------
__global__ void w2bf_kernel(const float* __restrict__ src, bf16* __restrict__ dst) {
    int i = (blockIdx.x * 256 + threadIdx.x) * 4;
    float4 v = *(const float4*)(src + i);
    *(bf162*)(dst + i)     = __floats2bfloat162_rn(v.x, v.y);
    *(bf162*)(dst + i + 2) = __floats2bfloat162_rn(v.z, v.w);
}

// ---------------- fused bias+mask precompute ----------------
__global__ void bias_combine_kernel(const float* __restrict__ rbt,
                                    const int*   __restrict__ relIdx,
                                    const float* __restrict__ mask,
                                    float* __restrict__ CB) {
    int mi = blockIdx.x, h = blockIdx.y;
    float* dst = CB + ((size_t)mi * NHn + h) * (Nn * Nn);
    const float* msk = mask + (size_t)mi * (Nn * Nn);
    for (int idx = threadIdx.x; idx < Nn * Nn; idx += blockDim.x)
        dst[idx] = __ldg(&rbt[relIdx[idx] * NHn + h]) + msk[idx];
}

// ---------------- LN1 + roll(-3,-3) + window partition ----------------
__global__ __launch_bounds__(256) void ln1_part_kernel(const float* __restrict__ x,
                                const float* __restrict__ w,
                                const float* __restrict__ b,
                                bf16* __restrict__ XW) {
    int t = blockIdx.x * 8 + (threadIdx.x >> 5);
    int lane = threadIdx.x & 31;
    int win = t / Nn, n = t - win * Nn;
    int bi = win >> 6, wi = win & 63;
    int hs = ((wi >> 3) * WS + n / WS + SHIFT) % Hdim;
    int ws = ((wi & 7) * WS + n % WS + SHIFT) % Wdim;
    const float* xp = x + ((size_t)bi * (Hdim * Wdim) + hs * Wdim + ws) * Cdim;
    float4 v = *(const float4*)(xp + lane * 4);
    float s  = v.x + v.y + v.z + v.w;
    float s2 = v.x * v.x + v.y * v.y + v.z * v.z + v.w * v.w;
    #pragma unroll
    for (int o = 16; o > 0; o >>= 1) {
        s  += __shfl_xor_sync(0xffffffffu, s, o);
        s2 += __shfl_xor_sync(0xffffffffu, s2, o);
    }
    float mu  = s * (1.0f / Cdim);
    float var = s2 * (1.0f / Cdim) - mu * mu;
    float inv = rsqrtf(var + 1e-5f);
    float4 wv = *(const float4*)(w + lane * 4);
    float4 bv = *(const float4*)(b + lane * 4);
    bf16* dst = XW + (size_t)t * Cdim + lane * 4;
    *(bf162*)(dst)     = __floats2bfloat162_rn((v.x - mu) * inv * wv.x + bv.x,
                                               (v.y - mu) * inv * wv.y + bv.y);
    *(bf162*)(dst + 2) = __floats2bfloat162_rn((v.z - mu) * inv * wv.z + bv.z,
                                               (v.w - mu) * inv * wv.w + bv.w);
}

// ---------------- window reverse + roll + residual + LN2 ----------------
__global__ __launch_bounds__(256) void resid_ln2_kernel(const float* __restrict__ x,
                                 const float* __restrict__ Y,
                                 const float* __restrict__ w,
                                 const float* __restrict__ b,
                                 float* __restrict__ out,
                                 bf16* __restrict__ XN) {
    int t = blockIdx.x * 8 + (threadIdx.x >> 5);
    int lane = threadIdx.x & 31;
    int win = t / Nn, n = t - win * Nn;
    int bi = win >> 6, wi = win & 63;
    int hs = ((wi >> 3) * WS + n / WS + SHIFT) % Hdim;
    int ws = ((wi & 7) * WS + n % WS + SHIFT) % Wdim;
    size_t pos = ((size_t)bi * (Hdim * Wdim) + hs * Wdim + ws) * Cdim;
    float4 xv = *(const float4*)(x + pos + lane * 4);
    float4 yv = *(const float4*)(Y + (size_t)t * Cdim + lane * 4);
    float4 v;
    v.x = xv.x + yv.x; v.y = xv.y + yv.y; v.z = xv.z + yv.z; v.w = xv.w + yv.w;
    *(float4*)(out + pos + lane * 4) = v;
    float s  = v.x + v.y + v.z + v.w;
    float s2 = v.x * v.x + v.y * v.y + v.z * v.z + v.w * v.w;
    #pragma unroll
    for (int o = 16; o > 0; o >>= 1) {
        s  += __shfl_xor_sync(0xffffffffu, s, o);
        s2 += __shfl_xor_sync(0xffffffffu, s2, o);
    }
    float mu  = s * (1.0f / Cdim);
    float var = s2 * (1.0f / Cdim) - mu * mu;
    float inv = rsqrtf(var + 1e-5f);
    float4 wv = *(const float4*)(w + lane * 4);
    float4 bv = *(const float4*)(b + lane * 4);
    bf16* dst = XN + pos + lane * 4;
    *(bf162*)(dst)     = __floats2bfloat162_rn((v.x - mu) * inv * wv.x + bv.x,
                                               (v.y - mu) * inv * wv.y + bv.y);
    *(bf162*)(dst + 2) = __floats2bfloat162_rn((v.z - mu) * inv * wv.z + bv.z,
                                               (v.w - mu) * inv * wv.w + bv.w);
}

// ---------------- mma / ldmatrix helpers ----------------
__device__ __forceinline__ void mma_bf16(float* c, const uint32_t* a, uint32_t b0, uint32_t b1) {
    asm volatile("mma.sync.aligned.m16n8k16.row.col.f32.bf16.bf16.f32 "
        "{%0,%1,%2,%3}, {%4,%5,%6,%7}, {%8,%9}, {%0,%1,%2,%3};\n"
        : "+f"(c[0]), "+f"(c[1]), "+f"(c[2]), "+f"(c[3])
        : "r"(a[0]), "r"(a[1]), "r"(a[2]), "r"(a[3]), "r"(b0), "r"(b1));
}
__device__ __forceinline__ void ldsm_x4(uint32_t* r, const bf16* p) {
    uint32_t addr = (uint32_t)__cvta_generic_to_shared(p);
    asm volatile("ldmatrix.sync.aligned.m8n8.x4.shared.b16 {%0,%1,%2,%3}, [%4];\n"
        : "=r"(r[0]), "=r"(r[1]), "=r"(r[2]), "=r"(r[3]) : "r"(addr));
}
__device__ __forceinline__ void cpa16(uint32_t dst, const void* src, bool pred) {
    int sz = pred ? 16 : 0;
    asm volatile("cp.async.cg.shared.global [%0], [%1], 16, %2;\n"
                 :: "r"(dst), "l"(src), "r"(sz));
}

// ---------------- BF16 GEMM: C = beta*C + alpha*act(A @ B^T + bias) ----------------
// A: MxK bf16 row-major, B: NxK bf16 row-major. M%128==0, K%32==0.
#define BM 128
#define BN 128
#define BK 32
#define GST 40   // smem row stride (bf16 elems) = 80B, conflict-free + 16B aligned

__global__ __launch_bounds__(256, 2) void bgemm(
    const bf16* __restrict__ A, int lda,
    const bf16* __restrict__ B, int ldb,
    const float* __restrict__ bias,
    void* __restrict__ Cv, int ldc,
    int M, int N, int K,
    const float* __restrict__ gwPtr, int alphaIdx, int alphaMode, int splitM,
    int betaOne, int doGelu, int outBf16) {
    __shared__ bf16 As[2][BM * GST];
    __shared__ bf16 Bs[2][BN * GST];

    const int tid = threadIdx.x;
    const int bm = blockIdx.y * BM;
    const int bn = blockIdx.x * BN;
    const int wid = tid >> 5, lane = tid & 31;
    const int wm = (wid & 3) * 32;
    const int wn = (wid >> 2) * 64;
    const int g = lane >> 2, t4 = lane & 3;

    float acc[2][8][4];
    #pragma unroll
    for (int i = 0; i < 2; i++)
        #pragma unroll
        for (int j = 0; j < 8; j++)
            #pragma unroll
            for (int q = 0; q < 4; q++) acc[i][j][q] = 0.0f;

    const int lrow = tid >> 2;          // 0..63
    const int lc = (tid & 3) * 8;       // k offset (bf16)
    const bf16* Ag = A + (size_t)(bm + lrow) * lda + lc;
    const bf16* Bg = B + (size_t)(bn + lrow) * ldb + lc;
    uint32_t asA[2][2], asB[2][2];
    #pragma unroll
    for (int bf = 0; bf < 2; bf++)
        #pragma unroll
        for (int r = 0; r < 2; r++) {
            asA[bf][r] = (uint32_t)__cvta_generic_to_shared(&As[bf][(lrow + r * 64) * GST + lc]);
            asB[bf][r] = (uint32_t)__cvta_generic_to_shared(&Bs[bf][(lrow + r * 64) * GST + lc]);
        }

    #pragma unroll
    for (int r = 0; r < 2; r++) {
        cpa16(asA[0][r], Ag + (size_t)r * 64 * lda, true);
        cpa16(asB[0][r], Bg + (size_t)r * 64 * ldb, (bn + lrow + r * 64) < N);
    }
    asm volatile("cp.async.commit_group;\n");

    int buf = 0;
    for (int k0 = 0; k0 < K; k0 += BK) {
        if (k0 + BK < K) {
            #pragma unroll
            for (int r = 0; r < 2; r++) {
                cpa16(asA[buf ^ 1][r], Ag + (size_t)r * 64 * lda + k0 + BK, true);
                cpa16(asB[buf ^ 1][r], Bg + (size_t)r * 64 * ldb + k0 + BK, (bn + lrow + r * 64) < N);
            }
            asm volatile("cp.async.commit_group;\n");
            asm volatile("cp.async.wait_group 1;\n");
        } else {
            asm volatile("cp.async.wait_group 0;\n");
        }
        __syncthreads();
        #pragma unroll
        for (int ks = 0; ks < 2; ks++) {
            const int kb = ks * 16;
            uint32_t af[2][4];
            #pragma unroll
            for (int mt = 0; mt < 2; mt++)
                ldsm_x4(af[mt], &As[buf][(wm + mt * 16 + (lane & 15)) * GST + kb + ((lane >> 4) << 3)]);
            uint32_t bfm[8][2];
            #pragma unroll
            for (int nt2 = 0; nt2 < 4; nt2++) {
                uint32_t r4[4];
                ldsm_x4(r4, &Bs[buf][(wn + nt2 * 16 + (lane & 7) + ((lane >> 4) << 3)) * GST
                                      + kb + (((lane >> 3) & 1) << 3)]);
                bfm[nt2 * 2][0] = r4[0]; bfm[nt2 * 2][1] = r4[1];
                bfm[nt2 * 2 + 1][0] = r4[2]; bfm[nt2 * 2 + 1][1] = r4[3];
            }
            #pragma unroll
            for (int nt = 0; nt < 8; nt++) {
                mma_bf16(acc[0][nt], af[0], bfm[nt][0], bfm[nt][1]);
                mma_bf16(acc[1][nt], af[1], bfm[nt][0], bfm[nt][1]);
            }
        }
        __syncthreads();
        buf ^= 1;
    }

    float alpha = 1.0f;
    if (alphaMode == 1) alpha = __ldg(&gwPtr[alphaIdx]);
    else if (alphaMode == 2 && bm >= splitM) alpha = __ldg(&gwPtr[0]);

    #pragma unroll
    for (int nt = 0; nt < 8; nt++) {
        int c0 = bn + wn + nt * 8 + t4 * 2;
        if (c0 >= N) continue;
        float bv0 = bias ? bias[c0] : 0.0f;
        float bv1 = bias ? bias[c0 + 1] : 0.0f;
        #pragma unroll
        for (int mt = 0; mt < 2; mt++) {
            #pragma unroll
            for (int half = 0; half < 2; half++) {
                int r = bm + wm + mt * 16 + g + half * 8;
                float v0 = acc[mt][nt][half * 2 + 0] + bv0;
                float v1 = acc[mt][nt][half * 2 + 1] + bv1;
                if (doGelu) {
                    v0 = 0.5f * v0 * (1.0f + erff(v0 * 0.70710678118654752f));
                    v1 = 0.5f * v1 * (1.0f + erff(v1 * 0.70710678118654752f));
                }
                v0 *= alpha; v1 *= alpha;
                size_t off = (size_t)r * ldc + c0;
                if (outBf16) {
                    *(bf162*)((bf16*)Cv + off) = __floats2bfloat162_rn(v0, v1);
                } else {
                    float* Cf = (float*)Cv;
                    if (betaOne) {
                        float2 old = *(const float2*)(Cf + off);
                        v0 += old.x; v1 += old.y;
                    }
                    *(float2*)(Cf + off) = make_float2(v0, v1);
                }
            }
        }
    }
}

// ---------------- bf16 tensor-core window attention ----------------
// one block per (window, head); 4 warps; Q rows pad->64, K rows pad->64, inner pad->64
#define AQS 56   // q/k smem stride (bf16) = 112B
#define VST 72   // Vt / P stride (bf16) = 144B
#define SST 68   // score stride (fp32)
__global__ __launch_bounds__(128) void attn_kernel(
    const bf16* __restrict__ QKV,    // (nwin*49, 384)
    const float* __restrict__ CB,    // (64, 4, 49*49)
    bf16* __restrict__ O) {          // (nwin*49, 128)
    const int lw = blockIdx.x;
    const int h  = blockIdx.y;
    const int mi = lw & 63;
    __shared__ bf16 sq[64 * AQS];
    __shared__ bf16 sk[64 * AQS];
    __shared__ bf16 sVt[32 * VST];
    __shared__ bf16 sP[64 * VST];
    __shared__ float sS[64 * SST];
    const int tid = threadIdx.x;
    const int wid = tid >> 5, lane = tid & 31;
    const int g = lane >> 2, t4 = lane & 3;
    const int wr = wid * 16;

    const bf16* base = QKV + (size_t)lw * Nn * 384 + h * HDd;
    for (int idx = tid; idx < Nn * 4; idx += 128) {       // vectorized q/k
        int n = idx >> 2, dc = (idx & 3) * 8;
        const bf16* row = base + n * 384;
        *(uint4*)&sq[n * AQS + dc] = *(const uint4*)(row + dc);
        *(uint4*)&sk[n * AQS + dc] = *(const uint4*)(row + 128 + dc);
    }
    for (int idx = tid; idx < Nn * HDd; idx += 128) {     // v transposed
        int n = idx >> 5, d = idx & 31;
        sVt[d * VST + n] = base[n * 384 + 256 + d];
    }
    for (int idx = tid; idx < 15 * 32; idx += 128) {      // pad q/k rows 49..63
        int n = 49 + (idx >> 5), d = idx & 31;
        sq[n * AQS + d] = __float2bfloat16(0.0f);
        sk[n * AQS + d] = __float2bfloat16(0.0f);
    }
    for (int idx = tid; idx < 32 * 15; idx += 128) {      // pad Vt cols 49..63
        int d = idx / 15, m = 49 + idx % 15;
        sVt[d * VST + m] = __float2bfloat16(0.0f);
    }
    for (int idx = tid; idx < 15 * 64; idx += 128) {      // pad P rows 49..63
        int n = 49 + (idx >> 6), m = idx & 63;
        sP[n * VST + m] = __float2bfloat16(0.0f);
    }
    __syncthreads();

    // ---- S = (Q @ K^T) * SCALE + CB ----
    const float* cb = CB + ((size_t)mi * NHn + h) * (Nn * Nn);
    {
        float acc[8][4];
        #pragma unroll
        for (int nt = 0; nt < 8; nt++)
            #pragma unroll
            for (int q = 0; q < 4; q++) acc[nt][q] = 0.0f;
        #pragma unroll
        for (int ks = 0; ks < 2; ks++) {
            int kb = ks * 16;
            uint32_t aq[4];
            ldsm_x4(aq, &sq[(wr + (lane & 15)) * AQS + kb + ((lane >> 4) << 3)]);
            #pragma unroll
            for (int nt2 = 0; nt2 < 4; nt2++) {
                uint32_t r4[4];
                ldsm_x4(r4, &sk[(nt2 * 16 + (lane & 7) + ((lane >> 4) << 3)) * AQS
                                 + kb + (((lane >> 3) & 1) << 3)]);
                mma_bf16(acc[nt2 * 2],     aq, r4[0], r4[1]);
                mma_bf16(acc[nt2 * 2 + 1], aq, r4[2], r4[3]);
            }
        }
        #pragma unroll
        for (int nt = 0; nt < 8; nt++) {
            int col = nt * 8 + t4 * 2;
            #pragma unroll
            for (int half = 0; half < 2; half++) {
                int r = wr + g + half * 8;
                float v0 = acc[nt][half * 2 + 0] * SCALE;
                float v1 = acc[nt][half * 2 + 1] * SCALE;
                if (r < Nn) {
                    if (col < Nn)     v0 += __ldg(&cb[r * Nn + col]);
                    if (col + 1 < Nn) v1 += __ldg(&cb[r * Nn + col + 1]);
                }
                sS[r * SST + col]     = v0;
                sS[r * SST + col + 1] = v1;
            }
        }
    }
    __syncthreads();

    // ---- softmax, write P (bf16), zero pad cols ----
    if (tid < Nn) {
        const float* row = &sS[tid * SST];
        bf16* prow = &sP[tid * VST];
        float mx = -1e30f;
        #pragma unroll
        for (int m = 0; m < Nn; m++) mx = fmaxf(mx, row[m]);
        float sum = 0.0f;
        float e[Nn];
        #pragma unroll
        for (int m = 0; m < Nn; m++) { e[m] = __expf(row[m] - mx); sum += e[m]; }
        float rs = 1.0f / sum;
        #pragma unroll
        for (int m = 0; m < Nn; m++) prow[m] = __float2bfloat16(e[m] * rs);
        #pragma unroll
        for (int m = Nn; m < 64; m++) prow[m] = __float2bfloat16(0.0f);
    }
    __syncthreads();

    // ---- O = P @ V ----
    {
        float acc[4][4];
        #pragma unroll
        for (int nt = 0; nt < 4; nt++)
            #pragma unroll
            for (int q = 0; q < 4; q++) acc[nt][q] = 0.0f;
        #pragma unroll
        for (int ks = 0; ks < 4; ks++) {
            int kb = ks * 16;
            uint32_t ap[4];
            ldsm_x4(ap, &sP[(wr + (lane & 15)) * VST + kb + ((lane >> 4) << 3)]);
            #pragma unroll
            for (int nt2 = 0; nt2 < 2; nt2++) {
                uint32_t r4[4];
                ldsm_x4(r4, &sVt[(nt2 * 16 + (lane & 7) + ((lane >> 4) << 3)) * VST
                                  + kb + (((lane >> 3) & 1) << 3)]);
                mma_bf16(acc[nt2 * 2],     ap, r4[0], r4[1]);
                mma_bf16(acc[nt2 * 2 + 1], ap, r4[2], r4[3]);
            }
        }
        #pragma unroll
        for (int nt = 0; nt < 4; nt++) {
            int col = nt * 8 + t4 * 2;
            #pragma unroll
            for (int half = 0; half < 2; half++) {
                int r = wr + g + half * 8;
                if (r < Nn)
                    *(bf162*)(O + (size_t)(lw * Nn + r) * Cdim + h * HDd + col)
                        = __floats2bfloat162_rn(acc[nt][half * 2 + 0], acc[nt][half * 2 + 1]);
            }
        }
    }
}

// ---------------- host helpers ----------------
static inline void launch_gemm(const bf16* A, int lda, const bf16* B, int ldb,
                               const float* bias, void* C, int ldc,
                               int M, int N, int K,
                               const float* gwP, int ai, int aMode, int splitM,
                               int betaOne, int gelu, int outBf16) {
    dim3 grid((N + BN - 1) / BN, M / BM);
    bgemm<<<grid, 256>>>(A, lda, B, ldb, bias, C, ldc, M, N, K,
                         gwP, ai, aMode, splitM, betaOne, gelu, outBf16);
}

extern "C" void kernel_launch(void* const* d_in, const int* in_sizes, int n_in,
                              void* d_out, int out_size) {
    const float* x     = (const float*)d_in[0];
    const float* gw    = (const float*)d_in[1];
    const float* n1w   = (const float*)d_in[2];
    const float* n1b   = (const float*)d_in[3];
    const float* qkvw  = (const float*)d_in[4];
    const float* qkvb  = (const float*)d_in[5];
    const float* rbt   = (const float*)d_in[6];
    const float* projw = (const float*)d_in[7];
    const float* projb = (const float*)d_in[8];
    const float* amask = (const float*)d_in[9];
    const float* n2w   = (const float*)d_in[10];
    const float* n2b   = (const float*)d_in[11];
    const float* f1w   = (const float*)d_in[12];
    const float* f1b   = (const float*)d_in[13];
    const float* f2w   = (const float*)d_in[14];
    const float* f2b   = (const float*)d_in[15];
    const int*   relIdx= (const int*)d_in[16];
    float* out = (float*)d_out;

    bf16 *XW, *QKVf, *QKV1, *QKV2, *O, *Oh, *XN, *Hb, *Wb;
    float *Y, *CB;
    cudaGetSymbolAddress((void**)&XW,   g_XW);
    cudaGetSymbolAddress((void**)&QKVf, g_QKVf);
    cudaGetSymbolAddress((void**)&QKV1, g_QKV1);
    cudaGetSymbolAddress((void**)&QKV2, g_QKV2);
    cudaGetSymbolAddress((void**)&O,    g_O);
    cudaGetSymbolAddress((void**)&Oh,   g_Oh);
    cudaGetSymbolAddress((void**)&Y,    g_Y);
    cudaGetSymbolAddress((void**)&XN,   g_XN);
    cudaGetSymbolAddress((void**)&Hb,   g_H);
    cudaGetSymbolAddress((void**)&CB,   g_CB);
    cudaGetSymbolAddress((void**)&Wb,   g_Wb);

    const bf16* qkvwB = Wb;
    const bf16* projwB = Wb + 49152;
    const bf16* f1wB = Wb + 65536;
    const bf16* f2wB = Wb + 131072;

    const int Mh = TOK_HALF;
    const int Mf = TOK_TOTAL;

    // prep
    w2bf_kernel<<<48, 256>>>(qkvw, Wb);
    w2bf_kernel<<<16, 256>>>(projw, Wb + 49152);
    w2bf_kernel<<<64, 256>>>(f1w, Wb + 65536);
    w2bf_kernel<<<64, 256>>>(f2w, Wb + 131072);
    bias_combine_kernel<<<dim3(NWn, NHn), 256>>>(rbt, relIdx, amask, CB);
    ln1_part_kernel<<<TOK_TOTAL / 8, 256>>>(x, n1w, n1b, XW);

    // QKV
    launch_gemm(XW, Cdim, qkvwB, Cdim, qkvb, QKVf, 384, Mf, 384, 128, nullptr, 0, 0, 0, 0, 0, 1);
    launch_gemm(XW + (size_t)Mh * Cdim, Cdim, qkvwB, Cdim, qkvb, QKV1, 384, Mh, 384, 64,  nullptr, 0, 0, 0, 0, 0, 1);
    launch_gemm(XW + (size_t)Mh * Cdim, Cdim, qkvwB, Cdim, qkvb, QKV2, 384, Mh, 384, 32,  nullptr, 0, 0, 0, 0, 0, 1);

    // attention + proj
    attn_kernel<<<dim3(NWIN_TOTAL, NHn), 128>>>(QKVf, CB, O);
    launch_gemm(O, Cdim, projwB, Cdim, projb, Y, Cdim, Mf, 128, 128, gw, 0, 2, Mh, 0, 0, 0);

    attn_kernel<<<dim3(NWIN_HALF, NHn), 128>>>(QKV1, CB, Oh);
    launch_gemm(Oh, Cdim, projwB, Cdim, projb, Y + (size_t)Mh * Cdim, Cdim, Mh, 64, 128, gw, 1, 1, 0, 1, 0, 0);

    attn_kernel<<<dim3(NWIN_HALF, NHn), 128>>>(QKV2, CB, Oh);
    launch_gemm(Oh, Cdim, projwB, Cdim, projb, Y + (size_t)Mh * Cdim, Cdim, Mh, 32, 128, gw, 2, 1, 0, 1, 0, 0);

    // residual + LN2
    resid_ln2_kernel<<<TOK_TOTAL / 8, 256>>>(x, Y, n2w, n2b, out, XN);

    // MLP
    launch_gemm(XN, Cdim, f1wB, Cdim, f1b, Hb, HID, Mf, HID, 128, nullptr, 0, 0, 0, 0, 1, 1);
    launch_gemm(Hb, HID, f2wB, HID, f2b, out, Cdim, Mf, 128, 512, gw, 0, 2, Mh, 1, 0, 0);

    launch_gemm(XN + (size_t)Mh * Cdim, Cdim, f1wB, Cdim, f1b, Hb + (size_t)Mh * HID, HID, Mh, HID, 64, nullptr, 0, 0, 0, 0, 1, 1);
    launch_gemm(Hb + (size_t)Mh * HID, HID, f2wB, HID, f2b, out + (size_t)Mh * Cdim, Cdim, Mh, 64, 512, gw, 1, 1, 0, 1, 0, 0);

    launch_gemm(XN + (size_t)Mh * Cdim, Cdim, f1wB, Cdim, f1b, Hb + (size_t)Mh * HID, HID, Mh, HID, 32, nullptr, 0, 0, 0, 0, 1, 1);
    launch_gemm(Hb + (size_t)Mh * HID, HID, f2wB, HID, f2b, out + (size_t)Mh * Cdim, Cdim, Mh, 32, 512, gw, 2, 1, 0, 1, 0, 0);
}

// round 6
// speedup vs baseline: 4.9647x; 1.0972x over previous
#include <cuda_runtime.h>
#include <cuda_bf16.h>
#include <cstdint>
#include <cstddef>
#include <math.h>

// ---------------- problem constants ----------------
#define Bimg 64
#define Hdim 56
#define Wdim 56
#define WS 7
#define SHIFT 3
#define Cdim 128
#define NHn 4
#define HDd 32
#define Nn 49
#define NWn 64
#define HID 512
#define SCALE 0.17677669529663688f

#define NWIN_TOTAL (Bimg * NWn)          // 4096
#define NWIN_HALF  (NWIN_TOTAL / 2)      // 2048
#define TOK_TOTAL  (NWIN_TOTAL * Nn)     // 200704
#define TOK_HALF   (NWIN_HALF * Nn)      // 100352

typedef __nv_bfloat16 bf16;
typedef __nv_bfloat162 bf162;

// ---------------- scratch (device globals) ----------------
__device__ bf16  g_XW  [(size_t)TOK_TOTAL * Cdim];
__device__ bf16  g_QKVf[(size_t)TOK_TOTAL * 384];
__device__ bf16  g_QKV1[(size_t)TOK_HALF  * 384];
__device__ bf16  g_QKV2[(size_t)TOK_HALF  * 384];
__device__ bf16  g_O   [(size_t)TOK_TOTAL * Cdim];
__device__ bf16  g_Oh1 [(size_t)TOK_HALF  * Cdim];
__device__ bf16  g_Oh2 [(size_t)TOK_HALF  * Cdim];
__device__ float g_Y   [(size_t)TOK_TOTAL * Cdim];
__device__ bf16  g_XN  [(size_t)TOK_TOTAL * Cdim];
__device__ bf16  g_H   [(size_t)TOK_TOTAL * HID];
__device__ bf16  g_H1  [(size_t)TOK_HALF  * HID];
__device__ bf16  g_H2  [(size_t)TOK_HALF  * HID];
__device__ float g_CB  [(size_t)NWn * NHn * Nn * Nn];
__device__ bf16  g_Wb  [196608];   // bf16 weights: qkvw|projw|f1w|f2w

// ---------------- all weights fp32 -> bf16, one launch ----------------
__global__ void w2bf_all_kernel(const float* __restrict__ qkvw, const float* __restrict__ projw,
                                const float* __restrict__ f1w, const float* __restrict__ f2w,
                                bf16* __restrict__ dst) {
    int i = (blockIdx.x * 256 + threadIdx.x) * 4;   // 0 .. 196604
    const float* src;
    int off;
    if (i < 49152)       { src = qkvw;  off = i; }
    else if (i < 65536)  { src = projw; off = i - 49152; }
    else if (i < 131072) { src = f1w;   off = i - 65536; }
    else                 { src = f2w;   off = i - 131072; }
    float4 v = *(const float4*)(src + off);
    *(bf162*)(dst + i)     = __floats2bfloat162_rn(v.x, v.y);
    *(bf162*)(dst + i + 2) = __floats2bfloat162_rn(v.z, v.w);
}

// ---------------- fused bias+mask precompute ----------------
__global__ void bias_combine_kernel(const float* __restrict__ rbt,
                                    const int*   __restrict__ relIdx,
                                    const float* __restrict__ mask,
                                    float* __restrict__ CB) {
    int mi = blockIdx.x, h = blockIdx.y;
    float* dst = CB + ((size_t)mi * NHn + h) * (Nn * Nn);
    const float* msk = mask + (size_t)mi * (Nn * Nn);
    for (int idx = threadIdx.x; idx < Nn * Nn; idx += blockDim.x)
        dst[idx] = __ldg(&rbt[relIdx[idx] * NHn + h]) + msk[idx];
}

// ---------------- LN1 + roll(-3,-3) + window partition ----------------
__global__ __launch_bounds__(256) void ln1_part_kernel(const float* __restrict__ x,
                                const float* __restrict__ w,
                                const float* __restrict__ b,
                                bf16* __restrict__ XW) {
    int t = blockIdx.x * 8 + (threadIdx.x >> 5);
    int lane = threadIdx.x & 31;
    int win = t / Nn, n = t - win * Nn;
    int bi = win >> 6, wi = win & 63;
    int hs = ((wi >> 3) * WS + n / WS + SHIFT) % Hdim;
    int ws = ((wi & 7) * WS + n % WS + SHIFT) % Wdim;
    const float* xp = x + ((size_t)bi * (Hdim * Wdim) + hs * Wdim + ws) * Cdim;
    float4 v = *(const float4*)(xp + lane * 4);
    float s  = v.x + v.y + v.z + v.w;
    float s2 = v.x * v.x + v.y * v.y + v.z * v.z + v.w * v.w;
    #pragma unroll
    for (int o = 16; o > 0; o >>= 1) {
        s  += __shfl_xor_sync(0xffffffffu, s, o);
        s2 += __shfl_xor_sync(0xffffffffu, s2, o);
    }
    float mu  = s * (1.0f / Cdim);
    float var = s2 * (1.0f / Cdim) - mu * mu;
    float inv = rsqrtf(var + 1e-5f);
    float4 wv = *(const float4*)(w + lane * 4);
    float4 bv = *(const float4*)(b + lane * 4);
    bf16* dst = XW + (size_t)t * Cdim + lane * 4;
    *(bf162*)(dst)     = __floats2bfloat162_rn((v.x - mu) * inv * wv.x + bv.x,
                                               (v.y - mu) * inv * wv.y + bv.y);
    *(bf162*)(dst + 2) = __floats2bfloat162_rn((v.z - mu) * inv * wv.z + bv.z,
                                               (v.w - mu) * inv * wv.w + bv.w);
}

// ---------------- window reverse + roll + residual + LN2 ----------------
__global__ __launch_bounds__(256) void resid_ln2_kernel(const float* __restrict__ x,
                                 const float* __restrict__ Y,
                                 const float* __restrict__ w,
                                 const float* __restrict__ b,
                                 float* __restrict__ out,
                                 bf16* __restrict__ XN) {
    int t = blockIdx.x * 8 + (threadIdx.x >> 5);
    int lane = threadIdx.x & 31;
    int win = t / Nn, n = t - win * Nn;
    int bi = win >> 6, wi = win & 63;
    int hs = ((wi >> 3) * WS + n / WS + SHIFT) % Hdim;
    int ws = ((wi & 7) * WS + n % WS + SHIFT) % Wdim;
    size_t pos = ((size_t)bi * (Hdim * Wdim) + hs * Wdim + ws) * Cdim;
    float4 xv = *(const float4*)(x + pos + lane * 4);
    float4 yv = *(const float4*)(Y + (size_t)t * Cdim + lane * 4);
    float4 v;
    v.x = xv.x + yv.x; v.y = xv.y + yv.y; v.z = xv.z + yv.z; v.w = xv.w + yv.w;
    *(float4*)(out + pos + lane * 4) = v;
    float s  = v.x + v.y + v.z + v.w;
    float s2 = v.x * v.x + v.y * v.y + v.z * v.z + v.w * v.w;
    #pragma unroll
    for (int o = 16; o > 0; o >>= 1) {
        s  += __shfl_xor_sync(0xffffffffu, s, o);
        s2 += __shfl_xor_sync(0xffffffffu, s2, o);
    }
    float mu  = s * (1.0f / Cdim);
    float var = s2 * (1.0f / Cdim) - mu * mu;
    float inv = rsqrtf(var + 1e-5f);
    float4 wv = *(const float4*)(w + lane * 4);
    float4 bv = *(const float4*)(b + lane * 4);
    bf16* dst = XN + pos + lane * 4;
    *(bf162*)(dst)     = __floats2bfloat162_rn((v.x - mu) * inv * wv.x + bv.x,
                                               (v.y - mu) * inv * wv.y + bv.y);
    *(bf162*)(dst + 2) = __floats2bfloat162_rn((v.z - mu) * inv * wv.z + bv.z,
                                               (v.w - mu) * inv * wv.w + bv.w);
}

// ---------------- mma / ldmatrix helpers ----------------
__device__ __forceinline__ void mma_bf16(float* c, const uint32_t* a, uint32_t b0, uint32_t b1) {
    asm volatile("mma.sync.aligned.m16n8k16.row.col.f32.bf16.bf16.f32 "
        "{%0,%1,%2,%3}, {%4,%5,%6,%7}, {%8,%9}, {%0,%1,%2,%3};\n"
        : "+f"(c[0]), "+f"(c[1]), "+f"(c[2]), "+f"(c[3])
        : "r"(a[0]), "r"(a[1]), "r"(a[2]), "r"(a[3]), "r"(b0), "r"(b1));
}
__device__ __forceinline__ void ldsm_x4(uint32_t* r, const bf16* p) {
    uint32_t addr = (uint32_t)__cvta_generic_to_shared(p);
    asm volatile("ldmatrix.sync.aligned.m8n8.x4.shared.b16 {%0,%1,%2,%3}, [%4];\n"
        : "=r"(r[0]), "=r"(r[1]), "=r"(r[2]), "=r"(r[3]) : "r"(addr));
}
__device__ __forceinline__ void cpa16(uint32_t dst, const void* src, bool pred) {
    int sz = pred ? 16 : 0;
    asm volatile("cp.async.cg.shared.global [%0], [%1], 16, %2;\n"
                 :: "r"(dst), "l"(src), "r"(sz));
}

// ---------------- BF16 GEMM, 3-stage cp.async, prefix-snapshot outputs ----------------
// A: MxK bf16 row-major, B: NxK bf16 row-major. M%128==0, K%32==0, K>=128.
// prefix2/prefix1: optional bf16 outputs of the K<=32 / K<=64 partial GEMM
// (same bias/gelu epilogue), written only for blocks with bm >= splitM at
// prefix row (r - splitM). Used to fuse the gumbel sub-network variants.
#define BM 128
#define BN 128
#define BK 32
#define GST 40                      // smem row stride in bf16 (80B)
#define STG_E (BM * GST)            // elems per stage per operand
#define GEMM_SMEM (3 * 2 * STG_E * 2)  // bytes

__global__ __launch_bounds__(256, 2) void bgemm(
    const bf16* __restrict__ A, int lda,
    const bf16* __restrict__ B, int ldb,
    const float* __restrict__ bias,
    void* __restrict__ Cv, int ldc,
    int M, int N, int K,
    const float* __restrict__ gwPtr, int alphaIdx, int alphaMode, int splitM,
    int betaOne, int doGelu, int outBf16,
    bf16* __restrict__ pfx2, bf16* __restrict__ pfx1, int pfxLd) {
    extern __shared__ bf16 smem[];
    bf16* As = smem;
    bf16* Bs = smem + 3 * STG_E;

    const int tid = threadIdx.x;
    const int bm = blockIdx.y * BM;
    const int bn = blockIdx.x * BN;
    const int wid = tid >> 5, lane = tid & 31;
    const int wm = (wid & 3) * 32;
    const int wn = (wid >> 2) * 64;
    const int g = lane >> 2, t4 = lane & 3;
    const bool doPfx = (pfx2 != nullptr) && (bm >= splitM);

    float acc[2][8][4];
    #pragma unroll
    for (int i = 0; i < 2; i++)
        #pragma unroll
        for (int j = 0; j < 8; j++)
            #pragma unroll
            for (int q = 0; q < 4; q++) acc[i][j][q] = 0.0f;

    const int lrow = tid >> 2;          // 0..63
    const int lc = (tid & 3) * 8;       // k offset (bf16)
    const bf16* Ag = A + (size_t)(bm + lrow) * lda + lc;
    const bf16* Bg = B + (size_t)(bn + lrow) * ldb + lc;
    const bool bval0 = (bn + lrow) < N;
    const bool bval1 = (bn + lrow + 64) < N;

    const int KI = K / BK;

    // prologue: stages 0,1 (k-iters 0,1)
    #pragma unroll
    for (int st = 0; st < 2; st++) {
        uint32_t a0 = (uint32_t)__cvta_generic_to_shared(&As[st * STG_E + lrow * GST + lc]);
        uint32_t b0 = (uint32_t)__cvta_generic_to_shared(&Bs[st * STG_E + lrow * GST + lc]);
        cpa16(a0, Ag + (size_t)0 * lda + st * BK, true);
        cpa16(a0 + 64 * GST * 2, Ag + (size_t)64 * lda + st * BK, true);
        cpa16(b0, Bg + (size_t)0 * ldb + st * BK, bval0);
        cpa16(b0 + 64 * GST * 2, Bg + (size_t)64 * ldb + st * BK, bval1);
        asm volatile("cp.async.commit_group;\n");
    }

    int stage = 0;
    #pragma unroll 1
    for (int i = 0; i < KI; i++) {
        if (i + 1 < KI) { asm volatile("cp.async.wait_group 1;\n"); }
        else            { asm volatile("cp.async.wait_group 0;\n"); }
        __syncthreads();
        // issue k-iter i+2 into the stage consumed at iter i-1 (safe post-sync)
        if (i + 2 < KI) {
            int st = (stage + 2) % 3;
            uint32_t a0 = (uint32_t)__cvta_generic_to_shared(&As[st * STG_E + lrow * GST + lc]);
            uint32_t b0 = (uint32_t)__cvta_generic_to_shared(&Bs[st * STG_E + lrow * GST + lc]);
            int ko = (i + 2) * BK;
            cpa16(a0, Ag + (size_t)0 * lda + ko, true);
            cpa16(a0 + 64 * GST * 2, Ag + (size_t)64 * lda + ko, true);
            cpa16(b0, Bg + (size_t)0 * ldb + ko, bval0);
            cpa16(b0 + 64 * GST * 2, Bg + (size_t)64 * ldb + ko, bval1);
            asm volatile("cp.async.commit_group;\n");
        }
        const bf16* Ab = &As[stage * STG_E];
        const bf16* Bb = &Bs[stage * STG_E];
        #pragma unroll
        for (int ks = 0; ks < 2; ks++) {
            const int kb = ks * 16;
            uint32_t af[2][4];
            #pragma unroll
            for (int mt = 0; mt < 2; mt++)
                ldsm_x4(af[mt], &Ab[(wm + mt * 16 + (lane & 15)) * GST + kb + ((lane >> 4) << 3)]);
            uint32_t bfm[8][2];
            #pragma unroll
            for (int nt2 = 0; nt2 < 4; nt2++) {
                uint32_t r4[4];
                ldsm_x4(r4, &Bb[(wn + nt2 * 16 + (lane & 7) + ((lane >> 4) << 3)) * GST
                                 + kb + (((lane >> 3) & 1) << 3)]);
                bfm[nt2 * 2][0] = r4[0]; bfm[nt2 * 2][1] = r4[1];
                bfm[nt2 * 2 + 1][0] = r4[2]; bfm[nt2 * 2 + 1][1] = r4[3];
            }
            #pragma unroll
            for (int nt = 0; nt < 8; nt++) {
                mma_bf16(acc[0][nt], af[0], bfm[nt][0], bfm[nt][1]);
                mma_bf16(acc[1][nt], af[1], bfm[nt][0], bfm[nt][1]);
            }
        }
        // prefix snapshots: acc now holds sum over k < (i+1)*32
        if (doPfx && i <= 1) {
            bf16* P = (i == 0) ? pfx2 : pfx1;
            #pragma unroll
            for (int nt = 0; nt < 8; nt++) {
                int c0 = bn + wn + nt * 8 + t4 * 2;
                if (c0 >= N) continue;
                float bv0 = bias ? bias[c0] : 0.0f;
                float bv1 = bias ? bias[c0 + 1] : 0.0f;
                #pragma unroll
                for (int mt = 0; mt < 2; mt++)
                    #pragma unroll
                    for (int half = 0; half < 2; half++) {
                        int r = bm + wm + mt * 16 + g + half * 8;
                        float v0 = acc[mt][nt][half * 2 + 0] + bv0;
                        float v1 = acc[mt][nt][half * 2 + 1] + bv1;
                        if (doGelu) {
                            v0 = 0.5f * v0 * (1.0f + erff(v0 * 0.70710678118654752f));
                            v1 = 0.5f * v1 * (1.0f + erff(v1 * 0.70710678118654752f));
                        }
                        *(bf162*)(P + (size_t)(r - splitM) * pfxLd + c0)
                            = __floats2bfloat162_rn(v0, v1);
                    }
            }
        }
        __syncthreads();
        stage = (stage + 1) % 3;
    }

    float alpha = 1.0f;
    if (alphaMode == 1) alpha = __ldg(&gwPtr[alphaIdx]);
    else if (alphaMode == 2 && bm >= splitM) alpha = __ldg(&gwPtr[0]);

    #pragma unroll
    for (int nt = 0; nt < 8; nt++) {
        int c0 = bn + wn + nt * 8 + t4 * 2;
        if (c0 >= N) continue;
        float bv0 = bias ? bias[c0] : 0.0f;
        float bv1 = bias ? bias[c0 + 1] : 0.0f;
        #pragma unroll
        for (int mt = 0; mt < 2; mt++) {
            #pragma unroll
            for (int half = 0; half < 2; half++) {
                int r = bm + wm + mt * 16 + g + half * 8;
                float v0 = acc[mt][nt][half * 2 + 0] + bv0;
                float v1 = acc[mt][nt][half * 2 + 1] + bv1;
                if (doGelu) {
                    v0 = 0.5f * v0 * (1.0f + erff(v0 * 0.70710678118654752f));
                    v1 = 0.5f * v1 * (1.0f + erff(v1 * 0.70710678118654752f));
                }
                v0 *= alpha; v1 *= alpha;
                size_t off = (size_t)r * ldc + c0;
                if (outBf16) {
                    *(bf162*)((bf16*)Cv + off) = __floats2bfloat162_rn(v0, v1);
                } else {
                    float* Cf = (float*)Cv;
                    if (betaOne) {
                        float2 old = *(const float2*)(Cf + off);
                        v0 += old.x; v1 += old.y;
                    }
                    *(float2*)(Cf + off) = make_float2(v0, v1);
                }
            }
        }
    }
}

// ---------------- bf16 tensor-core window attention ----------------
#define AQS 56
#define VST 72
#define SST 68
__global__ __launch_bounds__(128) void attn_kernel(
    const bf16* __restrict__ QKVa,
    const bf16* __restrict__ QKVb,   // variant b (z==1), may equal QKVa
    const float* __restrict__ CB,
    bf16* __restrict__ Oa,
    bf16* __restrict__ Ob) {
    const int lw = blockIdx.x;
    const int h  = blockIdx.y;
    const int mi = lw & 63;
    const bf16* QKV = (blockIdx.z == 0) ? QKVa : QKVb;
    bf16* O = (blockIdx.z == 0) ? Oa : Ob;
    __shared__ bf16 sq[64 * AQS];
    __shared__ bf16 sk[64 * AQS];
    __shared__ bf16 sVt[32 * VST];
    __shared__ bf16 sP[64 * VST];
    __shared__ float sS[64 * SST];
    const int tid = threadIdx.x;
    const int wid = tid >> 5, lane = tid & 31;
    const int g = lane >> 2, t4 = lane & 3;
    const int wr = wid * 16;

    const bf16* base = QKV + (size_t)lw * Nn * 384 + h * HDd;
    for (int idx = tid; idx < Nn * 4; idx += 128) {
        int n = idx >> 2, dc = (idx & 3) * 8;
        const bf16* row = base + n * 384;
        *(uint4*)&sq[n * AQS + dc] = *(const uint4*)(row + dc);
        *(uint4*)&sk[n * AQS + dc] = *(const uint4*)(row + 128 + dc);
    }
    for (int idx = tid; idx < Nn * HDd; idx += 128) {
        int n = idx >> 5, d = idx & 31;
        sVt[d * VST + n] = base[n * 384 + 256 + d];
    }
    for (int idx = tid; idx < 15 * 32; idx += 128) {
        int n = 49 + (idx >> 5), d = idx & 31;
        sq[n * AQS + d] = __float2bfloat16(0.0f);
        sk[n * AQS + d] = __float2bfloat16(0.0f);
    }
    for (int idx = tid; idx < 32 * 15; idx += 128) {
        int d = idx / 15, m = 49 + idx % 15;
        sVt[d * VST + m] = __float2bfloat16(0.0f);
    }
    for (int idx = tid; idx < 15 * 64; idx += 128) {
        int n = 49 + (idx >> 6), m = idx & 63;
        sP[n * VST + m] = __float2bfloat16(0.0f);
    }
    __syncthreads();

    const float* cb = CB + ((size_t)mi * NHn + h) * (Nn * Nn);
    {
        float acc[8][4];
        #pragma unroll
        for (int nt = 0; nt < 8; nt++)
            #pragma unroll
            for (int q = 0; q < 4; q++) acc[nt][q] = 0.0f;
        #pragma unroll
        for (int ks = 0; ks < 2; ks++) {
            int kb = ks * 16;
            uint32_t aq[4];
            ldsm_x4(aq, &sq[(wr + (lane & 15)) * AQS + kb + ((lane >> 4) << 3)]);
            #pragma unroll
            for (int nt2 = 0; nt2 < 4; nt2++) {
                uint32_t r4[4];
                ldsm_x4(r4, &sk[(nt2 * 16 + (lane & 7) + ((lane >> 4) << 3)) * AQS
                                 + kb + (((lane >> 3) & 1) << 3)]);
                mma_bf16(acc[nt2 * 2],     aq, r4[0], r4[1]);
                mma_bf16(acc[nt2 * 2 + 1], aq, r4[2], r4[3]);
            }
        }
        #pragma unroll
        for (int nt = 0; nt < 8; nt++) {
            int col = nt * 8 + t4 * 2;
            #pragma unroll
            for (int half = 0; half < 2; half++) {
                int r = wr + g + half * 8;
                float v0 = acc[nt][half * 2 + 0] * SCALE;
                float v1 = acc[nt][half * 2 + 1] * SCALE;
                if (r < Nn) {
                    if (col < Nn)     v0 += __ldg(&cb[r * Nn + col]);
                    if (col + 1 < Nn) v1 += __ldg(&cb[r * Nn + col + 1]);
                }
                sS[r * SST + col]     = v0;
                sS[r * SST + col + 1] = v1;
            }
        }
    }
    __syncthreads();

    if (tid < Nn) {
        const float* row = &sS[tid * SST];
        bf16* prow = &sP[tid * VST];
        float mx = -1e30f;
        #pragma unroll
        for (int m = 0; m < Nn; m++) mx = fmaxf(mx, row[m]);
        float sum = 0.0f;
        float e[Nn];
        #pragma unroll
        for (int m = 0; m < Nn; m++) { e[m] = __expf(row[m] - mx); sum += e[m]; }
        float rs = 1.0f / sum;
        #pragma unroll
        for (int m = 0; m < Nn; m++) prow[m] = __float2bfloat16(e[m] * rs);
        #pragma unroll
        for (int m = Nn; m < 64; m++) prow[m] = __float2bfloat16(0.0f);
    }
    __syncthreads();

    {
        float acc[4][4];
        #pragma unroll
        for (int nt = 0; nt < 4; nt++)
            #pragma unroll
            for (int q = 0; q < 4; q++) acc[nt][q] = 0.0f;
        #pragma unroll
        for (int ks = 0; ks < 4; ks++) {
            int kb = ks * 16;
            uint32_t ap[4];
            ldsm_x4(ap, &sP[(wr + (lane & 15)) * VST + kb + ((lane >> 4) << 3)]);
            #pragma unroll
            for (int nt2 = 0; nt2 < 2; nt2++) {
                uint32_t r4[4];
                ldsm_x4(r4, &sVt[(nt2 * 16 + (lane & 7) + ((lane >> 4) << 3)) * VST
                                  + kb + (((lane >> 3) & 1) << 3)]);
                mma_bf16(acc[nt2 * 2],     ap, r4[0], r4[1]);
                mma_bf16(acc[nt2 * 2 + 1], ap, r4[2], r4[3]);
            }
        }
        #pragma unroll
        for (int nt = 0; nt < 4; nt++) {
            int col = nt * 8 + t4 * 2;
            #pragma unroll
            for (int half = 0; half < 2; half++) {
                int r = wr + g + half * 8;
                if (r < Nn)
                    *(bf162*)(O + (size_t)(lw * Nn + r) * Cdim + h * HDd + col)
                        = __floats2bfloat162_rn(acc[nt][half * 2 + 0], acc[nt][half * 2 + 1]);
            }
        }
    }
}

// ---------------- host helpers ----------------
static inline void launch_gemm(const bf16* A, int lda, const bf16* B, int ldb,
                               const float* bias, void* C, int ldc,
                               int M, int N, int K,
                               const float* gwP, int ai, int aMode, int splitM,
                               int betaOne, int gelu, int outBf16,
                               bf16* pfx2 = nullptr, bf16* pfx1 = nullptr, int pfxLd = 0) {
    dim3 grid((N + BN - 1) / BN, M / BM);
    bgemm<<<grid, 256, GEMM_SMEM>>>(A, lda, B, ldb, bias, C, ldc, M, N, K,
                                    gwP, ai, aMode, splitM, betaOne, gelu, outBf16,
                                    pfx2, pfx1, pfxLd);
}

extern "C" void kernel_launch(void* const* d_in, const int* in_sizes, int n_in,
                              void* d_out, int out_size) {
    const float* x     = (const float*)d_in[0];
    const float* gw    = (const float*)d_in[1];
    const float* n1w   = (const float*)d_in[2];
    const float* n1b   = (const float*)d_in[3];
    const float* qkvw  = (const float*)d_in[4];
    const float* qkvb  = (const float*)d_in[5];
    const float* rbt   = (const float*)d_in[6];
    const float* projw = (const float*)d_in[7];
    const float* projb = (const float*)d_in[8];
    const float* amask = (const float*)d_in[9];
    const float* n2w   = (const float*)d_in[10];
    const float* n2b   = (const float*)d_in[11];
    const float* f1w   = (const float*)d_in[12];
    const float* f1b   = (const float*)d_in[13];
    const float* f2w   = (const float*)d_in[14];
    const float* f2b   = (const float*)d_in[15];
    const int*   relIdx= (const int*)d_in[16];
    float* out = (float*)d_out;

    cudaFuncSetAttribute(bgemm, cudaFuncAttributeMaxDynamicSharedMemorySize, GEMM_SMEM);

    bf16 *XW, *QKVf, *QKV1, *QKV2, *O, *Oh1, *Oh2, *XN, *Hb, *H1, *H2, *Wb;
    float *Y, *CB;
    cudaGetSymbolAddress((void**)&XW,   g_XW);
    cudaGetSymbolAddress((void**)&QKVf, g_QKVf);
    cudaGetSymbolAddress((void**)&QKV1, g_QKV1);
    cudaGetSymbolAddress((void**)&QKV2, g_QKV2);
    cudaGetSymbolAddress((void**)&O,    g_O);
    cudaGetSymbolAddress((void**)&Oh1,  g_Oh1);
    cudaGetSymbolAddress((void**)&Oh2,  g_Oh2);
    cudaGetSymbolAddress((void**)&Y,    g_Y);
    cudaGetSymbolAddress((void**)&XN,   g_XN);
    cudaGetSymbolAddress((void**)&Hb,   g_H);
    cudaGetSymbolAddress((void**)&H1,   g_H1);
    cudaGetSymbolAddress((void**)&H2,   g_H2);
    cudaGetSymbolAddress((void**)&CB,   g_CB);
    cudaGetSymbolAddress((void**)&Wb,   g_Wb);

    const bf16* qkvwB = Wb;
    const bf16* projwB = Wb + 49152;
    const bf16* f1wB = Wb + 65536;
    const bf16* f2wB = Wb + 131072;

    const int Mh = TOK_HALF;
    const int Mf = TOK_TOTAL;

    // prep
    w2bf_all_kernel<<<192, 256>>>(qkvw, projw, f1w, f2w, Wb);
    bias_combine_kernel<<<dim3(NWn, NHn), 256>>>(rbt, relIdx, amask, CB);
    ln1_part_kernel<<<TOK_TOTAL / 8, 256>>>(x, n1w, n1b, XW);

    // QKV: one merged launch emits full (K=128) + prefix K=64 -> QKV1, K=32 -> QKV2
    launch_gemm(XW, Cdim, qkvwB, Cdim, qkvb, QKVf, 384, Mf, 384, 128,
                nullptr, 0, 0, Mh, 0, 0, 1, QKV2, QKV1, 384);

    // attention + proj
    attn_kernel<<<dim3(NWIN_TOTAL, NHn, 1), 128>>>(QKVf, QKVf, CB, O, O);
    launch_gemm(O, Cdim, projwB, Cdim, projb, Y, Cdim, Mf, 128, 128, gw, 0, 2, Mh, 0, 0, 0);

    attn_kernel<<<dim3(NWIN_HALF, NHn, 2), 128>>>(QKV1, QKV2, CB, Oh1, Oh2);
    launch_gemm(Oh1, Cdim, projwB, Cdim, projb, Y + (size_t)Mh * Cdim, Cdim, Mh, 64, 128, gw, 1, 1, 0, 1, 0, 0);
    launch_gemm(Oh2, Cdim, projwB, Cdim, projb, Y + (size_t)Mh * Cdim, Cdim, Mh, 32, 128, gw, 2, 1, 0, 1, 0, 0);

    // residual + LN2
    resid_ln2_kernel<<<TOK_TOTAL / 8, 256>>>(x, Y, n2w, n2b, out, XN);

    // FC1: merged launch emits H (K=128) + H1 (K=64) + H2 (K=32), GELU on all
    launch_gemm(XN, Cdim, f1wB, Cdim, f1b, Hb, HID, Mf, HID, 128,
                nullptr, 0, 0, Mh, 0, 1, 1, H2, H1, HID);

    // FC2
    launch_gemm(Hb, HID, f2wB, HID, f2b, out, Cdim, Mf, 128, 512, gw, 0, 2, Mh, 1, 0, 0);
    launch_gemm(H1, HID, f2wB, HID, f2b, out + (size_t)Mh * Cdim, Cdim, Mh, 64, 512, gw, 1, 1, 0, 1, 0, 0);
    launch_gemm(H2, HID, f2wB, HID, f2b, out + (size_t)Mh * Cdim, Cdim, Mh, 32, 512, gw, 2, 1, 0, 1, 0, 0);
}

// round 7
// speedup vs baseline: 5.0220x; 1.0115x over previous
#include <cuda_runtime.h>
#include <cuda_bf16.h>
#include <cstdint>
#include <cstddef>
#include <math.h>

// ---------------- problem constants ----------------
#define Bimg 64
#define Hdim 56
#define Wdim 56
#define WS 7
#define SHIFT 3
#define Cdim 128
#define NHn 4
#define HDd 32
#define Nn 49
#define NWn 64
#define HID 512
#define SCALE 0.17677669529663688f

#define NWIN_TOTAL (Bimg * NWn)          // 4096
#define NWIN_HALF  (NWIN_TOTAL / 2)      // 2048
#define TOK_TOTAL  (NWIN_TOTAL * Nn)     // 200704
#define TOK_HALF   (NWIN_HALF * Nn)      // 100352

typedef __nv_bfloat16 bf16;
typedef __nv_bfloat162 bf162;

// ---------------- scratch (device globals) ----------------
__device__ bf16  g_XW  [(size_t)TOK_TOTAL * Cdim];
__device__ bf16  g_QKVf[(size_t)TOK_TOTAL * 384];
__device__ bf16  g_QKV1[(size_t)TOK_HALF  * 384];
__device__ bf16  g_QKV2[(size_t)TOK_HALF  * 384];
__device__ bf16  g_O   [(size_t)TOK_TOTAL * Cdim];
__device__ bf16  g_Oh1 [(size_t)TOK_HALF  * Cdim];
__device__ bf16  g_Oh2 [(size_t)TOK_HALF  * Cdim];
__device__ float g_Y   [(size_t)TOK_TOTAL * Cdim];
__device__ bf16  g_XN  [(size_t)TOK_TOTAL * Cdim];
__device__ bf16  g_H   [(size_t)TOK_TOTAL * HID];
__device__ bf16  g_H1  [(size_t)TOK_HALF  * HID];
__device__ bf16  g_H2  [(size_t)TOK_HALF  * HID];
__device__ float g_CB  [(size_t)NWn * NHn * Nn * Nn];
__device__ bf16  g_Wb  [196608];   // bf16 weights: qkvw|projw|f1w|f2w

// ---------------- fused prep: weights->bf16, bias+mask, LN1+roll+partition ----------------
// blocks [0,192): weight cast; [192,448): bias combine; [448, 448+25088): LN1
#define PREP_W 192
#define PREP_B 256
#define PREP_LN (TOK_TOTAL / 8)
__global__ __launch_bounds__(256) void prep_kernel(
    const float* __restrict__ qkvw, const float* __restrict__ projw,
    const float* __restrict__ f1w, const float* __restrict__ f2w,
    bf16* __restrict__ Wb,
    const float* __restrict__ rbt, const int* __restrict__ relIdx,
    const float* __restrict__ mask, float* __restrict__ CB,
    const float* __restrict__ x, const float* __restrict__ n1w,
    const float* __restrict__ n1b, bf16* __restrict__ XW) {
    int bid = blockIdx.x;
    if (bid < PREP_W) {
        int i = (bid * 256 + threadIdx.x) * 4;
        const float* src; int off;
        if (i < 49152)       { src = qkvw;  off = i; }
        else if (i < 65536)  { src = projw; off = i - 49152; }
        else if (i < 131072) { src = f1w;   off = i - 65536; }
        else                 { src = f2w;   off = i - 131072; }
        float4 v = *(const float4*)(src + off);
        *(bf162*)(Wb + i)     = __floats2bfloat162_rn(v.x, v.y);
        *(bf162*)(Wb + i + 2) = __floats2bfloat162_rn(v.z, v.w);
        return;
    }
    if (bid < PREP_W + PREP_B) {
        int b = bid - PREP_W;
        int mi = b >> 2, h = b & 3;
        float* dst = CB + ((size_t)mi * NHn + h) * (Nn * Nn);
        const float* msk = mask + (size_t)mi * (Nn * Nn);
        for (int idx = threadIdx.x; idx < Nn * Nn; idx += 256)
            dst[idx] = __ldg(&rbt[relIdx[idx] * NHn + h]) + msk[idx];
        return;
    }
    int t = (bid - PREP_W - PREP_B) * 8 + (threadIdx.x >> 5);
    int lane = threadIdx.x & 31;
    int win = t / Nn, n = t - win * Nn;
    int bi = win >> 6, wi = win & 63;
    int hs = ((wi >> 3) * WS + n / WS + SHIFT) % Hdim;
    int ws = ((wi & 7) * WS + n % WS + SHIFT) % Wdim;
    const float* xp = x + ((size_t)bi * (Hdim * Wdim) + hs * Wdim + ws) * Cdim;
    float4 v = *(const float4*)(xp + lane * 4);
    float s  = v.x + v.y + v.z + v.w;
    float s2 = v.x * v.x + v.y * v.y + v.z * v.z + v.w * v.w;
    #pragma unroll
    for (int o = 16; o > 0; o >>= 1) {
        s  += __shfl_xor_sync(0xffffffffu, s, o);
        s2 += __shfl_xor_sync(0xffffffffu, s2, o);
    }
    float mu  = s * (1.0f / Cdim);
    float var = s2 * (1.0f / Cdim) - mu * mu;
    float inv = rsqrtf(var + 1e-5f);
    float4 wv = *(const float4*)(n1w + lane * 4);
    float4 bv = *(const float4*)(n1b + lane * 4);
    bf16* dst = XW + (size_t)t * Cdim + lane * 4;
    *(bf162*)(dst)     = __floats2bfloat162_rn((v.x - mu) * inv * wv.x + bv.x,
                                               (v.y - mu) * inv * wv.y + bv.y);
    *(bf162*)(dst + 2) = __floats2bfloat162_rn((v.z - mu) * inv * wv.z + bv.z,
                                               (v.w - mu) * inv * wv.w + bv.w);
}

// ---------------- window reverse + roll + residual + LN2 ----------------
__global__ __launch_bounds__(256) void resid_ln2_kernel(const float* __restrict__ x,
                                 const float* __restrict__ Y,
                                 const float* __restrict__ w,
                                 const float* __restrict__ b,
                                 float* __restrict__ out,
                                 bf16* __restrict__ XN) {
    int t = blockIdx.x * 8 + (threadIdx.x >> 5);
    int lane = threadIdx.x & 31;
    int win = t / Nn, n = t - win * Nn;
    int bi = win >> 6, wi = win & 63;
    int hs = ((wi >> 3) * WS + n / WS + SHIFT) % Hdim;
    int ws = ((wi & 7) * WS + n % WS + SHIFT) % Wdim;
    size_t pos = ((size_t)bi * (Hdim * Wdim) + hs * Wdim + ws) * Cdim;
    float4 xv = *(const float4*)(x + pos + lane * 4);
    float4 yv = *(const float4*)(Y + (size_t)t * Cdim + lane * 4);
    float4 v;
    v.x = xv.x + yv.x; v.y = xv.y + yv.y; v.z = xv.z + yv.z; v.w = xv.w + yv.w;
    *(float4*)(out + pos + lane * 4) = v;
    float s  = v.x + v.y + v.z + v.w;
    float s2 = v.x * v.x + v.y * v.y + v.z * v.z + v.w * v.w;
    #pragma unroll
    for (int o = 16; o > 0; o >>= 1) {
        s  += __shfl_xor_sync(0xffffffffu, s, o);
        s2 += __shfl_xor_sync(0xffffffffu, s2, o);
    }
    float mu  = s * (1.0f / Cdim);
    float var = s2 * (1.0f / Cdim) - mu * mu;
    float inv = rsqrtf(var + 1e-5f);
    float4 wv = *(const float4*)(w + lane * 4);
    float4 bv = *(const float4*)(b + lane * 4);
    bf16* dst = XN + pos + lane * 4;
    *(bf162*)(dst)     = __floats2bfloat162_rn((v.x - mu) * inv * wv.x + bv.x,
                                               (v.y - mu) * inv * wv.y + bv.y);
    *(bf162*)(dst + 2) = __floats2bfloat162_rn((v.z - mu) * inv * wv.z + bv.z,
                                               (v.w - mu) * inv * wv.w + bv.w);
}

// ---------------- mma / ldmatrix helpers ----------------
__device__ __forceinline__ void mma_bf16(float* c, const uint32_t* a, uint32_t b0, uint32_t b1) {
    asm volatile("mma.sync.aligned.m16n8k16.row.col.f32.bf16.bf16.f32 "
        "{%0,%1,%2,%3}, {%4,%5,%6,%7}, {%8,%9}, {%0,%1,%2,%3};\n"
        : "+f"(c[0]), "+f"(c[1]), "+f"(c[2]), "+f"(c[3])
        : "r"(a[0]), "r"(a[1]), "r"(a[2]), "r"(a[3]), "r"(b0), "r"(b1));
}
__device__ __forceinline__ void ldsm_x4(uint32_t* r, const bf16* p) {
    uint32_t addr = (uint32_t)__cvta_generic_to_shared(p);
    asm volatile("ldmatrix.sync.aligned.m8n8.x4.shared.b16 {%0,%1,%2,%3}, [%4];\n"
        : "=r"(r[0]), "=r"(r[1]), "=r"(r[2]), "=r"(r[3]) : "r"(addr));
}
__device__ __forceinline__ void cpa16(uint32_t dst, const void* src, bool pred) {
    int sz = pred ? 16 : 0;
    asm volatile("cp.async.cg.shared.global [%0], [%1], 16, %2;\n"
                 :: "r"(dst), "l"(src), "r"(sz));
}

// ---------------- BF16 GEMM, 4-stage cp.async, single sync/iter ----------------
// A: MxK bf16 row-major, B: NxK bf16 row-major. M%128==0, K%32==0, K>=128.
#define BM 128
#define BN 128
#define BK 32
#define GST 40
#define STG_E (BM * GST)
#define NSTG 4
#define GEMM_SMEM (NSTG * 2 * STG_E * 2)

__global__ __launch_bounds__(256, 2) void bgemm(
    const bf16* __restrict__ A, int lda,
    const bf16* __restrict__ B, int ldb,
    const float* __restrict__ bias,
    void* __restrict__ Cv, int ldc,
    int M, int N, int K,
    const float* __restrict__ gwPtr, int alphaIdx, int alphaMode, int splitM,
    int betaOne, int doGelu, int outBf16,
    bf16* __restrict__ pfx2, bf16* __restrict__ pfx1, int pfxLd) {
    extern __shared__ bf16 smem[];
    bf16* As = smem;
    bf16* Bs = smem + NSTG * STG_E;

    const int tid = threadIdx.x;
    const int bm = blockIdx.y * BM;
    const int bn = blockIdx.x * BN;
    const int wid = tid >> 5, lane = tid & 31;
    const int wm = (wid & 3) * 32;
    const int wn = (wid >> 2) * 64;
    const int g = lane >> 2, t4 = lane & 3;
    const bool doPfx = (pfx2 != nullptr) && (bm >= splitM);

    float acc[2][8][4];
    #pragma unroll
    for (int i = 0; i < 2; i++)
        #pragma unroll
        for (int j = 0; j < 8; j++)
            #pragma unroll
            for (int q = 0; q < 4; q++) acc[i][j][q] = 0.0f;

    const int lrow = tid >> 2;
    const int lc = (tid & 3) * 8;
    const bf16* Ag = A + (size_t)(bm + lrow) * lda + lc;
    const bf16* Bg = B + (size_t)(bn + lrow) * ldb + lc;
    const bool bval0 = (bn + lrow) < N;
    const bool bval1 = (bn + lrow + 64) < N;

    const int KI = K / BK;

    // prologue: stages 0..2
    #pragma unroll
    for (int st = 0; st < 3; st++) {
        uint32_t a0 = (uint32_t)__cvta_generic_to_shared(&As[st * STG_E + lrow * GST + lc]);
        uint32_t b0 = (uint32_t)__cvta_generic_to_shared(&Bs[st * STG_E + lrow * GST + lc]);
        cpa16(a0, Ag + (size_t)0 * lda + st * BK, true);
        cpa16(a0 + 64 * GST * 2, Ag + (size_t)64 * lda + st * BK, true);
        cpa16(b0, Bg + (size_t)0 * ldb + st * BK, bval0);
        cpa16(b0 + 64 * GST * 2, Bg + (size_t)64 * ldb + st * BK, bval1);
        asm volatile("cp.async.commit_group;\n");
    }

    #pragma unroll 1
    for (int i = 0; i < KI; i++) {
        if (i + 2 < KI)      { asm volatile("cp.async.wait_group 2;\n"); }
        else if (i + 1 < KI) { asm volatile("cp.async.wait_group 1;\n"); }
        else                 { asm volatile("cp.async.wait_group 0;\n"); }
        __syncthreads();
        if (i + 3 < KI) {
            int st = (i + 3) & 3;
            uint32_t a0 = (uint32_t)__cvta_generic_to_shared(&As[st * STG_E + lrow * GST + lc]);
            uint32_t b0 = (uint32_t)__cvta_generic_to_shared(&Bs[st * STG_E + lrow * GST + lc]);
            int ko = (i + 3) * BK;
            cpa16(a0, Ag + (size_t)0 * lda + ko, true);
            cpa16(a0 + 64 * GST * 2, Ag + (size_t)64 * lda + ko, true);
            cpa16(b0, Bg + (size_t)0 * ldb + ko, bval0);
            cpa16(b0 + 64 * GST * 2, Bg + (size_t)64 * ldb + ko, bval1);
            asm volatile("cp.async.commit_group;\n");
        }
        const bf16* Ab = &As[(i & 3) * STG_E];
        const bf16* Bb = &Bs[(i & 3) * STG_E];
        #pragma unroll
        for (int ks = 0; ks < 2; ks++) {
            const int kb = ks * 16;
            uint32_t af[2][4];
            #pragma unroll
            for (int mt = 0; mt < 2; mt++)
                ldsm_x4(af[mt], &Ab[(wm + mt * 16 + (lane & 15)) * GST + kb + ((lane >> 4) << 3)]);
            uint32_t bfm[8][2];
            #pragma unroll
            for (int nt2 = 0; nt2 < 4; nt2++) {
                uint32_t r4[4];
                ldsm_x4(r4, &Bb[(wn + nt2 * 16 + (lane & 7) + ((lane >> 4) << 3)) * GST
                                 + kb + (((lane >> 3) & 1) << 3)]);
                bfm[nt2 * 2][0] = r4[0]; bfm[nt2 * 2][1] = r4[1];
                bfm[nt2 * 2 + 1][0] = r4[2]; bfm[nt2 * 2 + 1][1] = r4[3];
            }
            #pragma unroll
            for (int nt = 0; nt < 8; nt++) {
                mma_bf16(acc[0][nt], af[0], bfm[nt][0], bfm[nt][1]);
                mma_bf16(acc[1][nt], af[1], bfm[nt][0], bfm[nt][1]);
            }
        }
        // prefix snapshots: acc holds sum over k < (i+1)*32
        if (doPfx && i <= 1) {
            bf16* P = (i == 0) ? pfx2 : pfx1;
            #pragma unroll
            for (int nt = 0; nt < 8; nt++) {
                int c0 = bn + wn + nt * 8 + t4 * 2;
                if (c0 >= N) continue;
                float bv0 = bias ? bias[c0] : 0.0f;
                float bv1 = bias ? bias[c0 + 1] : 0.0f;
                #pragma unroll
                for (int mt = 0; mt < 2; mt++)
                    #pragma unroll
                    for (int half = 0; half < 2; half++) {
                        int r = bm + wm + mt * 16 + g + half * 8;
                        float v0 = acc[mt][nt][half * 2 + 0] + bv0;
                        float v1 = acc[mt][nt][half * 2 + 1] + bv1;
                        if (doGelu) {
                            v0 = 0.5f * v0 * (1.0f + erff(v0 * 0.70710678118654752f));
                            v1 = 0.5f * v1 * (1.0f + erff(v1 * 0.70710678118654752f));
                        }
                        *(bf162*)(P + (size_t)(r - splitM) * pfxLd + c0)
                            = __floats2bfloat162_rn(v0, v1);
                    }
            }
        }
    }

    float alpha = 1.0f;
    if (alphaMode == 1) alpha = __ldg(&gwPtr[alphaIdx]);
    else if (alphaMode == 2 && bm >= splitM) alpha = __ldg(&gwPtr[0]);

    #pragma unroll
    for (int nt = 0; nt < 8; nt++) {
        int c0 = bn + wn + nt * 8 + t4 * 2;
        if (c0 >= N) continue;
        float bv0 = bias ? bias[c0] : 0.0f;
        float bv1 = bias ? bias[c0 + 1] : 0.0f;
        #pragma unroll
        for (int mt = 0; mt < 2; mt++) {
            #pragma unroll
            for (int half = 0; half < 2; half++) {
                int r = bm + wm + mt * 16 + g + half * 8;
                float v0 = acc[mt][nt][half * 2 + 0] + bv0;
                float v1 = acc[mt][nt][half * 2 + 1] + bv1;
                if (doGelu) {
                    v0 = 0.5f * v0 * (1.0f + erff(v0 * 0.70710678118654752f));
                    v1 = 0.5f * v1 * (1.0f + erff(v1 * 0.70710678118654752f));
                }
                v0 *= alpha; v1 *= alpha;
                size_t off = (size_t)r * ldc + c0;
                if (outBf16) {
                    *(bf162*)((bf16*)Cv + off) = __floats2bfloat162_rn(v0, v1);
                } else {
                    float* Cf = (float*)Cv;
                    if (betaOne) {
                        float2 old = *(const float2*)(Cf + off);
                        v0 += old.x; v1 += old.y;
                    }
                    *(float2*)(Cf + off) = make_float2(v0, v1);
                }
            }
        }
    }
}

// ---------------- bf16 tensor-core window attention (all variants, one launch) ----------------
#define AQS 56
#define VST 72
#define SST 68
__global__ __launch_bounds__(128) void attn_kernel(
    const bf16* __restrict__ QKVf,
    const bf16* __restrict__ QKV1,
    const bf16* __restrict__ QKV2,
    const float* __restrict__ CB,
    bf16* __restrict__ Of,
    bf16* __restrict__ O1,
    bf16* __restrict__ O2) {
    const int lw = blockIdx.x;
    const int h  = blockIdx.y;
    const int z  = blockIdx.z;
    if (z > 0 && lw >= NWIN_HALF) return;
    const int mi = lw & 63;
    const bf16* QKV = (z == 0) ? QKVf : (z == 1 ? QKV1 : QKV2);
    bf16* O = (z == 0) ? Of : (z == 1 ? O1 : O2);
    __shared__ bf16 sq[64 * AQS];
    __shared__ bf16 sk[64 * AQS];
    __shared__ bf16 sVt[32 * VST];
    __shared__ bf16 sP[64 * VST];
    __shared__ float sS[64 * SST];
    const int tid = threadIdx.x;
    const int wid = tid >> 5, lane = tid & 31;
    const int g = lane >> 2, t4 = lane & 3;
    const int wr = wid * 16;

    const bf16* base = QKV + (size_t)lw * Nn * 384 + h * HDd;
    for (int idx = tid; idx < Nn * 4; idx += 128) {
        int n = idx >> 2, dc = (idx & 3) * 8;
        const bf16* row = base + n * 384;
        *(uint4*)&sq[n * AQS + dc] = *(const uint4*)(row + dc);
        *(uint4*)&sk[n * AQS + dc] = *(const uint4*)(row + 128 + dc);
    }
    for (int idx = tid; idx < Nn * HDd; idx += 128) {
        int n = idx >> 5, d = idx & 31;
        sVt[d * VST + n] = base[n * 384 + 256 + d];
    }
    for (int idx = tid; idx < 15 * 32; idx += 128) {
        int n = 49 + (idx >> 5), d = idx & 31;
        sq[n * AQS + d] = __float2bfloat16(0.0f);
        sk[n * AQS + d] = __float2bfloat16(0.0f);
    }
    for (int idx = tid; idx < 32 * 15; idx += 128) {
        int d = idx / 15, m = 49 + idx % 15;
        sVt[d * VST + m] = __float2bfloat16(0.0f);
    }
    for (int idx = tid; idx < 15 * 64; idx += 128) {
        int n = 49 + (idx >> 6), m = idx & 63;
        sP[n * VST + m] = __float2bfloat16(0.0f);
    }
    __syncthreads();

    const float* cb = CB + ((size_t)mi * NHn + h) * (Nn * Nn);
    {
        float acc[8][4];
        #pragma unroll
        for (int nt = 0; nt < 8; nt++)
            #pragma unroll
            for (int q = 0; q < 4; q++) acc[nt][q] = 0.0f;
        #pragma unroll
        for (int ks = 0; ks < 2; ks++) {
            int kb = ks * 16;
            uint32_t aq[4];
            ldsm_x4(aq, &sq[(wr + (lane & 15)) * AQS + kb + ((lane >> 4) << 3)]);
            #pragma unroll
            for (int nt2 = 0; nt2 < 4; nt2++) {
                uint32_t r4[4];
                ldsm_x4(r4, &sk[(nt2 * 16 + (lane & 7) + ((lane >> 4) << 3)) * AQS
                                 + kb + (((lane >> 3) & 1) << 3)]);
                mma_bf16(acc[nt2 * 2],     aq, r4[0], r4[1]);
                mma_bf16(acc[nt2 * 2 + 1], aq, r4[2], r4[3]);
            }
        }
        #pragma unroll
        for (int nt = 0; nt < 8; nt++) {
            int col = nt * 8 + t4 * 2;
            #pragma unroll
            for (int half = 0; half < 2; half++) {
                int r = wr + g + half * 8;
                float v0 = acc[nt][half * 2 + 0] * SCALE;
                float v1 = acc[nt][half * 2 + 1] * SCALE;
                if (r < Nn) {
                    if (col < Nn)     v0 += __ldg(&cb[r * Nn + col]);
                    if (col + 1 < Nn) v1 += __ldg(&cb[r * Nn + col + 1]);
                }
                sS[r * SST + col]     = v0;
                sS[r * SST + col + 1] = v1;
            }
        }
    }
    __syncthreads();

    if (tid < Nn) {
        const float* row = &sS[tid * SST];
        bf16* prow = &sP[tid * VST];
        float mx = -1e30f;
        #pragma unroll
        for (int m = 0; m < Nn; m++) mx = fmaxf(mx, row[m]);
        float sum = 0.0f;
        float e[Nn];
        #pragma unroll
        for (int m = 0; m < Nn; m++) { e[m] = __expf(row[m] - mx); sum += e[m]; }
        float rs = 1.0f / sum;
        #pragma unroll
        for (int m = 0; m < Nn; m++) prow[m] = __float2bfloat16(e[m] * rs);
        #pragma unroll
        for (int m = Nn; m < 64; m++) prow[m] = __float2bfloat16(0.0f);
    }
    __syncthreads();

    {
        float acc[4][4];
        #pragma unroll
        for (int nt = 0; nt < 4; nt++)
            #pragma unroll
            for (int q = 0; q < 4; q++) acc[nt][q] = 0.0f;
        #pragma unroll
        for (int ks = 0; ks < 4; ks++) {
            int kb = ks * 16;
            uint32_t ap[4];
            ldsm_x4(ap, &sP[(wr + (lane & 15)) * VST + kb + ((lane >> 4) << 3)]);
            #pragma unroll
            for (int nt2 = 0; nt2 < 2; nt2++) {
                uint32_t r4[4];
                ldsm_x4(r4, &sVt[(nt2 * 16 + (lane & 7) + ((lane >> 4) << 3)) * VST
                                  + kb + (((lane >> 3) & 1) << 3)]);
                mma_bf16(acc[nt2 * 2],     ap, r4[0], r4[1]);
                mma_bf16(acc[nt2 * 2 + 1], ap, r4[2], r4[3]);
            }
        }
        #pragma unroll
        for (int nt = 0; nt < 4; nt++) {
            int col = nt * 8 + t4 * 2;
            #pragma unroll
            for (int half = 0; half < 2; half++) {
                int r = wr + g + half * 8;
                if (r < Nn)
                    *(bf162*)(O + (size_t)(lw * Nn + r) * Cdim + h * HDd + col)
                        = __floats2bfloat162_rn(acc[nt][half * 2 + 0], acc[nt][half * 2 + 1]);
            }
        }
    }
}

// ---------------- host helpers ----------------
static inline void launch_gemm(const bf16* A, int lda, const bf16* B, int ldb,
                               const float* bias, void* C, int ldc,
                               int M, int N, int K,
                               const float* gwP, int ai, int aMode, int splitM,
                               int betaOne, int gelu, int outBf16,
                               bf16* pfx2 = nullptr, bf16* pfx1 = nullptr, int pfxLd = 0) {
    dim3 grid((N + BN - 1) / BN, M / BM);
    bgemm<<<grid, 256, GEMM_SMEM>>>(A, lda, B, ldb, bias, C, ldc, M, N, K,
                                    gwP, ai, aMode, splitM, betaOne, gelu, outBf16,
                                    pfx2, pfx1, pfxLd);
}

extern "C" void kernel_launch(void* const* d_in, const int* in_sizes, int n_in,
                              void* d_out, int out_size) {
    const float* x     = (const float*)d_in[0];
    const float* gw    = (const float*)d_in[1];
    const float* n1w   = (const float*)d_in[2];
    const float* n1b   = (const float*)d_in[3];
    const float* qkvw  = (const float*)d_in[4];
    const float* qkvb  = (const float*)d_in[5];
    const float* rbt   = (const float*)d_in[6];
    const float* projw = (const float*)d_in[7];
    const float* projb = (const float*)d_in[8];
    const float* amask = (const float*)d_in[9];
    const float* n2w   = (const float*)d_in[10];
    const float* n2b   = (const float*)d_in[11];
    const float* f1w   = (const float*)d_in[12];
    const float* f1b   = (const float*)d_in[13];
    const float* f2w   = (const float*)d_in[14];
    const float* f2b   = (const float*)d_in[15];
    const int*   relIdx= (const int*)d_in[16];
    float* out = (float*)d_out;

    cudaFuncSetAttribute(bgemm, cudaFuncAttributeMaxDynamicSharedMemorySize, GEMM_SMEM);

    bf16 *XW, *QKVf, *QKV1, *QKV2, *O, *Oh1, *Oh2, *XN, *Hb, *H1, *H2, *Wb;
    float *Y, *CB;
    cudaGetSymbolAddress((void**)&XW,   g_XW);
    cudaGetSymbolAddress((void**)&QKVf, g_QKVf);
    cudaGetSymbolAddress((void**)&QKV1, g_QKV1);
    cudaGetSymbolAddress((void**)&QKV2, g_QKV2);
    cudaGetSymbolAddress((void**)&O,    g_O);
    cudaGetSymbolAddress((void**)&Oh1,  g_Oh1);
    cudaGetSymbolAddress((void**)&Oh2,  g_Oh2);
    cudaGetSymbolAddress((void**)&Y,    g_Y);
    cudaGetSymbolAddress((void**)&XN,   g_XN);
    cudaGetSymbolAddress((void**)&Hb,   g_H);
    cudaGetSymbolAddress((void**)&H1,   g_H1);
    cudaGetSymbolAddress((void**)&H2,   g_H2);
    cudaGetSymbolAddress((void**)&CB,   g_CB);
    cudaGetSymbolAddress((void**)&Wb,   g_Wb);

    const bf16* qkvwB = Wb;
    const bf16* projwB = Wb + 49152;
    const bf16* f1wB = Wb + 65536;
    const bf16* f2wB = Wb + 131072;

    const int Mh = TOK_HALF;
    const int Mf = TOK_TOTAL;

    // fused prep: weight cast + bias table + LN1/partition
    prep_kernel<<<PREP_W + PREP_B + PREP_LN, 256>>>(
        qkvw, projw, f1w, f2w, Wb, rbt, relIdx, amask, CB, x, n1w, n1b, XW);

    // QKV merged: full (K=128) + prefix K=64 -> QKV1, K=32 -> QKV2
    launch_gemm(XW, Cdim, qkvwB, Cdim, qkvb, QKVf, 384, Mf, 384, 128,
                nullptr, 0, 0, Mh, 0, 0, 1, QKV2, QKV1, 384);

    // attention: all three variants in one launch
    attn_kernel<<<dim3(NWIN_TOTAL, NHn, 3), 128>>>(QKVf, QKV1, QKV2, CB, O, Oh1, Oh2);

    // proj
    launch_gemm(O, Cdim, projwB, Cdim, projb, Y, Cdim, Mf, 128, 128, gw, 0, 2, Mh, 0, 0, 0);
    launch_gemm(Oh1, Cdim, projwB, Cdim, projb, Y + (size_t)Mh * Cdim, Cdim, Mh, 64, 128, gw, 1, 1, 0, 1, 0, 0);
    launch_gemm(Oh2, Cdim, projwB, Cdim, projb, Y + (size_t)Mh * Cdim, Cdim, Mh, 32, 128, gw, 2, 1, 0, 1, 0, 0);

    // residual + LN2
    resid_ln2_kernel<<<TOK_TOTAL / 8, 256>>>(x, Y, n2w, n2b, out, XN);

    // FC1 merged: H (K=128) + H1 (K=64) + H2 (K=32), GELU on all
    launch_gemm(XN, Cdim, f1wB, Cdim, f1b, Hb, HID, Mf, HID, 128,
                nullptr, 0, 0, Mh, 0, 1, 1, H2, H1, HID);

    // FC2
    launch_gemm(Hb, HID, f2wB, HID, f2b, out, Cdim, Mf, 128, 512, gw, 0, 2, Mh, 1, 0, 0);
    launch_gemm(H1, HID, f2wB, HID, f2b, out + (size_t)Mh * Cdim, Cdim, Mh, 64, 512, gw, 1, 1, 0, 1, 0, 0);
    launch_gemm(H2, HID, f2wB, HID, f2b, out + (size_t)Mh * Cdim, Cdim, Mh, 32, 512, gw, 2, 1, 0, 1, 0, 0);
}

// round 8
// speedup vs baseline: 5.0503x; 1.0056x over previous
#include <cuda_runtime.h>
#include <cuda_bf16.h>
#include <cstdint>
#include <cstddef>
#include <math.h>

// ---------------- problem constants ----------------
#define Bimg 64
#define Hdim 56
#define Wdim 56
#define WS 7
#define SHIFT 3
#define Cdim 128
#define NHn 4
#define HDd 32
#define Nn 49
#define NWn 64
#define HID 512
#define SCALE 0.17677669529663688f

#define NWIN_TOTAL (Bimg * NWn)          // 4096
#define NWIN_HALF  (NWIN_TOTAL / 2)      // 2048
#define TOK_TOTAL  (NWIN_TOTAL * Nn)     // 200704
#define TOK_HALF   (NWIN_HALF * Nn)      // 100352

typedef __nv_bfloat16 bf16;
typedef __nv_bfloat162 bf162;

// ---------------- scratch (device globals) ----------------
__device__ bf16  g_XW  [(size_t)TOK_TOTAL * Cdim];
__device__ bf16  g_QKVf[(size_t)TOK_TOTAL * 384];
__device__ bf16  g_QKV1[(size_t)TOK_HALF  * 384];
__device__ bf16  g_QKV2[(size_t)TOK_HALF  * 384];
__device__ bf16  g_O   [(size_t)TOK_TOTAL * Cdim];
__device__ bf16  g_Oh1 [(size_t)TOK_HALF  * Cdim];
__device__ bf16  g_Oh2 [(size_t)TOK_HALF  * Cdim];
__device__ float g_Y   [(size_t)TOK_TOTAL * Cdim];
__device__ bf16  g_XN  [(size_t)TOK_TOTAL * Cdim];
__device__ bf16  g_H   [(size_t)TOK_TOTAL * HID];
__device__ bf16  g_H1  [(size_t)TOK_HALF  * HID];
__device__ bf16  g_H2  [(size_t)TOK_HALF  * HID];
__device__ float g_CB  [(size_t)NWn * NHn * Nn * Nn];
__device__ bf16  g_Wb  [196608];   // bf16 weights: qkvw|projw|f1w|f2w

// ---------------- fused prep: weights->bf16, bias+mask, LN1+roll+partition ----------------
#define PREP_W 192
#define PREP_B 256
#define PREP_LN (TOK_TOTAL / 8)
__global__ __launch_bounds__(256) void prep_kernel(
    const float* __restrict__ qkvw, const float* __restrict__ projw,
    const float* __restrict__ f1w, const float* __restrict__ f2w,
    bf16* __restrict__ Wb,
    const float* __restrict__ rbt, const int* __restrict__ relIdx,
    const float* __restrict__ mask, float* __restrict__ CB,
    const float* __restrict__ x, const float* __restrict__ n1w,
    const float* __restrict__ n1b, bf16* __restrict__ XW) {
    int bid = blockIdx.x;
    if (bid < PREP_W) {
        int i = (bid * 256 + threadIdx.x) * 4;
        const float* src; int off;
        if (i < 49152)       { src = qkvw;  off = i; }
        else if (i < 65536)  { src = projw; off = i - 49152; }
        else if (i < 131072) { src = f1w;   off = i - 65536; }
        else                 { src = f2w;   off = i - 131072; }
        float4 v = *(const float4*)(src + off);
        *(bf162*)(Wb + i)     = __floats2bfloat162_rn(v.x, v.y);
        *(bf162*)(Wb + i + 2) = __floats2bfloat162_rn(v.z, v.w);
        return;
    }
    if (bid < PREP_W + PREP_B) {
        int b = bid - PREP_W;
        int mi = b >> 2, h = b & 3;
        float* dst = CB + ((size_t)mi * NHn + h) * (Nn * Nn);
        const float* msk = mask + (size_t)mi * (Nn * Nn);
        for (int idx = threadIdx.x; idx < Nn * Nn; idx += 256)
            dst[idx] = __ldg(&rbt[relIdx[idx] * NHn + h]) + msk[idx];
        return;
    }
    int t = (bid - PREP_W - PREP_B) * 8 + (threadIdx.x >> 5);
    int lane = threadIdx.x & 31;
    int win = t / Nn, n = t - win * Nn;
    int bi = win >> 6, wi = win & 63;
    int hs = ((wi >> 3) * WS + n / WS + SHIFT) % Hdim;
    int ws = ((wi & 7) * WS + n % WS + SHIFT) % Wdim;
    const float* xp = x + ((size_t)bi * (Hdim * Wdim) + hs * Wdim + ws) * Cdim;
    float4 v = *(const float4*)(xp + lane * 4);
    float s  = v.x + v.y + v.z + v.w;
    float s2 = v.x * v.x + v.y * v.y + v.z * v.z + v.w * v.w;
    #pragma unroll
    for (int o = 16; o > 0; o >>= 1) {
        s  += __shfl_xor_sync(0xffffffffu, s, o);
        s2 += __shfl_xor_sync(0xffffffffu, s2, o);
    }
    float mu  = s * (1.0f / Cdim);
    float var = s2 * (1.0f / Cdim) - mu * mu;
    float inv = rsqrtf(var + 1e-5f);
    float4 wv = *(const float4*)(n1w + lane * 4);
    float4 bv = *(const float4*)(n1b + lane * 4);
    bf16* dst = XW + (size_t)t * Cdim + lane * 4;
    *(bf162*)(dst)     = __floats2bfloat162_rn((v.x - mu) * inv * wv.x + bv.x,
                                               (v.y - mu) * inv * wv.y + bv.y);
    *(bf162*)(dst + 2) = __floats2bfloat162_rn((v.z - mu) * inv * wv.z + bv.z,
                                               (v.w - mu) * inv * wv.w + bv.w);
}

// ---------------- window reverse + roll + residual + LN2 ----------------
__global__ __launch_bounds__(256) void resid_ln2_kernel(const float* __restrict__ x,
                                 const float* __restrict__ Y,
                                 const float* __restrict__ w,
                                 const float* __restrict__ b,
                                 float* __restrict__ out,
                                 bf16* __restrict__ XN) {
    int t = blockIdx.x * 8 + (threadIdx.x >> 5);
    int lane = threadIdx.x & 31;
    int win = t / Nn, n = t - win * Nn;
    int bi = win >> 6, wi = win & 63;
    int hs = ((wi >> 3) * WS + n / WS + SHIFT) % Hdim;
    int ws = ((wi & 7) * WS + n % WS + SHIFT) % Wdim;
    size_t pos = ((size_t)bi * (Hdim * Wdim) + hs * Wdim + ws) * Cdim;
    float4 xv = *(const float4*)(x + pos + lane * 4);
    float4 yv = *(const float4*)(Y + (size_t)t * Cdim + lane * 4);
    float4 v;
    v.x = xv.x + yv.x; v.y = xv.y + yv.y; v.z = xv.z + yv.z; v.w = xv.w + yv.w;
    *(float4*)(out + pos + lane * 4) = v;
    float s  = v.x + v.y + v.z + v.w;
    float s2 = v.x * v.x + v.y * v.y + v.z * v.z + v.w * v.w;
    #pragma unroll
    for (int o = 16; o > 0; o >>= 1) {
        s  += __shfl_xor_sync(0xffffffffu, s, o);
        s2 += __shfl_xor_sync(0xffffffffu, s2, o);
    }
    float mu  = s * (1.0f / Cdim);
    float var = s2 * (1.0f / Cdim) - mu * mu;
    float inv = rsqrtf(var + 1e-5f);
    float4 wv = *(const float4*)(w + lane * 4);
    float4 bv = *(const float4*)(b + lane * 4);
    bf16* dst = XN + pos + lane * 4;
    *(bf162*)(dst)     = __floats2bfloat162_rn((v.x - mu) * inv * wv.x + bv.x,
                                               (v.y - mu) * inv * wv.y + bv.y);
    *(bf162*)(dst + 2) = __floats2bfloat162_rn((v.z - mu) * inv * wv.z + bv.z,
                                               (v.w - mu) * inv * wv.w + bv.w);
}

// ---------------- mma / ldmatrix helpers ----------------
__device__ __forceinline__ void mma_bf16(float* c, const uint32_t* a, uint32_t b0, uint32_t b1) {
    asm volatile("mma.sync.aligned.m16n8k16.row.col.f32.bf16.bf16.f32 "
        "{%0,%1,%2,%3}, {%4,%5,%6,%7}, {%8,%9}, {%0,%1,%2,%3};\n"
        : "+f"(c[0]), "+f"(c[1]), "+f"(c[2]), "+f"(c[3])
        : "r"(a[0]), "r"(a[1]), "r"(a[2]), "r"(a[3]), "r"(b0), "r"(b1));
}
__device__ __forceinline__ void ldsm_x4(uint32_t* r, const bf16* p) {
    uint32_t addr = (uint32_t)__cvta_generic_to_shared(p);
    asm volatile("ldmatrix.sync.aligned.m8n8.x4.shared.b16 {%0,%1,%2,%3}, [%4];\n"
        : "=r"(r[0]), "=r"(r[1]), "=r"(r[2]), "=r"(r[3]) : "r"(addr));
}
__device__ __forceinline__ void cpa16(uint32_t dst, const void* src, bool pred) {
    int sz = pred ? 16 : 0;
    asm volatile("cp.async.cg.shared.global [%0], [%1], 16, %2;\n"
                 :: "r"(dst), "l"(src), "r"(sz));
}

// ---------------- persistent BF16 GEMM, flattened (tile,k) cp.async pipeline ----------------
// A: MxK bf16 row-major, B: NxK bf16 row-major. M%128==0, K in {128,512}.
// Each CTA fixes bn and strides over M tiles; pipeline never drains between tiles.
// For K=128 the B tile is smem-resident after the first tile (stage==k).
#define BM 128
#define BN 128
#define BK 32
#define GST 40
#define STG_E (BM * GST)
#define NSTG 4
#define GEMM_SMEM (NSTG * 2 * STG_E * 2)

__global__ __launch_bounds__(256, 2) void bgemm(
    const bf16* __restrict__ A, int lda,
    const bf16* __restrict__ B, int ldb,
    const float* __restrict__ bias,
    void* __restrict__ Cv, int ldc,
    int M, int N, int K,
    const float* __restrict__ gwPtr, int alphaIdx, int alphaMode, int splitM,
    int betaOne, int doGelu, int outBf16,
    bf16* __restrict__ pfx2, bf16* __restrict__ pfx1, int pfxLd) {
    extern __shared__ bf16 smem[];
    bf16* As = smem;
    bf16* Bs = smem + NSTG * STG_E;

    const int tid = threadIdx.x;
    const int bn = blockIdx.x * BN;
    const int wid = tid >> 5, lane = tid & 31;
    const int wm = (wid & 3) * 32;
    const int wn = (wid >> 2) * 64;
    const int g4 = lane >> 2, t4 = lane & 3;

    const int lrow = tid >> 2;
    const int lc = (tid & 3) * 8;
    const bf16* Bg = B + (size_t)(bn + lrow) * ldb + lc;
    const bool bval0 = (bn + lrow) < N;
    const bool bval1 = (bn + lrow + 64) < N;

    const int KI = K / BK;                 // 4 or 16
    const int kiLog = (KI == 16) ? 4 : 2;
    const int kiMask = KI - 1;
    const bool resB = (KI == 4);           // B resident after first tile
    const int nT = M / BM;
    const int GYm = gridDim.y;
    const int myT = (nT - (int)blockIdx.y + GYm - 1) / GYm;
    if (myT <= 0) return;
    const int G = myT * KI;

    float acc[2][8][4];

    auto tileBM = [&](int t) { return ((int)blockIdx.y + t * GYm) * BM; };

    auto issue = [&](int g) {
        int t = g >> kiLog, k = g & kiMask;
        int bm = tileBM(t);
        int st = g & 3;
        uint32_t a0 = (uint32_t)__cvta_generic_to_shared(&As[st * STG_E + lrow * GST + lc]);
        const bf16* Agp = A + (size_t)(bm + lrow) * lda + k * BK + lc;
        cpa16(a0, Agp, true);
        cpa16(a0 + 64 * GST * 2, Agp + (size_t)64 * lda, true);
        if (!resB || g < 4) {
            uint32_t b0 = (uint32_t)__cvta_generic_to_shared(&Bs[st * STG_E + lrow * GST + lc]);
            cpa16(b0, Bg + k * BK, bval0);
            cpa16(b0 + 64 * GST * 2, Bg + k * BK + (size_t)64 * ldb, bval1);
        }
        asm volatile("cp.async.commit_group;\n");
    };

    auto computeStage = [&](int st) {
        const bf16* Ab = &As[st * STG_E];
        const bf16* Bb = &Bs[st * STG_E];
        #pragma unroll
        for (int ks = 0; ks < 2; ks++) {
            const int kb = ks * 16;
            uint32_t af[2][4];
            #pragma unroll
            for (int mt = 0; mt < 2; mt++)
                ldsm_x4(af[mt], &Ab[(wm + mt * 16 + (lane & 15)) * GST + kb + ((lane >> 4) << 3)]);
            uint32_t bfm[8][2];
            #pragma unroll
            for (int nt2 = 0; nt2 < 4; nt2++) {
                uint32_t r4[4];
                ldsm_x4(r4, &Bb[(wn + nt2 * 16 + (lane & 7) + ((lane >> 4) << 3)) * GST
                                 + kb + (((lane >> 3) & 1) << 3)]);
                bfm[nt2 * 2][0] = r4[0]; bfm[nt2 * 2][1] = r4[1];
                bfm[nt2 * 2 + 1][0] = r4[2]; bfm[nt2 * 2 + 1][1] = r4[3];
            }
            #pragma unroll
            for (int nt = 0; nt < 8; nt++) {
                mma_bf16(acc[0][nt], af[0], bfm[nt][0], bfm[nt][1]);
                mma_bf16(acc[1][nt], af[1], bfm[nt][0], bfm[nt][1]);
            }
        }
    };

    auto snapshot = [&](bf16* __restrict__ P, int bm) {
        #pragma unroll
        for (int nt = 0; nt < 8; nt++) {
            int c0 = bn + wn + nt * 8 + t4 * 2;
            if (c0 >= N) continue;
            float bv0 = bias ? bias[c0] : 0.0f;
            float bv1 = bias ? bias[c0 + 1] : 0.0f;
            #pragma unroll
            for (int mt = 0; mt < 2; mt++)
                #pragma unroll
                for (int half = 0; half < 2; half++) {
                    int r = bm + wm + mt * 16 + g4 + half * 8;
                    float v0 = acc[mt][nt][half * 2 + 0] + bv0;
                    float v1 = acc[mt][nt][half * 2 + 1] + bv1;
                    if (doGelu) {
                        v0 = 0.5f * v0 * (1.0f + erff(v0 * 0.70710678118654752f));
                        v1 = 0.5f * v1 * (1.0f + erff(v1 * 0.70710678118654752f));
                    }
                    *(bf162*)(P + (size_t)(r - splitM) * pfxLd + c0)
                        = __floats2bfloat162_rn(v0, v1);
                }
        }
    };

    auto epilogue = [&](int bm) {
        float alpha = 1.0f;
        if (alphaMode == 1) alpha = __ldg(&gwPtr[alphaIdx]);
        else if (alphaMode == 2 && bm >= splitM) alpha = __ldg(&gwPtr[0]);
        #pragma unroll
        for (int nt = 0; nt < 8; nt++) {
            int c0 = bn + wn + nt * 8 + t4 * 2;
            if (c0 >= N) continue;
            float bv0 = bias ? bias[c0] : 0.0f;
            float bv1 = bias ? bias[c0 + 1] : 0.0f;
            #pragma unroll
            for (int mt = 0; mt < 2; mt++) {
                #pragma unroll
                for (int half = 0; half < 2; half++) {
                    int r = bm + wm + mt * 16 + g4 + half * 8;
                    float v0 = acc[mt][nt][half * 2 + 0] + bv0;
                    float v1 = acc[mt][nt][half * 2 + 1] + bv1;
                    if (doGelu) {
                        v0 = 0.5f * v0 * (1.0f + erff(v0 * 0.70710678118654752f));
                        v1 = 0.5f * v1 * (1.0f + erff(v1 * 0.70710678118654752f));
                    }
                    v0 *= alpha; v1 *= alpha;
                    size_t off = (size_t)r * ldc + c0;
                    if (outBf16) {
                        *(bf162*)((bf16*)Cv + off) = __floats2bfloat162_rn(v0, v1);
                    } else {
                        float* Cf = (float*)Cv;
                        if (betaOne) {
                            float2 old = *(const float2*)(Cf + off);
                            v0 += old.x; v1 += old.y;
                        }
                        *(float2*)(Cf + off) = make_float2(v0, v1);
                    }
                }
            }
        }
    };

    // prologue: 3 groups in flight
    issue(0); issue(1); issue(2);

    #pragma unroll 1
    for (int g = 0; g < G; g++) {
        int rem = G - 1 - g;
        if (rem >= 2)      { asm volatile("cp.async.wait_group 2;\n"); }
        else if (rem == 1) { asm volatile("cp.async.wait_group 1;\n"); }
        else               { asm volatile("cp.async.wait_group 0;\n"); }
        __syncthreads();
        if (g + 3 < G) issue(g + 3);

        int t = g >> kiLog, k = g & kiMask;
        int bm = tileBM(t);
        if (k == 0) {
            #pragma unroll
            for (int i = 0; i < 2; i++)
                #pragma unroll
                for (int j = 0; j < 8; j++)
                    #pragma unroll
                    for (int q = 0; q < 4; q++) acc[i][j][q] = 0.0f;
        }
        computeStage(g & 3);
        if (pfx2 != nullptr && bm >= splitM && k <= 1)
            snapshot((k == 0) ? pfx2 : pfx1, bm);
        if (k == kiMask) epilogue(bm);
    }
}

// ---------------- bf16 tensor-core window attention (all variants, one launch) ----------------
#define AQS 56
#define VST 72
#define SST 68
__global__ __launch_bounds__(128) void attn_kernel(
    const bf16* __restrict__ QKVf,
    const bf16* __restrict__ QKV1,
    const bf16* __restrict__ QKV2,
    const float* __restrict__ CB,
    bf16* __restrict__ Of,
    bf16* __restrict__ O1,
    bf16* __restrict__ O2) {
    const int lw = blockIdx.x;
    const int h  = blockIdx.y;
    const int z  = blockIdx.z;
    if (z > 0 && lw >= NWIN_HALF) return;
    const int mi = lw & 63;
    const bf16* QKV = (z == 0) ? QKVf : (z == 1 ? QKV1 : QKV2);
    bf16* O = (z == 0) ? Of : (z == 1 ? O1 : O2);
    __shared__ bf16 sq[64 * AQS];
    __shared__ bf16 sk[64 * AQS];
    __shared__ bf16 sVt[32 * VST];
    __shared__ bf16 sP[64 * VST];
    __shared__ float sS[64 * SST];
    const int tid = threadIdx.x;
    const int wid = tid >> 5, lane = tid & 31;
    const int g = lane >> 2, t4 = lane & 3;
    const int wr = wid * 16;

    const bf16* base = QKV + (size_t)lw * Nn * 384 + h * HDd;
    for (int idx = tid; idx < Nn * 4; idx += 128) {
        int n = idx >> 2, dc = (idx & 3) * 8;
        const bf16* row = base + n * 384;
        *(uint4*)&sq[n * AQS + dc] = *(const uint4*)(row + dc);
        *(uint4*)&sk[n * AQS + dc] = *(const uint4*)(row + 128 + dc);
    }
    for (int idx = tid; idx < Nn * HDd; idx += 128) {
        int n = idx >> 5, d = idx & 31;
        sVt[d * VST + n] = base[n * 384 + 256 + d];
    }
    for (int idx = tid; idx < 15 * 32; idx += 128) {
        int n = 49 + (idx >> 5), d = idx & 31;
        sq[n * AQS + d] = __float2bfloat16(0.0f);
        sk[n * AQS + d] = __float2bfloat16(0.0f);
    }
    for (int idx = tid; idx < 32 * 15; idx += 128) {
        int d = idx / 15, m = 49 + idx % 15;
        sVt[d * VST + m] = __float2bfloat16(0.0f);
    }
    for (int idx = tid; idx < 15 * 64; idx += 128) {
        int n = 49 + (idx >> 6), m = idx & 63;
        sP[n * VST + m] = __float2bfloat16(0.0f);
    }
    __syncthreads();

    const float* cb = CB + ((size_t)mi * NHn + h) * (Nn * Nn);
    {
        float acc[8][4];
        #pragma unroll
        for (int nt = 0; nt < 8; nt++)
            #pragma unroll
            for (int q = 0; q < 4; q++) acc[nt][q] = 0.0f;
        #pragma unroll
        for (int ks = 0; ks < 2; ks++) {
            int kb = ks * 16;
            uint32_t aq[4];
            ldsm_x4(aq, &sq[(wr + (lane & 15)) * AQS + kb + ((lane >> 4) << 3)]);
            #pragma unroll
            for (int nt2 = 0; nt2 < 4; nt2++) {
                uint32_t r4[4];
                ldsm_x4(r4, &sk[(nt2 * 16 + (lane & 7) + ((lane >> 4) << 3)) * AQS
                                 + kb + (((lane >> 3) & 1) << 3)]);
                mma_bf16(acc[nt2 * 2],     aq, r4[0], r4[1]);
                mma_bf16(acc[nt2 * 2 + 1], aq, r4[2], r4[3]);
            }
        }
        #pragma unroll
        for (int nt = 0; nt < 8; nt++) {
            int col = nt * 8 + t4 * 2;
            #pragma unroll
            for (int half = 0; half < 2; half++) {
                int r = wr + g + half * 8;
                float v0 = acc[nt][half * 2 + 0] * SCALE;
                float v1 = acc[nt][half * 2 + 1] * SCALE;
                if (r < Nn) {
                    if (col < Nn)     v0 += __ldg(&cb[r * Nn + col]);
                    if (col + 1 < Nn) v1 += __ldg(&cb[r * Nn + col + 1]);
                }
                sS[r * SST + col]     = v0;
                sS[r * SST + col + 1] = v1;
            }
        }
    }
    __syncthreads();

    if (tid < Nn) {
        const float* row = &sS[tid * SST];
        bf16* prow = &sP[tid * VST];
        float mx = -1e30f;
        #pragma unroll
        for (int m = 0; m < Nn; m++) mx = fmaxf(mx, row[m]);
        float sum = 0.0f;
        float e[Nn];
        #pragma unroll
        for (int m = 0; m < Nn; m++) { e[m] = __expf(row[m] - mx); sum += e[m]; }
        float rs = 1.0f / sum;
        #pragma unroll
        for (int m = 0; m < Nn; m++) prow[m] = __float2bfloat16(e[m] * rs);
        #pragma unroll
        for (int m = Nn; m < 64; m++) prow[m] = __float2bfloat16(0.0f);
    }
    __syncthreads();

    {
        float acc[4][4];
        #pragma unroll
        for (int nt = 0; nt < 4; nt++)
            #pragma unroll
            for (int q = 0; q < 4; q++) acc[nt][q] = 0.0f;
        #pragma unroll
        for (int ks = 0; ks < 4; ks++) {
            int kb = ks * 16;
            uint32_t ap[4];
            ldsm_x4(ap, &sP[(wr + (lane & 15)) * VST + kb + ((lane >> 4) << 3)]);
            #pragma unroll
            for (int nt2 = 0; nt2 < 2; nt2++) {
                uint32_t r4[4];
                ldsm_x4(r4, &sVt[(nt2 * 16 + (lane & 7) + ((lane >> 4) << 3)) * VST
                                  + kb + (((lane >> 3) & 1) << 3)]);
                mma_bf16(acc[nt2 * 2],     ap, r4[0], r4[1]);
                mma_bf16(acc[nt2 * 2 + 1], ap, r4[2], r4[3]);
            }
        }
        #pragma unroll
        for (int nt = 0; nt < 4; nt++) {
            int col = nt * 8 + t4 * 2;
            #pragma unroll
            for (int half = 0; half < 2; half++) {
                int r = wr + g + half * 8;
                if (r < Nn)
                    *(bf162*)(O + (size_t)(lw * Nn + r) * Cdim + h * HDd + col)
                        = __floats2bfloat162_rn(acc[nt][half * 2 + 0], acc[nt][half * 2 + 1]);
            }
        }
    }
}

// ---------------- host helpers ----------------
static inline void launch_gemm(const bf16* A, int lda, const bf16* B, int ldb,
                               const float* bias, void* C, int ldc,
                               int M, int N, int K,
                               const float* gwP, int ai, int aMode, int splitM,
                               int betaOne, int gelu, int outBf16,
                               bf16* pfx2 = nullptr, bf16* pfx1 = nullptr, int pfxLd = 0) {
    int nbn = (N + BN - 1) / BN;
    int nT = M / BM;
    int gy = 296 / nbn;
    if (gy > nT) gy = nT;
    if (gy < 1) gy = 1;
    dim3 grid(nbn, gy);
    bgemm<<<grid, 256, GEMM_SMEM>>>(A, lda, B, ldb, bias, C, ldc, M, N, K,
                                    gwP, ai, aMode, splitM, betaOne, gelu, outBf16,
                                    pfx2, pfx1, pfxLd);
}

extern "C" void kernel_launch(void* const* d_in, const int* in_sizes, int n_in,
                              void* d_out, int out_size) {
    const float* x     = (const float*)d_in[0];
    const float* gw    = (const float*)d_in[1];
    const float* n1w   = (const float*)d_in[2];
    const float* n1b   = (const float*)d_in[3];
    const float* qkvw  = (const float*)d_in[4];
    const float* qkvb  = (const float*)d_in[5];
    const float* rbt   = (const float*)d_in[6];
    const float* projw = (const float*)d_in[7];
    const float* projb = (const float*)d_in[8];
    const float* amask = (const float*)d_in[9];
    const float* n2w   = (const float*)d_in[10];
    const float* n2b   = (const float*)d_in[11];
    const float* f1w   = (const float*)d_in[12];
    const float* f1b   = (const float*)d_in[13];
    const float* f2w   = (const float*)d_in[14];
    const float* f2b   = (const float*)d_in[15];
    const int*   relIdx= (const int*)d_in[16];
    float* out = (float*)d_out;

    cudaFuncSetAttribute(bgemm, cudaFuncAttributeMaxDynamicSharedMemorySize, GEMM_SMEM);

    bf16 *XW, *QKVf, *QKV1, *QKV2, *O, *Oh1, *Oh2, *XN, *Hb, *H1, *H2, *Wb;
    float *Y, *CB;
    cudaGetSymbolAddress((void**)&XW,   g_XW);
    cudaGetSymbolAddress((void**)&QKVf, g_QKVf);
    cudaGetSymbolAddress((void**)&QKV1, g_QKV1);
    cudaGetSymbolAddress((void**)&QKV2, g_QKV2);
    cudaGetSymbolAddress((void**)&O,    g_O);
    cudaGetSymbolAddress((void**)&Oh1,  g_Oh1);
    cudaGetSymbolAddress((void**)&Oh2,  g_Oh2);
    cudaGetSymbolAddress((void**)&Y,    g_Y);
    cudaGetSymbolAddress((void**)&XN,   g_XN);
    cudaGetSymbolAddress((void**)&Hb,   g_H);
    cudaGetSymbolAddress((void**)&H1,   g_H1);
    cudaGetSymbolAddress((void**)&H2,   g_H2);
    cudaGetSymbolAddress((void**)&CB,   g_CB);
    cudaGetSymbolAddress((void**)&Wb,   g_Wb);

    const bf16* qkvwB = Wb;
    const bf16* projwB = Wb + 49152;
    const bf16* f1wB = Wb + 65536;
    const bf16* f2wB = Wb + 131072;

    const int Mh = TOK_HALF;
    const int Mf = TOK_TOTAL;

    // fused prep: weight cast + bias table + LN1/partition
    prep_kernel<<<PREP_W + PREP_B + PREP_LN, 256>>>(
        qkvw, projw, f1w, f2w, Wb, rbt, relIdx, amask, CB, x, n1w, n1b, XW);

    // QKV merged: full (K=128) + prefix K=64 -> QKV1, K=32 -> QKV2
    launch_gemm(XW, Cdim, qkvwB, Cdim, qkvb, QKVf, 384, Mf, 384, 128,
                nullptr, 0, 0, Mh, 0, 0, 1, QKV2, QKV1, 384);

    // attention: all three variants in one launch
    attn_kernel<<<dim3(NWIN_TOTAL, NHn, 3), 128>>>(QKVf, QKV1, QKV2, CB, O, Oh1, Oh2);

    // proj
    launch_gemm(O, Cdim, projwB, Cdim, projb, Y, Cdim, Mf, 128, 128, gw, 0, 2, Mh, 0, 0, 0);
    launch_gemm(Oh1, Cdim, projwB, Cdim, projb, Y + (size_t)Mh * Cdim, Cdim, Mh, 64, 128, gw, 1, 1, 0, 1, 0, 0);
    launch_gemm(Oh2, Cdim, projwB, Cdim, projb, Y + (size_t)Mh * Cdim, Cdim, Mh, 32, 128, gw, 2, 1, 0, 1, 0, 0);

    // residual + LN2
    resid_ln2_kernel<<<TOK_TOTAL / 8, 256>>>(x, Y, n2w, n2b, out, XN);

    // FC1 merged: H (K=128) + H1 (K=64) + H2 (K=32), GELU on all
    launch_gemm(XN, Cdim, f1wB, Cdim, f1b, Hb, HID, Mf, HID, 128,
                nullptr, 0, 0, Mh, 0, 1, 1, H2, H1, HID);

    // FC2
    launch_gemm(Hb, HID, f2wB, HID, f2b, out, Cdim, Mf, 128, 512, gw, 0, 2, Mh, 1, 0, 0);
    launch_gemm(H1, HID, f2wB, HID, f2b, out + (size_t)Mh * Cdim, Cdim, Mh, 64, 512, gw, 1, 1, 0, 1, 0, 0);
    launch_gemm(H2, HID, f2wB, HID, f2b, out + (size_t)Mh * Cdim, Cdim, Mh, 32, 512, gw, 2, 1, 0, 1, 0, 0);
}

// round 9
// speedup vs baseline: 5.4555x; 1.0802x over previous
#include <cuda_runtime.h>
#include <cuda_bf16.h>
#include <cstdint>
#include <cstddef>
#include <math.h>

// ---------------- problem constants ----------------
#define Bimg 64
#define Hdim 56
#define Wdim 56
#define WS 7
#define SHIFT 3
#define Cdim 128
#define NHn 4
#define HDd 32
#define Nn 49
#define NWn 64
#define HID 512
#define SCALE 0.17677669529663688f

#define NWIN_TOTAL (Bimg * NWn)          // 4096
#define NWIN_HALF  (NWIN_TOTAL / 2)      // 2048
#define TOK_TOTAL  (NWIN_TOTAL * Nn)     // 200704
#define TOK_HALF   (NWIN_HALF * Nn)      // 100352

typedef __nv_bfloat16 bf16;
typedef __nv_bfloat162 bf162;

// ---------------- scratch (device globals) ----------------
__device__ bf16  g_XW  [(size_t)TOK_TOTAL * Cdim];
__device__ bf16  g_QKVf[(size_t)TOK_TOTAL * 384];
__device__ bf16  g_QKV1[(size_t)TOK_HALF  * 384];
__device__ bf16  g_QKV2[(size_t)TOK_HALF  * 384];
__device__ bf16  g_O   [(size_t)TOK_TOTAL * Cdim];
__device__ bf16  g_Oh1 [(size_t)TOK_HALF  * Cdim];
__device__ bf16  g_Oh2 [(size_t)TOK_HALF  * Cdim];
__device__ float g_Y   [(size_t)TOK_TOTAL * Cdim];
__device__ bf16  g_XN  [(size_t)TOK_TOTAL * Cdim];
__device__ bf16  g_H   [(size_t)TOK_TOTAL * HID];
__device__ bf16  g_H1  [(size_t)TOK_HALF  * HID];
__device__ bf16  g_H2  [(size_t)TOK_HALF  * HID];
__device__ float g_CB  [(size_t)NWn * NHn * Nn * Nn];
__device__ bf16  g_Wb  [196608];   // bf16 weights: qkvw|projw|f1w|f2w

// ---------------- fused prep: weights->bf16, bias+mask, LN1+roll+partition ----------------
#define PREP_W 192
#define PREP_B 256
#define PREP_LN (TOK_TOTAL / 8)
__global__ __launch_bounds__(256) void prep_kernel(
    const float* __restrict__ qkvw, const float* __restrict__ projw,
    const float* __restrict__ f1w, const float* __restrict__ f2w,
    bf16* __restrict__ Wb,
    const float* __restrict__ rbt, const int* __restrict__ relIdx,
    const float* __restrict__ mask, float* __restrict__ CB,
    const float* __restrict__ x, const float* __restrict__ n1w,
    const float* __restrict__ n1b, bf16* __restrict__ XW) {
    int bid = blockIdx.x;
    if (bid < PREP_W) {
        int i = (bid * 256 + threadIdx.x) * 4;
        const float* src; int off;
        if (i < 49152)       { src = qkvw;  off = i; }
        else if (i < 65536)  { src = projw; off = i - 49152; }
        else if (i < 131072) { src = f1w;   off = i - 65536; }
        else                 { src = f2w;   off = i - 131072; }
        float4 v = *(const float4*)(src + off);
        *(bf162*)(Wb + i)     = __floats2bfloat162_rn(v.x, v.y);
        *(bf162*)(Wb + i + 2) = __floats2bfloat162_rn(v.z, v.w);
        return;
    }
    if (bid < PREP_W + PREP_B) {
        int b = bid - PREP_W;
        int mi = b >> 2, h = b & 3;
        float* dst = CB + ((size_t)mi * NHn + h) * (Nn * Nn);
        const float* msk = mask + (size_t)mi * (Nn * Nn);
        for (int idx = threadIdx.x; idx < Nn * Nn; idx += 256)
            dst[idx] = __ldg(&rbt[relIdx[idx] * NHn + h]) + msk[idx];
        return;
    }
    int t = (bid - PREP_W - PREP_B) * 8 + (threadIdx.x >> 5);
    int lane = threadIdx.x & 31;
    int win = t / Nn, n = t - win * Nn;
    int bi = win >> 6, wi = win & 63;
    int hs = ((wi >> 3) * WS + n / WS + SHIFT) % Hdim;
    int ws = ((wi & 7) * WS + n % WS + SHIFT) % Wdim;
    const float* xp = x + ((size_t)bi * (Hdim * Wdim) + hs * Wdim + ws) * Cdim;
    float4 v = *(const float4*)(xp + lane * 4);
    float s  = v.x + v.y + v.z + v.w;
    float s2 = v.x * v.x + v.y * v.y + v.z * v.z + v.w * v.w;
    #pragma unroll
    for (int o = 16; o > 0; o >>= 1) {
        s  += __shfl_xor_sync(0xffffffffu, s, o);
        s2 += __shfl_xor_sync(0xffffffffu, s2, o);
    }
    float mu  = s * (1.0f / Cdim);
    float var = s2 * (1.0f / Cdim) - mu * mu;
    float inv = rsqrtf(var + 1e-5f);
    float4 wv = *(const float4*)(n1w + lane * 4);
    float4 bv = *(const float4*)(n1b + lane * 4);
    bf16* dst = XW + (size_t)t * Cdim + lane * 4;
    *(bf162*)(dst)     = __floats2bfloat162_rn((v.x - mu) * inv * wv.x + bv.x,
                                               (v.y - mu) * inv * wv.y + bv.y);
    *(bf162*)(dst + 2) = __floats2bfloat162_rn((v.z - mu) * inv * wv.z + bv.z,
                                               (v.w - mu) * inv * wv.w + bv.w);
}

// ---------------- window reverse + roll + residual + LN2 ----------------
__global__ __launch_bounds__(256) void resid_ln2_kernel(const float* __restrict__ x,
                                 const float* __restrict__ Y,
                                 const float* __restrict__ w,
                                 const float* __restrict__ b,
                                 float* __restrict__ out,
                                 bf16* __restrict__ XN) {
    int t = blockIdx.x * 8 + (threadIdx.x >> 5);
    int lane = threadIdx.x & 31;
    int win = t / Nn, n = t - win * Nn;
    int bi = win >> 6, wi = win & 63;
    int hs = ((wi >> 3) * WS + n / WS + SHIFT) % Hdim;
    int ws = ((wi & 7) * WS + n % WS + SHIFT) % Wdim;
    size_t pos = ((size_t)bi * (Hdim * Wdim) + hs * Wdim + ws) * Cdim;
    float4 xv = *(const float4*)(x + pos + lane * 4);
    float4 yv = *(const float4*)(Y + (size_t)t * Cdim + lane * 4);
    float4 v;
    v.x = xv.x + yv.x; v.y = xv.y + yv.y; v.z = xv.z + yv.z; v.w = xv.w + yv.w;
    *(float4*)(out + pos + lane * 4) = v;
    float s  = v.x + v.y + v.z + v.w;
    float s2 = v.x * v.x + v.y * v.y + v.z * v.z + v.w * v.w;
    #pragma unroll
    for (int o = 16; o > 0; o >>= 1) {
        s  += __shfl_xor_sync(0xffffffffu, s, o);
        s2 += __shfl_xor_sync(0xffffffffu, s2, o);
    }
    float mu  = s * (1.0f / Cdim);
    float var = s2 * (1.0f / Cdim) - mu * mu;
    float inv = rsqrtf(var + 1e-5f);
    float4 wv = *(const float4*)(w + lane * 4);
    float4 bv = *(const float4*)(b + lane * 4);
    bf16* dst = XN + pos + lane * 4;
    *(bf162*)(dst)     = __floats2bfloat162_rn((v.x - mu) * inv * wv.x + bv.x,
                                               (v.y - mu) * inv * wv.y + bv.y);
    *(bf162*)(dst + 2) = __floats2bfloat162_rn((v.z - mu) * inv * wv.z + bv.z,
                                               (v.w - mu) * inv * wv.w + bv.w);
}

// ---------------- mma / ldmatrix helpers ----------------
__device__ __forceinline__ void mma_bf16(float* c, const uint32_t* a, uint32_t b0, uint32_t b1) {
    asm volatile("mma.sync.aligned.m16n8k16.row.col.f32.bf16.bf16.f32 "
        "{%0,%1,%2,%3}, {%4,%5,%6,%7}, {%8,%9}, {%0,%1,%2,%3};\n"
        : "+f"(c[0]), "+f"(c[1]), "+f"(c[2]), "+f"(c[3])
        : "r"(a[0]), "r"(a[1]), "r"(a[2]), "r"(a[3]), "r"(b0), "r"(b1));
}
__device__ __forceinline__ void ldsm_x4(uint32_t* r, const bf16* p) {
    uint32_t addr = (uint32_t)__cvta_generic_to_shared(p);
    asm volatile("ldmatrix.sync.aligned.m8n8.x4.shared.b16 {%0,%1,%2,%3}, [%4];\n"
        : "=r"(r[0]), "=r"(r[1]), "=r"(r[2]), "=r"(r[3]) : "r"(addr));
}
__device__ __forceinline__ void cpa16(uint32_t dst, const void* src, bool pred) {
    int sz = pred ? 16 : 0;
    asm volatile("cp.async.cg.shared.global [%0], [%1], 16, %2;\n"
                 :: "r"(dst), "l"(src), "r"(sz));
}
__device__ __forceinline__ uint32_t packbf(float a, float b) {
    bf162 t = __floats2bfloat162_rn(a, b);
    return *(uint32_t*)&t;
}

// ---------------- persistent BF16 GEMM, flattened (tile,k) cp.async pipeline ----------------
#define BM 128
#define BN 128
#define BK 32
#define GST 40
#define STG_E (BM * GST)
#define NSTG 4
#define GEMM_SMEM (NSTG * 2 * STG_E * 2)

__global__ __launch_bounds__(256, 2) void bgemm(
    const bf16* __restrict__ A, int lda,
    const bf16* __restrict__ B, int ldb,
    const float* __restrict__ bias,
    void* __restrict__ Cv, int ldc,
    int M, int N, int K,
    const float* __restrict__ gwPtr, int alphaIdx, int alphaMode, int splitM,
    int betaOne, int doGelu, int outBf16,
    bf16* __restrict__ pfx2, bf16* __restrict__ pfx1, int pfxLd) {
    extern __shared__ bf16 smem[];
    bf16* As = smem;
    bf16* Bs = smem + NSTG * STG_E;

    const int tid = threadIdx.x;
    const int bn = blockIdx.x * BN;
    const int wid = tid >> 5, lane = tid & 31;
    const int wm = (wid & 3) * 32;
    const int wn = (wid >> 2) * 64;
    const int g4 = lane >> 2, t4 = lane & 3;

    const int lrow = tid >> 2;
    const int lc = (tid & 3) * 8;
    const bf16* Bg = B + (size_t)(bn + lrow) * ldb + lc;
    const bool bval0 = (bn + lrow) < N;
    const bool bval1 = (bn + lrow + 64) < N;

    const int KI = K / BK;
    const int kiLog = (KI == 16) ? 4 : 2;
    const int kiMask = KI - 1;
    const bool resB = (KI == 4);
    const int nT = M / BM;
    const int GYm = gridDim.y;
    const int myT = (nT - (int)blockIdx.y + GYm - 1) / GYm;
    if (myT <= 0) return;
    const int G = myT * KI;

    float acc[2][8][4];

    auto tileBM = [&](int t) { return ((int)blockIdx.y + t * GYm) * BM; };

    auto issue = [&](int g) {
        int t = g >> kiLog, k = g & kiMask;
        int bm = tileBM(t);
        int st = g & 3;
        uint32_t a0 = (uint32_t)__cvta_generic_to_shared(&As[st * STG_E + lrow * GST + lc]);
        const bf16* Agp = A + (size_t)(bm + lrow) * lda + k * BK + lc;
        cpa16(a0, Agp, true);
        cpa16(a0 + 64 * GST * 2, Agp + (size_t)64 * lda, true);
        if (!resB || g < 4) {
            uint32_t b0 = (uint32_t)__cvta_generic_to_shared(&Bs[st * STG_E + lrow * GST + lc]);
            cpa16(b0, Bg + k * BK, bval0);
            cpa16(b0 + 64 * GST * 2, Bg + k * BK + (size_t)64 * ldb, bval1);
        }
        asm volatile("cp.async.commit_group;\n");
    };

    auto computeStage = [&](int st) {
        const bf16* Ab = &As[st * STG_E];
        const bf16* Bb = &Bs[st * STG_E];
        #pragma unroll
        for (int ks = 0; ks < 2; ks++) {
            const int kb = ks * 16;
            uint32_t af[2][4];
            #pragma unroll
            for (int mt = 0; mt < 2; mt++)
                ldsm_x4(af[mt], &Ab[(wm + mt * 16 + (lane & 15)) * GST + kb + ((lane >> 4) << 3)]);
            uint32_t bfm[8][2];
            #pragma unroll
            for (int nt2 = 0; nt2 < 4; nt2++) {
                uint32_t r4[4];
                ldsm_x4(r4, &Bb[(wn + nt2 * 16 + (lane & 7) + ((lane >> 4) << 3)) * GST
                                 + kb + (((lane >> 3) & 1) << 3)]);
                bfm[nt2 * 2][0] = r4[0]; bfm[nt2 * 2][1] = r4[1];
                bfm[nt2 * 2 + 1][0] = r4[2]; bfm[nt2 * 2 + 1][1] = r4[3];
            }
            #pragma unroll
            for (int nt = 0; nt < 8; nt++) {
                mma_bf16(acc[0][nt], af[0], bfm[nt][0], bfm[nt][1]);
                mma_bf16(acc[1][nt], af[1], bfm[nt][0], bfm[nt][1]);
            }
        }
    };

    auto snapshot = [&](bf16* __restrict__ P, int bm) {
        #pragma unroll
        for (int nt = 0; nt < 8; nt++) {
            int c0 = bn + wn + nt * 8 + t4 * 2;
            if (c0 >= N) continue;
            float bv0 = bias ? bias[c0] : 0.0f;
            float bv1 = bias ? bias[c0 + 1] : 0.0f;
            #pragma unroll
            for (int mt = 0; mt < 2; mt++)
                #pragma unroll
                for (int half = 0; half < 2; half++) {
                    int r = bm + wm + mt * 16 + g4 + half * 8;
                    float v0 = acc[mt][nt][half * 2 + 0] + bv0;
                    float v1 = acc[mt][nt][half * 2 + 1] + bv1;
                    if (doGelu) {
                        v0 = 0.5f * v0 * (1.0f + erff(v0 * 0.70710678118654752f));
                        v1 = 0.5f * v1 * (1.0f + erff(v1 * 0.70710678118654752f));
                    }
                    *(bf162*)(P + (size_t)(r - splitM) * pfxLd + c0)
                        = __floats2bfloat162_rn(v0, v1);
                }
        }
    };

    auto epilogue = [&](int bm) {
        float alpha = 1.0f;
        if (alphaMode == 1) alpha = __ldg(&gwPtr[alphaIdx]);
        else if (alphaMode == 2 && bm >= splitM) alpha = __ldg(&gwPtr[0]);
        #pragma unroll
        for (int nt = 0; nt < 8; nt++) {
            int c0 = bn + wn + nt * 8 + t4 * 2;
            if (c0 >= N) continue;
            float bv0 = bias ? bias[c0] : 0.0f;
            float bv1 = bias ? bias[c0 + 1] : 0.0f;
            #pragma unroll
            for (int mt = 0; mt < 2; mt++) {
                #pragma unroll
                for (int half = 0; half < 2; half++) {
                    int r = bm + wm + mt * 16 + g4 + half * 8;
                    float v0 = acc[mt][nt][half * 2 + 0] + bv0;
                    float v1 = acc[mt][nt][half * 2 + 1] + bv1;
                    if (doGelu) {
                        v0 = 0.5f * v0 * (1.0f + erff(v0 * 0.70710678118654752f));
                        v1 = 0.5f * v1 * (1.0f + erff(v1 * 0.70710678118654752f));
                    }
                    v0 *= alpha; v1 *= alpha;
                    size_t off = (size_t)r * ldc + c0;
                    if (outBf16) {
                        *(bf162*)((bf16*)Cv + off) = __floats2bfloat162_rn(v0, v1);
                    } else {
                        float* Cf = (float*)Cv;
                        if (betaOne) {
                            float2 old = *(const float2*)(Cf + off);
                            v0 += old.x; v1 += old.y;
                        }
                        *(float2*)(Cf + off) = make_float2(v0, v1);
                    }
                }
            }
        }
    };

    issue(0); issue(1); issue(2);

    #pragma unroll 1
    for (int g = 0; g < G; g++) {
        int rem = G - 1 - g;
        if (rem >= 2)      { asm volatile("cp.async.wait_group 2;\n"); }
        else if (rem == 1) { asm volatile("cp.async.wait_group 1;\n"); }
        else               { asm volatile("cp.async.wait_group 0;\n"); }
        __syncthreads();
        if (g + 3 < G) issue(g + 3);

        int t = g >> kiLog, k = g & kiMask;
        int bm = tileBM(t);
        if (k == 0) {
            #pragma unroll
            for (int i = 0; i < 2; i++)
                #pragma unroll
                for (int j = 0; j < 8; j++)
                    #pragma unroll
                    for (int q = 0; q < 4; q++) acc[i][j][q] = 0.0f;
        }
        computeStage(g & 3);
        if (pfx2 != nullptr && bm >= splitM && k <= 1)
            snapshot((k == 0) ? pfx2 : pfx1, bm);
        if (k == kiMask) epilogue(bm);
    }
}

// ---------------- FA-style window attention: 1 block/window, warp-per-head ----------------
#define AQP 136   // q/k smem row stride (bf16): 128 + 8 pad
#define VTP 72    // v^T smem row stride
#define ATTN_SMEM (2 * 64 * AQP * 2 + NHn * 32 * VTP * 2)

__global__ __launch_bounds__(128) void attn_kernel(
    const bf16* __restrict__ QKVf,
    const bf16* __restrict__ QKV1,
    const bf16* __restrict__ QKV2,
    const float* __restrict__ CB,
    bf16* __restrict__ Of,
    bf16* __restrict__ O1,
    bf16* __restrict__ O2) {
    extern __shared__ bf16 ash[];
    bf16* sq  = ash;                 // [64][AQP]
    bf16* sk  = sq + 64 * AQP;       // [64][AQP]
    bf16* svt = sk + 64 * AQP;       // [NHn][32][VTP]

    int win = blockIdx.x;
    const bf16* QKV; bf16* O; int lw;
    if (win < NWIN_TOTAL)                  { QKV = QKVf; O = Of; lw = win; }
    else if (win < NWIN_TOTAL + NWIN_HALF) { QKV = QKV1; O = O1; lw = win - NWIN_TOTAL; }
    else                                   { QKV = QKV2; O = O2; lw = win - NWIN_TOTAL - NWIN_HALF; }
    const int mi = lw & 63;

    const int tid = threadIdx.x;
    const int wid = tid >> 5, lane = tid & 31;
    const int g = lane >> 2, t4 = lane & 3;
    const int h = wid;
    const int qcol = h * HDd;

    // stage Q,K rows (full 128 cols), V transposed per head (pad m>=49 to 0)
    const bf16* base = QKV + (size_t)lw * Nn * 384;
    for (int idx = tid; idx < Nn * 16; idx += 128) {
        int n = idx >> 4, c8 = (idx & 15) << 3;
        *(uint4*)&sq[n * AQP + c8] = *(const uint4*)(base + n * 384 + c8);
        *(uint4*)&sk[n * AQP + c8] = *(const uint4*)(base + n * 384 + 128 + c8);
    }
    {
        const bf16* vb = base + 256 + qcol + lane;
        bf16* dst = svt + (h * 32 + lane) * VTP;
        #pragma unroll 4
        for (int m = 0; m < 64; m++)
            dst[m] = (m < Nn) ? vb[(size_t)m * 384] : __float2bfloat16(0.0f);
    }
    __syncthreads();

    const float* cb = CB + ((size_t)mi * NHn + h) * (Nn * Nn);

    // K fragments: [ks][nt2][4]
    uint32_t kf[2][4][4];
    #pragma unroll
    for (int ks = 0; ks < 2; ks++)
        #pragma unroll
        for (int nt2 = 0; nt2 < 4; nt2++)
            ldsm_x4(kf[ks][nt2], &sk[(nt2 * 16 + (lane & 7) + ((lane >> 4) << 3)) * AQP
                                      + qcol + ks * 16 + (((lane >> 3) & 1) << 3)]);
    // V^T fragments: [kt][nv][4]
    uint32_t vf[4][2][4];
    #pragma unroll
    for (int kt = 0; kt < 4; kt++)
        #pragma unroll
        for (int nv = 0; nv < 2; nv++)
            ldsm_x4(vf[kt][nv], &svt[(h * 32 + nv * 16 + (lane & 7) + ((lane >> 4) << 3)) * VTP
                                      + kt * 16 + (((lane >> 3) & 1) << 3)]);

    #pragma unroll
    for (int mt = 0; mt < 4; mt++) {
        // Q fragments for this 16-row tile
        uint32_t qa[2][4];
        #pragma unroll
        for (int ks = 0; ks < 2; ks++)
            ldsm_x4(qa[ks], &sq[(mt * 16 + (lane & 15)) * AQP + qcol + ks * 16 + ((lane >> 4) << 3)]);

        // S = Q K^T
        float acc[7][4];
        #pragma unroll
        for (int nt = 0; nt < 7; nt++)
            #pragma unroll
            for (int q = 0; q < 4; q++) acc[nt][q] = 0.0f;
        #pragma unroll
        for (int ks = 0; ks < 2; ks++)
            #pragma unroll
            for (int nt = 0; nt < 7; nt++)
                mma_bf16(acc[nt], qa[ks], kf[ks][nt >> 1][(nt & 1) * 2], kf[ks][nt >> 1][(nt & 1) * 2 + 1]);

        const int r0 = mt * 16 + g, r1 = r0 + 8;
        // scale + bias/mask; kill garbage rows/cols
        #pragma unroll
        for (int nt = 0; nt < 7; nt++) {
            int c0 = nt * 8 + t4 * 2;
            acc[nt][0] = (c0 < Nn)     ? ((r0 < Nn) ? acc[nt][0] * SCALE + __ldg(&cb[r0 * Nn + c0])     : 0.0f) : -1e30f;
            acc[nt][1] = (c0 + 1 < Nn) ? ((r0 < Nn) ? acc[nt][1] * SCALE + __ldg(&cb[r0 * Nn + c0 + 1]) : 0.0f) : -1e30f;
            acc[nt][2] = (c0 < Nn)     ? ((r1 < Nn) ? acc[nt][2] * SCALE + __ldg(&cb[r1 * Nn + c0])     : 0.0f) : -1e30f;
            acc[nt][3] = (c0 + 1 < Nn) ? ((r1 < Nn) ? acc[nt][3] * SCALE + __ldg(&cb[r1 * Nn + c0 + 1]) : 0.0f) : -1e30f;
        }

        // in-register softmax (rows r0, r1); row spread over quad lanes
        float mx0 = -1e30f, mx1 = -1e30f;
        #pragma unroll
        for (int nt = 0; nt < 7; nt++) {
            mx0 = fmaxf(mx0, fmaxf(acc[nt][0], acc[nt][1]));
            mx1 = fmaxf(mx1, fmaxf(acc[nt][2], acc[nt][3]));
        }
        mx0 = fmaxf(mx0, __shfl_xor_sync(0xffffffffu, mx0, 1));
        mx0 = fmaxf(mx0, __shfl_xor_sync(0xffffffffu, mx0, 2));
        mx1 = fmaxf(mx1, __shfl_xor_sync(0xffffffffu, mx1, 1));
        mx1 = fmaxf(mx1, __shfl_xor_sync(0xffffffffu, mx1, 2));
        float s0 = 0.0f, s1 = 0.0f;
        #pragma unroll
        for (int nt = 0; nt < 7; nt++) {
            acc[nt][0] = __expf(acc[nt][0] - mx0); s0 += acc[nt][0];
            acc[nt][1] = __expf(acc[nt][1] - mx0); s0 += acc[nt][1];
            acc[nt][2] = __expf(acc[nt][2] - mx1); s1 += acc[nt][2];
            acc[nt][3] = __expf(acc[nt][3] - mx1); s1 += acc[nt][3];
        }
        s0 += __shfl_xor_sync(0xffffffffu, s0, 1);
        s0 += __shfl_xor_sync(0xffffffffu, s0, 2);
        s1 += __shfl_xor_sync(0xffffffffu, s1, 1);
        s1 += __shfl_xor_sync(0xffffffffu, s1, 2);
        float rs0 = 1.0f / s0, rs1 = 1.0f / s1;

        // pack P accumulator frags directly into A frags (C-frag == A-frag layout)
        uint32_t pf[4][4];
        #pragma unroll
        for (int kt = 0; kt < 4; kt++) {
            int n0 = 2 * kt, n1 = 2 * kt + 1;
            pf[kt][0] = packbf(acc[n0][0] * rs0, acc[n0][1] * rs0);
            pf[kt][1] = packbf(acc[n0][2] * rs1, acc[n0][3] * rs1);
            if (n1 < 7) {
                pf[kt][2] = packbf(acc[n1][0] * rs0, acc[n1][1] * rs0);
                pf[kt][3] = packbf(acc[n1][2] * rs1, acc[n1][3] * rs1);
            } else {
                pf[kt][2] = 0u; pf[kt][3] = 0u;
            }
        }

        // O = P V
        float oacc[4][4];
        #pragma unroll
        for (int nt = 0; nt < 4; nt++)
            #pragma unroll
            for (int q = 0; q < 4; q++) oacc[nt][q] = 0.0f;
        #pragma unroll
        for (int kt = 0; kt < 4; kt++)
            #pragma unroll
            for (int nt = 0; nt < 4; nt++)
                mma_bf16(oacc[nt], pf[kt], vf[kt][nt >> 1][(nt & 1) * 2], vf[kt][nt >> 1][(nt & 1) * 2 + 1]);

        #pragma unroll
        for (int nt = 0; nt < 4; nt++) {
            int c = nt * 8 + t4 * 2;
            if (r0 < Nn)
                *(bf162*)(O + ((size_t)(lw * Nn + r0)) * Cdim + qcol + c)
                    = __floats2bfloat162_rn(oacc[nt][0], oacc[nt][1]);
            if (r1 < Nn)
                *(bf162*)(O + ((size_t)(lw * Nn + r1)) * Cdim + qcol + c)
                    = __floats2bfloat162_rn(oacc[nt][2], oacc[nt][3]);
        }
    }
}

// ---------------- host helpers ----------------
static inline void launch_gemm(const bf16* A, int lda, const bf16* B, int ldb,
                               const float* bias, void* C, int ldc,
                               int M, int N, int K,
                               const float* gwP, int ai, int aMode, int splitM,
                               int betaOne, int gelu, int outBf16,
                               bf16* pfx2 = nullptr, bf16* pfx1 = nullptr, int pfxLd = 0) {
    int nbn = (N + BN - 1) / BN;
    int nT = M / BM;
    int gy = 296 / nbn;
    if (gy > nT) gy = nT;
    if (gy < 1) gy = 1;
    dim3 grid(nbn, gy);
    bgemm<<<grid, 256, GEMM_SMEM>>>(A, lda, B, ldb, bias, C, ldc, M, N, K,
                                    gwP, ai, aMode, splitM, betaOne, gelu, outBf16,
                                    pfx2, pfx1, pfxLd);
}

extern "C" void kernel_launch(void* const* d_in, const int* in_sizes, int n_in,
                              void* d_out, int out_size) {
    const float* x     = (const float*)d_in[0];
    const float* gw    = (const float*)d_in[1];
    const float* n1w   = (const float*)d_in[2];
    const float* n1b   = (const float*)d_in[3];
    const float* qkvw  = (const float*)d_in[4];
    const float* qkvb  = (const float*)d_in[5];
    const float* rbt   = (const float*)d_in[6];
    const float* projw = (const float*)d_in[7];
    const float* projb = (const float*)d_in[8];
    const float* amask = (const float*)d_in[9];
    const float* n2w   = (const float*)d_in[10];
    const float* n2b   = (const float*)d_in[11];
    const float* f1w   = (const float*)d_in[12];
    const float* f1b   = (const float*)d_in[13];
    const float* f2w   = (const float*)d_in[14];
    const float* f2b   = (const float*)d_in[15];
    const int*   relIdx= (const int*)d_in[16];
    float* out = (float*)d_out;

    cudaFuncSetAttribute(bgemm, cudaFuncAttributeMaxDynamicSharedMemorySize, GEMM_SMEM);
    cudaFuncSetAttribute(attn_kernel, cudaFuncAttributeMaxDynamicSharedMemorySize, ATTN_SMEM);

    bf16 *XW, *QKVf, *QKV1, *QKV2, *O, *Oh1, *Oh2, *XN, *Hb, *H1, *H2, *Wb;
    float *Y, *CB;
    cudaGetSymbolAddress((void**)&XW,   g_XW);
    cudaGetSymbolAddress((void**)&QKVf, g_QKVf);
    cudaGetSymbolAddress((void**)&QKV1, g_QKV1);
    cudaGetSymbolAddress((void**)&QKV2, g_QKV2);
    cudaGetSymbolAddress((void**)&O,    g_O);
    cudaGetSymbolAddress((void**)&Oh1,  g_Oh1);
    cudaGetSymbolAddress((void**)&Oh2,  g_Oh2);
    cudaGetSymbolAddress((void**)&Y,    g_Y);
    cudaGetSymbolAddress((void**)&XN,   g_XN);
    cudaGetSymbolAddress((void**)&Hb,   g_H);
    cudaGetSymbolAddress((void**)&H1,   g_H1);
    cudaGetSymbolAddress((void**)&H2,   g_H2);
    cudaGetSymbolAddress((void**)&CB,   g_CB);
    cudaGetSymbolAddress((void**)&Wb,   g_Wb);

    const bf16* qkvwB = Wb;
    const bf16* projwB = Wb + 49152;
    const bf16* f1wB = Wb + 65536;
    const bf16* f2wB = Wb + 131072;

    const int Mh = TOK_HALF;
    const int Mf = TOK_TOTAL;

    // fused prep: weight cast + bias table + LN1/partition
    prep_kernel<<<PREP_W + PREP_B + PREP_LN, 256>>>(
        qkvw, projw, f1w, f2w, Wb, rbt, relIdx, amask, CB, x, n1w, n1b, XW);

    // QKV merged: full (K=128) + prefix K=64 -> QKV1, K=32 -> QKV2
    launch_gemm(XW, Cdim, qkvwB, Cdim, qkvb, QKVf, 384, Mf, 384, 128,
                nullptr, 0, 0, Mh, 0, 0, 1, QKV2, QKV1, 384);

    // attention: all variants, 1 block/window, warp-per-head
    attn_kernel<<<NWIN_TOTAL + 2 * NWIN_HALF, 128, ATTN_SMEM>>>(
        QKVf, QKV1, QKV2, CB, O, Oh1, Oh2);

    // proj
    launch_gemm(O, Cdim, projwB, Cdim, projb, Y, Cdim, Mf, 128, 128, gw, 0, 2, Mh, 0, 0, 0);
    launch_gemm(Oh1, Cdim, projwB, Cdim, projb, Y + (size_t)Mh * Cdim, Cdim, Mh, 64, 128, gw, 1, 1, 0, 1, 0, 0);
    launch_gemm(Oh2, Cdim, projwB, Cdim, projb, Y + (size_t)Mh * Cdim, Cdim, Mh, 32, 128, gw, 2, 1, 0, 1, 0, 0);

    // residual + LN2
    resid_ln2_kernel<<<TOK_TOTAL / 8, 256>>>(x, Y, n2w, n2b, out, XN);

    // FC1 merged: H (K=128) + H1 (K=64) + H2 (K=32), GELU on all
    launch_gemm(XN, Cdim, f1wB, Cdim, f1b, Hb, HID, Mf, HID, 128,
                nullptr, 0, 0, Mh, 0, 1, 1, H2, H1, HID);

    // FC2
    launch_gemm(Hb, HID, f2wB, HID, f2b, out, Cdim, Mf, 128, 512, gw, 0, 2, Mh, 1, 0, 0);
    launch_gemm(H1, HID, f2wB, HID, f2b, out + (size_t)Mh * Cdim, Cdim, Mh, 64, 512, gw, 1, 1, 0, 1, 0, 0);
    launch_gemm(H2, HID, f2wB, HID, f2b, out + (size_t)Mh * Cdim, Cdim, Mh, 32, 512, gw, 2, 1, 0, 1, 0, 0);
}

// round 10
// speedup vs baseline: 5.5248x; 1.0127x over previous
#include <cuda_runtime.h>
#include <cuda_bf16.h>
#include <cstdint>
#include <cstddef>
#include <math.h>

// ---------------- problem constants ----------------
#define Bimg 64
#define Hdim 56
#define Wdim 56
#define WS 7
#define SHIFT 3
#define Cdim 128
#define NHn 4
#define HDd 32
#define Nn 49
#define NWn 64
#define HID 512
#define SCALE 0.17677669529663688f

#define NWIN_TOTAL (Bimg * NWn)          // 4096
#define NWIN_HALF  (NWIN_TOTAL / 2)      // 2048
#define TOK_TOTAL  (NWIN_TOTAL * Nn)     // 200704
#define TOK_HALF   (NWIN_HALF * Nn)      // 100352

typedef __nv_bfloat16 bf16;
typedef __nv_bfloat162 bf162;

// ---------------- scratch (device globals) ----------------
__device__ bf16  g_XW  [(size_t)TOK_TOTAL * Cdim];
__device__ bf16  g_QKVf[(size_t)TOK_TOTAL * 384];
__device__ bf16  g_QKV1[(size_t)TOK_HALF  * 384];
__device__ bf16  g_QKV2[(size_t)TOK_HALF  * 384];
__device__ bf16  g_O   [(size_t)TOK_TOTAL * Cdim];
__device__ bf16  g_Oh1 [(size_t)TOK_HALF  * Cdim];
__device__ bf16  g_Oh2 [(size_t)TOK_HALF  * Cdim];
__device__ bf16  g_XN  [(size_t)TOK_TOTAL * Cdim];
__device__ float g_CB  [(size_t)NWn * NHn * Nn * Nn];
__device__ bf16  g_Wb  [196608];   // bf16 weights: qkvw|projw|f1w|f2w

// ---------------- fused prep: weights->bf16, bias+mask, LN1+roll+partition ----------------
#define PREP_W 192
#define PREP_B 256
#define PREP_LN (TOK_TOTAL / 8)
__global__ __launch_bounds__(256) void prep_kernel(
    const float* __restrict__ qkvw, const float* __restrict__ projw,
    const float* __restrict__ f1w, const float* __restrict__ f2w,
    bf16* __restrict__ Wb,
    const float* __restrict__ rbt, const int* __restrict__ relIdx,
    const float* __restrict__ mask, float* __restrict__ CB,
    const float* __restrict__ x, const float* __restrict__ n1w,
    const float* __restrict__ n1b, bf16* __restrict__ XW) {
    int bid = blockIdx.x;
    if (bid < PREP_W) {
        int i = (bid * 256 + threadIdx.x) * 4;
        const float* src; int off;
        if (i < 49152)       { src = qkvw;  off = i; }
        else if (i < 65536)  { src = projw; off = i - 49152; }
        else if (i < 131072) { src = f1w;   off = i - 65536; }
        else                 { src = f2w;   off = i - 131072; }
        float4 v = *(const float4*)(src + off);
        *(bf162*)(Wb + i)     = __floats2bfloat162_rn(v.x, v.y);
        *(bf162*)(Wb + i + 2) = __floats2bfloat162_rn(v.z, v.w);
        return;
    }
    if (bid < PREP_W + PREP_B) {
        int b = bid - PREP_W;
        int mi = b >> 2, h = b & 3;
        float* dst = CB + ((size_t)mi * NHn + h) * (Nn * Nn);
        const float* msk = mask + (size_t)mi * (Nn * Nn);
        for (int idx = threadIdx.x; idx < Nn * Nn; idx += 256)
            dst[idx] = __ldg(&rbt[relIdx[idx] * NHn + h]) + msk[idx];
        return;
    }
    int t = (bid - PREP_W - PREP_B) * 8 + (threadIdx.x >> 5);
    int lane = threadIdx.x & 31;
    int win = t / Nn, n = t - win * Nn;
    int bi = win >> 6, wi = win & 63;
    int hs = ((wi >> 3) * WS + n / WS + SHIFT) % Hdim;
    int ws = ((wi & 7) * WS + n % WS + SHIFT) % Wdim;
    const float* xp = x + ((size_t)bi * (Hdim * Wdim) + hs * Wdim + ws) * Cdim;
    float4 v = *(const float4*)(xp + lane * 4);
    float s  = v.x + v.y + v.z + v.w;
    float s2 = v.x * v.x + v.y * v.y + v.z * v.z + v.w * v.w;
    #pragma unroll
    for (int o = 16; o > 0; o >>= 1) {
        s  += __shfl_xor_sync(0xffffffffu, s, o);
        s2 += __shfl_xor_sync(0xffffffffu, s2, o);
    }
    float mu  = s * (1.0f / Cdim);
    float var = s2 * (1.0f / Cdim) - mu * mu;
    float inv = rsqrtf(var + 1e-5f);
    float4 wv = *(const float4*)(n1w + lane * 4);
    float4 bv = *(const float4*)(n1b + lane * 4);
    bf16* dst = XW + (size_t)t * Cdim + lane * 4;
    *(bf162*)(dst)     = __floats2bfloat162_rn((v.x - mu) * inv * wv.x + bv.x,
                                               (v.y - mu) * inv * wv.y + bv.y);
    *(bf162*)(dst + 2) = __floats2bfloat162_rn((v.z - mu) * inv * wv.z + bv.z,
                                               (v.w - mu) * inv * wv.w + bv.w);
}

// ---------------- LN2 (image layout, out holds residual already) ----------------
__global__ __launch_bounds__(256) void ln2_kernel(const float* __restrict__ out,
                                                  const float* __restrict__ w,
                                                  const float* __restrict__ b,
                                                  bf16* __restrict__ XN) {
    int t = blockIdx.x * 8 + (threadIdx.x >> 5);
    int lane = threadIdx.x & 31;
    float4 v = *(const float4*)(out + (size_t)t * Cdim + lane * 4);
    float s  = v.x + v.y + v.z + v.w;
    float s2 = v.x * v.x + v.y * v.y + v.z * v.z + v.w * v.w;
    #pragma unroll
    for (int o = 16; o > 0; o >>= 1) {
        s  += __shfl_xor_sync(0xffffffffu, s, o);
        s2 += __shfl_xor_sync(0xffffffffu, s2, o);
    }
    float mu  = s * (1.0f / Cdim);
    float var = s2 * (1.0f / Cdim) - mu * mu;
    float inv = rsqrtf(var + 1e-5f);
    float4 wv = *(const float4*)(w + lane * 4);
    float4 bv = *(const float4*)(b + lane * 4);
    bf16* dst = XN + (size_t)t * Cdim + lane * 4;
    *(bf162*)(dst)     = __floats2bfloat162_rn((v.x - mu) * inv * wv.x + bv.x,
                                               (v.y - mu) * inv * wv.y + bv.y);
    *(bf162*)(dst + 2) = __floats2bfloat162_rn((v.z - mu) * inv * wv.z + bv.z,
                                               (v.w - mu) * inv * wv.w + bv.w);
}

// ---------------- mma / ldmatrix helpers ----------------
__device__ __forceinline__ void mma_bf16(float* c, const uint32_t* a, uint32_t b0, uint32_t b1) {
    asm volatile("mma.sync.aligned.m16n8k16.row.col.f32.bf16.bf16.f32 "
        "{%0,%1,%2,%3}, {%4,%5,%6,%7}, {%8,%9}, {%0,%1,%2,%3};\n"
        : "+f"(c[0]), "+f"(c[1]), "+f"(c[2]), "+f"(c[3])
        : "r"(a[0]), "r"(a[1]), "r"(a[2]), "r"(a[3]), "r"(b0), "r"(b1));
}
__device__ __forceinline__ void ldsm_x4(uint32_t* r, const bf16* p) {
    uint32_t addr = (uint32_t)__cvta_generic_to_shared(p);
    asm volatile("ldmatrix.sync.aligned.m8n8.x4.shared.b16 {%0,%1,%2,%3}, [%4];\n"
        : "=r"(r[0]), "=r"(r[1]), "=r"(r[2]), "=r"(r[3]) : "r"(addr));
}
__device__ __forceinline__ void cpa16(uint32_t dst, const void* src, bool pred) {
    int sz = pred ? 16 : 0;
    asm volatile("cp.async.cg.shared.global [%0], [%1], 16, %2;\n"
                 :: "r"(dst), "l"(src), "r"(sz));
}
__device__ __forceinline__ uint32_t packbf(float a, float b) {
    bf162 t = __floats2bfloat162_rn(a, b);
    return *(uint32_t*)&t;
}
__device__ __forceinline__ float gelu_f(float v) {
    return 0.5f * v * (1.0f + erff(v * 0.70710678118654752f));
}
// window-token row -> image-layout float offset
__device__ __forceinline__ size_t perm_pos(int r) {
    int win = r / Nn, n = r - win * Nn;
    int bi = win >> 6, wi = win & 63;
    int hs = ((wi >> 3) * WS + n / WS + SHIFT) % Hdim;
    int ws = ((wi & 7) * WS + n % WS + SHIFT) % Wdim;
    return ((size_t)bi * (Hdim * Wdim) + hs * Wdim + ws) * Cdim;
}

// ---------------- persistent BF16 GEMM (QKV + proj) ----------------
#define BM 128
#define BN 128
#define BK 32
#define GST 40
#define STG_E (BM * GST)
#define NSTG 4
#define GEMM_SMEM (NSTG * 2 * STG_E * 2)

__global__ __launch_bounds__(256, 2) void bgemm(
    const bf16* __restrict__ A, int lda,
    const bf16* __restrict__ B, int ldb,
    const float* __restrict__ bias,
    void* __restrict__ Cv, int ldc,
    int M, int N, int K,
    const float* __restrict__ gwPtr, int alphaIdx, int alphaMode, int splitM,
    int outBf16,
    bf16* __restrict__ pfx2, bf16* __restrict__ pfx1, int pfxLd,
    const float* __restrict__ xres, int permMode, int rowOffset) {
    extern __shared__ bf16 smem[];
    bf16* As = smem;
    bf16* Bs = smem + NSTG * STG_E;

    const int tid = threadIdx.x;
    const int bn = blockIdx.x * BN;
    const int wid = tid >> 5, lane = tid & 31;
    const int wm = (wid & 3) * 32;
    const int wn = (wid >> 2) * 64;
    const int g4 = lane >> 2, t4 = lane & 3;

    const int lrow = tid >> 2;
    const int lc = (tid & 3) * 8;
    const bf16* Bg = B + (size_t)(bn + lrow) * ldb + lc;
    const bool bval0 = (bn + lrow) < N;
    const bool bval1 = (bn + lrow + 64) < N;

    const int KI = K / BK;
    const int kiLog = (KI == 16) ? 4 : 2;
    const int kiMask = KI - 1;
    const bool resB = (KI == 4);
    const int nT = M / BM;
    const int GYm = gridDim.y;
    const int myT = (nT - (int)blockIdx.y + GYm - 1) / GYm;
    if (myT <= 0) return;
    const int G = myT * KI;

    float acc[2][8][4];

    auto tileBM = [&](int t) { return ((int)blockIdx.y + t * GYm) * BM; };

    auto issue = [&](int g) {
        int t = g >> kiLog, k = g & kiMask;
        int bm = tileBM(t);
        int st = g & 3;
        uint32_t a0 = (uint32_t)__cvta_generic_to_shared(&As[st * STG_E + lrow * GST + lc]);
        const bf16* Agp = A + (size_t)(bm + lrow) * lda + k * BK + lc;
        cpa16(a0, Agp, true);
        cpa16(a0 + 64 * GST * 2, Agp + (size_t)64 * lda, true);
        if (!resB || g < 4) {
            uint32_t b0 = (uint32_t)__cvta_generic_to_shared(&Bs[st * STG_E + lrow * GST + lc]);
            cpa16(b0, Bg + k * BK, bval0);
            cpa16(b0 + 64 * GST * 2, Bg + k * BK + (size_t)64 * ldb, bval1);
        }
        asm volatile("cp.async.commit_group;\n");
    };

    auto computeStage = [&](int st) {
        const bf16* Ab = &As[st * STG_E];
        const bf16* Bb = &Bs[st * STG_E];
        #pragma unroll
        for (int ks = 0; ks < 2; ks++) {
            const int kb = ks * 16;
            uint32_t af[2][4];
            #pragma unroll
            for (int mt = 0; mt < 2; mt++)
                ldsm_x4(af[mt], &Ab[(wm + mt * 16 + (lane & 15)) * GST + kb + ((lane >> 4) << 3)]);
            uint32_t bfm[8][2];
            #pragma unroll
            for (int nt2 = 0; nt2 < 4; nt2++) {
                uint32_t r4[4];
                ldsm_x4(r4, &Bb[(wn + nt2 * 16 + (lane & 7) + ((lane >> 4) << 3)) * GST
                                 + kb + (((lane >> 3) & 1) << 3)]);
                bfm[nt2 * 2][0] = r4[0]; bfm[nt2 * 2][1] = r4[1];
                bfm[nt2 * 2 + 1][0] = r4[2]; bfm[nt2 * 2 + 1][1] = r4[3];
            }
            #pragma unroll
            for (int nt = 0; nt < 8; nt++) {
                mma_bf16(acc[0][nt], af[0], bfm[nt][0], bfm[nt][1]);
                mma_bf16(acc[1][nt], af[1], bfm[nt][0], bfm[nt][1]);
            }
        }
    };

    auto snapshot = [&](bf16* __restrict__ P, int bm) {
        #pragma unroll
        for (int nt = 0; nt < 8; nt++) {
            int c0 = bn + wn + nt * 8 + t4 * 2;
            if (c0 >= N) continue;
            float bv0 = bias ? bias[c0] : 0.0f;
            float bv1 = bias ? bias[c0 + 1] : 0.0f;
            #pragma unroll
            for (int mt = 0; mt < 2; mt++)
                #pragma unroll
                for (int half = 0; half < 2; half++) {
                    int r = bm + wm + mt * 16 + g4 + half * 8;
                    float v0 = acc[mt][nt][half * 2 + 0] + bv0;
                    float v1 = acc[mt][nt][half * 2 + 1] + bv1;
                    *(bf162*)(P + (size_t)(r - splitM) * pfxLd + c0)
                        = __floats2bfloat162_rn(v0, v1);
                }
        }
    };

    auto epilogue = [&](int bm) {
        float alpha = 1.0f;
        if (alphaMode == 1) alpha = __ldg(&gwPtr[alphaIdx]);
        else if (alphaMode == 2 && bm >= splitM) alpha = __ldg(&gwPtr[0]);
        size_t pos[2][2];
        if (permMode) {
            #pragma unroll
            for (int mt = 0; mt < 2; mt++)
                #pragma unroll
                for (int half = 0; half < 2; half++)
                    pos[mt][half] = perm_pos(rowOffset + bm + wm + mt * 16 + g4 + half * 8);
        }
        #pragma unroll
        for (int nt = 0; nt < 8; nt++) {
            int c0 = bn + wn + nt * 8 + t4 * 2;
            if (c0 >= N) continue;
            float bv0 = bias ? bias[c0] : 0.0f;
            float bv1 = bias ? bias[c0 + 1] : 0.0f;
            #pragma unroll
            for (int mt = 0; mt < 2; mt++) {
                #pragma unroll
                for (int half = 0; half < 2; half++) {
                    int r = bm + wm + mt * 16 + g4 + half * 8;
                    float v0 = (acc[mt][nt][half * 2 + 0] + bv0) * alpha;
                    float v1 = (acc[mt][nt][half * 2 + 1] + bv1) * alpha;
                    if (permMode) {
                        size_t off = pos[mt][half] + c0;
                        float* Cf = (float*)Cv;
                        if (permMode == 1) {
                            float2 xv = *(const float2*)(xres + off);
                            v0 += xv.x; v1 += xv.y;
                        } else {
                            float2 old = *(const float2*)(Cf + off);
                            v0 += old.x; v1 += old.y;
                        }
                        *(float2*)(Cf + off) = make_float2(v0, v1);
                    } else {
                        size_t off = (size_t)r * ldc + c0;
                        *(bf162*)((bf16*)Cv + off) = __floats2bfloat162_rn(v0, v1);
                    }
                }
            }
        }
    };

    issue(0); issue(1); issue(2);

    #pragma unroll 1
    for (int g = 0; g < G; g++) {
        int rem = G - 1 - g;
        if (rem >= 2)      { asm volatile("cp.async.wait_group 2;\n"); }
        else if (rem == 1) { asm volatile("cp.async.wait_group 1;\n"); }
        else               { asm volatile("cp.async.wait_group 0;\n"); }
        __syncthreads();
        if (g + 3 < G) issue(g + 3);

        int t = g >> kiLog, k = g & kiMask;
        int bm = tileBM(t);
        if (k == 0) {
            #pragma unroll
            for (int i = 0; i < 2; i++)
                #pragma unroll
                for (int j = 0; j < 8; j++)
                    #pragma unroll
                    for (int q = 0; q < 4; q++) acc[i][j][q] = 0.0f;
        }
        computeStage(g & 3);
        if (pfx2 != nullptr && bm >= splitM && k <= 1)
            snapshot((k == 0) ? pfx2 : pfx1, bm);
        if (k == kiMask) epilogue(bm);
    }
}

// ---------------- FA-style window attention: 1 block/window, warp-per-head ----------------
#define AQP 136
#define VTP 72
#define ATTN_SMEM (2 * 64 * AQP * 2 + NHn * 32 * VTP * 2)

__global__ __launch_bounds__(128) void attn_kernel(
    const bf16* __restrict__ QKVf,
    const bf16* __restrict__ QKV1,
    const bf16* __restrict__ QKV2,
    const float* __restrict__ CB,
    bf16* __restrict__ Of,
    bf16* __restrict__ O1,
    bf16* __restrict__ O2) {
    extern __shared__ bf16 ash[];
    bf16* sq  = ash;
    bf16* sk  = sq + 64 * AQP;
    bf16* svt = sk + 64 * AQP;

    int win = blockIdx.x;
    const bf16* QKV; bf16* O; int lw;
    if (win < NWIN_TOTAL)                  { QKV = QKVf; O = Of; lw = win; }
    else if (win < NWIN_TOTAL + NWIN_HALF) { QKV = QKV1; O = O1; lw = win - NWIN_TOTAL; }
    else                                   { QKV = QKV2; O = O2; lw = win - NWIN_TOTAL - NWIN_HALF; }
    const int mi = lw & 63;

    const int tid = threadIdx.x;
    const int wid = tid >> 5, lane = tid & 31;
    const int g = lane >> 2, t4 = lane & 3;
    const int h = wid;
    const int qcol = h * HDd;

    const bf16* base = QKV + (size_t)lw * Nn * 384;
    for (int idx = tid; idx < Nn * 16; idx += 128) {
        int n = idx >> 4, c8 = (idx & 15) << 3;
        *(uint4*)&sq[n * AQP + c8] = *(const uint4*)(base + n * 384 + c8);
        *(uint4*)&sk[n * AQP + c8] = *(const uint4*)(base + n * 384 + 128 + c8);
    }
    {
        const bf16* vb = base + 256 + qcol + lane;
        bf16* dst = svt + (h * 32 + lane) * VTP;
        #pragma unroll 4
        for (int m = 0; m < 64; m++)
            dst[m] = (m < Nn) ? vb[(size_t)m * 384] : __float2bfloat16(0.0f);
    }
    __syncthreads();

    const float* cb = CB + ((size_t)mi * NHn + h) * (Nn * Nn);

    uint32_t kf[2][4][4];
    #pragma unroll
    for (int ks = 0; ks < 2; ks++)
        #pragma unroll
        for (int nt2 = 0; nt2 < 4; nt2++)
            ldsm_x4(kf[ks][nt2], &sk[(nt2 * 16 + (lane & 7) + ((lane >> 4) << 3)) * AQP
                                      + qcol + ks * 16 + (((lane >> 3) & 1) << 3)]);
    uint32_t vf[4][2][4];
    #pragma unroll
    for (int kt = 0; kt < 4; kt++)
        #pragma unroll
        for (int nv = 0; nv < 2; nv++)
            ldsm_x4(vf[kt][nv], &svt[(h * 32 + nv * 16 + (lane & 7) + ((lane >> 4) << 3)) * VTP
                                      + kt * 16 + (((lane >> 3) & 1) << 3)]);

    #pragma unroll
    for (int mt = 0; mt < 4; mt++) {
        uint32_t qa[2][4];
        #pragma unroll
        for (int ks = 0; ks < 2; ks++)
            ldsm_x4(qa[ks], &sq[(mt * 16 + (lane & 15)) * AQP + qcol + ks * 16 + ((lane >> 4) << 3)]);

        float acc[7][4];
        #pragma unroll
        for (int nt = 0; nt < 7; nt++)
            #pragma unroll
            for (int q = 0; q < 4; q++) acc[nt][q] = 0.0f;
        #pragma unroll
        for (int ks = 0; ks < 2; ks++)
            #pragma unroll
            for (int nt = 0; nt < 7; nt++)
                mma_bf16(acc[nt], qa[ks], kf[ks][nt >> 1][(nt & 1) * 2], kf[ks][nt >> 1][(nt & 1) * 2 + 1]);

        const int r0 = mt * 16 + g, r1 = r0 + 8;
        #pragma unroll
        for (int nt = 0; nt < 7; nt++) {
            int c0 = nt * 8 + t4 * 2;
            acc[nt][0] = (c0 < Nn)     ? ((r0 < Nn) ? acc[nt][0] * SCALE + __ldg(&cb[r0 * Nn + c0])     : 0.0f) : -1e30f;
            acc[nt][1] = (c0 + 1 < Nn) ? ((r0 < Nn) ? acc[nt][1] * SCALE + __ldg(&cb[r0 * Nn + c0 + 1]) : 0.0f) : -1e30f;
            acc[nt][2] = (c0 < Nn)     ? ((r1 < Nn) ? acc[nt][2] * SCALE + __ldg(&cb[r1 * Nn + c0])     : 0.0f) : -1e30f;
            acc[nt][3] = (c0 + 1 < Nn) ? ((r1 < Nn) ? acc[nt][3] * SCALE + __ldg(&cb[r1 * Nn + c0 + 1]) : 0.0f) : -1e30f;
        }

        float mx0 = -1e30f, mx1 = -1e30f;
        #pragma unroll
        for (int nt = 0; nt < 7; nt++) {
            mx0 = fmaxf(mx0, fmaxf(acc[nt][0], acc[nt][1]));
            mx1 = fmaxf(mx1, fmaxf(acc[nt][2], acc[nt][3]));
        }
        mx0 = fmaxf(mx0, __shfl_xor_sync(0xffffffffu, mx0, 1));
        mx0 = fmaxf(mx0, __shfl_xor_sync(0xffffffffu, mx0, 2));
        mx1 = fmaxf(mx1, __shfl_xor_sync(0xffffffffu, mx1, 1));
        mx1 = fmaxf(mx1, __shfl_xor_sync(0xffffffffu, mx1, 2));
        float s0 = 0.0f, s1 = 0.0f;
        #pragma unroll
        for (int nt = 0; nt < 7; nt++) {
            acc[nt][0] = __expf(acc[nt][0] - mx0); s0 += acc[nt][0];
            acc[nt][1] = __expf(acc[nt][1] - mx0); s0 += acc[nt][1];
            acc[nt][2] = __expf(acc[nt][2] - mx1); s1 += acc[nt][2];
            acc[nt][3] = __expf(acc[nt][3] - mx1); s1 += acc[nt][3];
        }
        s0 += __shfl_xor_sync(0xffffffffu, s0, 1);
        s0 += __shfl_xor_sync(0xffffffffu, s0, 2);
        s1 += __shfl_xor_sync(0xffffffffu, s1, 1);
        s1 += __shfl_xor_sync(0xffffffffu, s1, 2);
        float rs0 = 1.0f / s0, rs1 = 1.0f / s1;

        uint32_t pf[4][4];
        #pragma unroll
        for (int kt = 0; kt < 4; kt++) {
            int n0 = 2 * kt, n1 = 2 * kt + 1;
            pf[kt][0] = packbf(acc[n0][0] * rs0, acc[n0][1] * rs0);
            pf[kt][1] = packbf(acc[n0][2] * rs1, acc[n0][3] * rs1);
            if (n1 < 7) {
                pf[kt][2] = packbf(acc[n1][0] * rs0, acc[n1][1] * rs0);
                pf[kt][3] = packbf(acc[n1][2] * rs1, acc[n1][3] * rs1);
            } else {
                pf[kt][2] = 0u; pf[kt][3] = 0u;
            }
        }

        float oacc[4][4];
        #pragma unroll
        for (int nt = 0; nt < 4; nt++)
            #pragma unroll
            for (int q = 0; q < 4; q++) oacc[nt][q] = 0.0f;
        #pragma unroll
        for (int kt = 0; kt < 4; kt++)
            #pragma unroll
            for (int nt = 0; nt < 4; nt++)
                mma_bf16(oacc[nt], pf[kt], vf[kt][nt >> 1][(nt & 1) * 2], vf[kt][nt >> 1][(nt & 1) * 2 + 1]);

        #pragma unroll
        for (int nt = 0; nt < 4; nt++) {
            int c = nt * 8 + t4 * 2;
            if (r0 < Nn)
                *(bf162*)(O + ((size_t)(lw * Nn + r0)) * Cdim + qcol + c)
                    = __floats2bfloat162_rn(oacc[nt][0], oacc[nt][1]);
            if (r1 < Nn)
                *(bf162*)(O + ((size_t)(lw * Nn + r1)) * Cdim + qcol + c)
                    = __floats2bfloat162_rn(oacc[nt][2], oacc[nt][3]);
        }
    }
}

// ---------------- fused MLP: out += variants( gelu(XN@f1w)@f2w ) ----------------
#define SXP 136
#define FMLP_SMEM (6 * 128 * SXP * 2)   // sX + 2*sW1 + 2*sW2 + sH = 208896B

__global__ __launch_bounds__(256, 1) void fmlp(
    const bf16* __restrict__ XN,
    const bf16* __restrict__ W1,          // (512,128) bf16
    const float* __restrict__ f1b,
    const bf16* __restrict__ W2,          // (128,512) bf16
    const float* __restrict__ f2b,
    const float* __restrict__ gw,
    float* __restrict__ out, int splitM) {
    extern __shared__ bf16 sm[];
    bf16* sX  = sm;
    bf16* sW1 = sX + 128 * SXP;
    bf16* sW2 = sW1 + 2 * 128 * SXP;
    bf16* sH  = sW2 + 2 * 128 * SXP;

    const int tid = threadIdx.x;
    const int bm = blockIdx.x * BM;
    const bool half2 = bm >= splitM;
    const int wid = tid >> 5, lane = tid & 31;
    const int wm = (wid & 3) * 32, wn = (wid >> 2) * 64;
    const int g4 = lane >> 2, t4 = lane & 3;
    const int lrow = tid >> 1;
    const int lcb = (tid & 1) * 64;

    {   // XN tile (resident)
        const bf16* src = XN + (size_t)(bm + lrow) * Cdim + lcb;
        uint32_t d = (uint32_t)__cvta_generic_to_shared(&sX[lrow * SXP + lcb]);
        #pragma unroll
        for (int i = 0; i < 8; i++) cpa16(d + i * 16, src + i * 8, true);
        asm volatile("cp.async.commit_group;\n");
    }
    auto issueW = [&](int c) {
        int buf = c & 1;
        const bf16* s1 = W1 + (size_t)(c * 128 + lrow) * Cdim + lcb;
        uint32_t d1 = (uint32_t)__cvta_generic_to_shared(&sW1[buf * 128 * SXP + lrow * SXP + lcb]);
        const bf16* s2 = W2 + (size_t)lrow * HID + c * 128 + lcb;
        uint32_t d2 = (uint32_t)__cvta_generic_to_shared(&sW2[buf * 128 * SXP + lrow * SXP + lcb]);
        #pragma unroll
        for (int i = 0; i < 8; i++) {
            cpa16(d1 + i * 16, s1 + i * 8, true);
            cpa16(d2 + i * 16, s2 + i * 8, true);
        }
        asm volatile("cp.async.commit_group;\n");
    };
    issueW(0); issueW(1);

    const float a0 = half2 ? __ldg(&gw[0]) : 1.0f;
    const float a1 = __ldg(&gw[1]);
    const float a2 = __ldg(&gw[2]);

    float accO[2][8][4];
    #pragma unroll
    for (int i = 0; i < 2; i++)
        #pragma unroll
        for (int j = 0; j < 8; j++)
            #pragma unroll
            for (int q = 0; q < 4; q++) accO[i][j][q] = 0.0f;

    #pragma unroll 1
    for (int c = 0; c < 4; c++) {
        if (c < 3) { asm volatile("cp.async.wait_group 1;\n"); }
        else       { asm volatile("cp.async.wait_group 0;\n"); }
        __syncthreads();
        const bf16* w1b = &sW1[(c & 1) * 128 * SXP];
        const bf16* w2b = &sW2[(c & 1) * 128 * SXP];

        float accH[2][8][4];
        #pragma unroll
        for (int i = 0; i < 2; i++)
            #pragma unroll
            for (int j = 0; j < 8; j++)
                #pragma unroll
                for (int q = 0; q < 4; q++) accH[i][j][q] = 0.0f;

        auto s1k = [&](int ki) {
            #pragma unroll
            for (int kh = 0; kh < 2; kh++) {
                int kb = ki * 32 + kh * 16;
                uint32_t af[2][4];
                #pragma unroll
                for (int mt = 0; mt < 2; mt++)
                    ldsm_x4(af[mt], &sX[(wm + mt * 16 + (lane & 15)) * SXP + kb + ((lane >> 4) << 3)]);
                uint32_t bfm[8][2];
                #pragma unroll
                for (int nt2 = 0; nt2 < 4; nt2++) {
                    uint32_t r4[4];
                    ldsm_x4(r4, &w1b[(wn + nt2 * 16 + (lane & 7) + ((lane >> 4) << 3)) * SXP
                                      + kb + (((lane >> 3) & 1) << 3)]);
                    bfm[nt2 * 2][0] = r4[0]; bfm[nt2 * 2][1] = r4[1];
                    bfm[nt2 * 2 + 1][0] = r4[2]; bfm[nt2 * 2 + 1][1] = r4[3];
                }
                #pragma unroll
                for (int nt = 0; nt < 8; nt++) {
                    mma_bf16(accH[0][nt], af[0], bfm[nt][0], bfm[nt][1]);
                    mma_bf16(accH[1][nt], af[1], bfm[nt][0], bfm[nt][1]);
                }
            }
        };
        auto writeH = [&](float scale) {
            #pragma unroll
            for (int nt = 0; nt < 8; nt++) {
                int cc = wn + nt * 8 + t4 * 2;
                float b0 = __ldg(&f1b[c * 128 + cc]);
                float b1 = __ldg(&f1b[c * 128 + cc + 1]);
                #pragma unroll
                for (int mt = 0; mt < 2; mt++)
                    #pragma unroll
                    for (int half = 0; half < 2; half++) {
                        int r = wm + mt * 16 + g4 + half * 8;
                        float v0 = gelu_f(accH[mt][nt][half * 2 + 0] + b0) * scale;
                        float v1 = gelu_f(accH[mt][nt][half * 2 + 1] + b1) * scale;
                        *(bf162*)(sH + r * SXP + cc) = __floats2bfloat162_rn(v0, v1);
                    }
            }
        };
        auto s2pass = [&](int maxcol) {
            #pragma unroll
            for (int kb = 0; kb < 128; kb += 16) {
                uint32_t af[2][4];
                #pragma unroll
                for (int mt = 0; mt < 2; mt++)
                    ldsm_x4(af[mt], &sH[(wm + mt * 16 + (lane & 15)) * SXP + kb + ((lane >> 4) << 3)]);
                #pragma unroll
                for (int nt2 = 0; nt2 < 4; nt2++) {
                    if (wn + nt2 * 16 >= maxcol) continue;
                    uint32_t r4[4];
                    ldsm_x4(r4, &w2b[(wn + nt2 * 16 + (lane & 7) + ((lane >> 4) << 3)) * SXP
                                      + kb + (((lane >> 3) & 1) << 3)]);
                    mma_bf16(accO[0][nt2 * 2],     af[0], r4[0], r4[1]);
                    mma_bf16(accO[0][nt2 * 2 + 1], af[0], r4[2], r4[3]);
                    mma_bf16(accO[1][nt2 * 2],     af[1], r4[0], r4[1]);
                    mma_bf16(accO[1][nt2 * 2 + 1], af[1], r4[2], r4[3]);
                }
            }
        };

        if (half2) {
            s1k(0); writeH(a2); __syncthreads(); s2pass(32);  __syncthreads();
            s1k(1); writeH(a1); __syncthreads(); s2pass(64);  __syncthreads();
            s1k(2); s1k(3);
            writeH(a0); __syncthreads(); s2pass(128); __syncthreads();
        } else {
            s1k(0); s1k(1); s1k(2); s1k(3);
            writeH(1.0f); __syncthreads(); s2pass(128); __syncthreads();
        }
        if (c + 2 < 4) issueW(c + 2);
    }

    // epilogue: out += accO + coef(col)*f2b
    #pragma unroll
    for (int nt = 0; nt < 8; nt++) {
        int cc = wn + nt * 8 + t4 * 2;
        float coef = half2 ? ((cc < 32) ? (a0 + a1 + a2) : (cc < 64) ? (a0 + a1) : a0) : 1.0f;
        float b0 = __ldg(&f2b[cc]) * coef;
        float b1 = __ldg(&f2b[cc + 1]) * coef;
        #pragma unroll
        for (int mt = 0; mt < 2; mt++)
            #pragma unroll
            for (int half = 0; half < 2; half++) {
                int r = bm + wm + mt * 16 + g4 + half * 8;
                size_t off = (size_t)r * Cdim + cc;
                float2 old = *(const float2*)(out + off);
                old.x += accO[mt][nt][half * 2 + 0] + b0;
                old.y += accO[mt][nt][half * 2 + 1] + b1;
                *(float2*)(out + off) = old;
            }
    }
}

// ---------------- host helpers ----------------
static inline void launch_gemm(const bf16* A, int lda, const bf16* B, int ldb,
                               const float* bias, void* C, int ldc,
                               int M, int N, int K,
                               const float* gwP, int ai, int aMode, int splitM,
                               int outBf16,
                               bf16* pfx2, bf16* pfx1, int pfxLd,
                               const float* xres, int permMode, int rowOffset) {
    int nbn = (N + BN - 1) / BN;
    int nT = M / BM;
    int gy = 296 / nbn;
    if (gy > nT) gy = nT;
    if (gy < 1) gy = 1;
    dim3 grid(nbn, gy);
    bgemm<<<grid, 256, GEMM_SMEM>>>(A, lda, B, ldb, bias, C, ldc, M, N, K,
                                    gwP, ai, aMode, splitM, outBf16,
                                    pfx2, pfx1, pfxLd, xres, permMode, rowOffset);
}

extern "C" void kernel_launch(void* const* d_in, const int* in_sizes, int n_in,
                              void* d_out, int out_size) {
    const float* x     = (const float*)d_in[0];
    const float* gw    = (const float*)d_in[1];
    const float* n1w   = (const float*)d_in[2];
    const float* n1b   = (const float*)d_in[3];
    const float* qkvw  = (const float*)d_in[4];
    const float* qkvb  = (const float*)d_in[5];
    const float* rbt   = (const float*)d_in[6];
    const float* projw = (const float*)d_in[7];
    const float* projb = (const float*)d_in[8];
    const float* amask = (const float*)d_in[9];
    const float* n2w   = (const float*)d_in[10];
    const float* n2b   = (const float*)d_in[11];
    const float* f1w   = (const float*)d_in[12];
    const float* f1b   = (const float*)d_in[13];
    const float* f2w   = (const float*)d_in[14];
    const float* f2b   = (const float*)d_in[15];
    const int*   relIdx= (const int*)d_in[16];
    float* out = (float*)d_out;

    cudaFuncSetAttribute(bgemm, cudaFuncAttributeMaxDynamicSharedMemorySize, GEMM_SMEM);
    cudaFuncSetAttribute(attn_kernel, cudaFuncAttributeMaxDynamicSharedMemorySize, ATTN_SMEM);
    cudaFuncSetAttribute(fmlp, cudaFuncAttributeMaxDynamicSharedMemorySize, FMLP_SMEM);

    bf16 *XW, *QKVf, *QKV1, *QKV2, *O, *Oh1, *Oh2, *XN, *Wb;
    float *CB;
    cudaGetSymbolAddress((void**)&XW,   g_XW);
    cudaGetSymbolAddress((void**)&QKVf, g_QKVf);
    cudaGetSymbolAddress((void**)&QKV1, g_QKV1);
    cudaGetSymbolAddress((void**)&QKV2, g_QKV2);
    cudaGetSymbolAddress((void**)&O,    g_O);
    cudaGetSymbolAddress((void**)&Oh1,  g_Oh1);
    cudaGetSymbolAddress((void**)&Oh2,  g_Oh2);
    cudaGetSymbolAddress((void**)&XN,   g_XN);
    cudaGetSymbolAddress((void**)&CB,   g_CB);
    cudaGetSymbolAddress((void**)&Wb,   g_Wb);

    const bf16* qkvwB = Wb;
    const bf16* projwB = Wb + 49152;
    const bf16* f1wB = Wb + 65536;
    const bf16* f2wB = Wb + 131072;

    const int Mh = TOK_HALF;
    const int Mf = TOK_TOTAL;

    // prep: weight cast + bias table + LN1/partition
    prep_kernel<<<PREP_W + PREP_B + PREP_LN, 256>>>(
        qkvw, projw, f1w, f2w, Wb, rbt, relIdx, amask, CB, x, n1w, n1b, XW);

    // QKV merged: full + prefix K=64 -> QKV1, K=32 -> QKV2
    launch_gemm(XW, Cdim, qkvwB, Cdim, qkvb, QKVf, 384, Mf, 384, 128,
                nullptr, 0, 0, Mh, 1, QKV2, QKV1, 384, nullptr, 0, 0);

    // attention: all variants, 1 block/window
    attn_kernel<<<NWIN_TOTAL + 2 * NWIN_HALF, 128, ATTN_SMEM>>>(
        QKVf, QKV1, QKV2, CB, O, Oh1, Oh2);

    // proj: writes out = x + alpha*v (permuted); variants RMW
    launch_gemm(O, Cdim, projwB, Cdim, projb, out, Cdim, Mf, 128, 128,
                gw, 0, 2, Mh, 0, nullptr, nullptr, 0, x, 1, 0);
    launch_gemm(Oh1, Cdim, projwB, Cdim, projb, out, Cdim, Mh, 64, 128,
                gw, 1, 1, 0, 0, nullptr, nullptr, 0, nullptr, 2, Mh);
    launch_gemm(Oh2, Cdim, projwB, Cdim, projb, out, Cdim, Mh, 32, 128,
                gw, 2, 1, 0, 0, nullptr, nullptr, 0, nullptr, 2, Mh);

    // LN2 (out already holds residual)
    ln2_kernel<<<TOK_TOTAL / 8, 256>>>(out, n2w, n2b, XN);

    // fused MLP: out += all variants
    fmlp<<<Mf / BM, 256, FMLP_SMEM>>>(XN, f1wB, f1b, f2wB, f2b, gw, out, Mh);
}